// round 5
// baseline (speedup 1.0000x reference)
#include <cuda_runtime.h>
#include <cuda_bf16.h>
#include <math.h>

typedef unsigned long long u64;
typedef unsigned int u32;

#define BATCH 16384
#define NF 10
#define LL 20
#define DD 16
#define FEAT 160
#define NE 8
#define SS 64
#define NG 3
#define TT 32
#define NCOLS (NE*SS)

#define TM 128
#define TN 128
#define STRIDE 168                      // padded bf16 row stride (336B: ldmatrix conflict-free)
#define TILE_U16 (128 * STRIDE)
#define DYN_SMEM (4 * TILE_U16 * 2)

// Scratch (device globals: no allocation allowed)
__device__ __align__(16) float          g_x  [BATCH * FEAT];
__device__ __align__(16) unsigned short g_xhi[BATCH * FEAT];
__device__ __align__(16) unsigned short g_xlo[BATCH * FEAT];
__device__ __align__(16) unsigned short g_whi[NCOLS * FEAT];
__device__ __align__(16) unsigned short g_wlo[NCOLS * FEAT];
__device__ __align__(16) float          g_exp[BATCH * NCOLS];

// ---------------- helpers ----------------
__device__ __forceinline__ u64 pack2(float lo, float hi) {
    u64 d;
    asm("mov.b64 %0, {%1, %2};" : "=l"(d)
        : "r"(__float_as_uint(lo)), "r"(__float_as_uint(hi)));
    return d;
}
__device__ __forceinline__ void unpack2(u64 v, float &lo, float &hi) {
    unsigned a, b;
    asm("mov.b64 {%0, %1}, %2;" : "=r"(a), "=r"(b) : "l"(v));
    lo = __uint_as_float(a); hi = __uint_as_float(b);
}
__device__ __forceinline__ u64 ffma2(u64 a, u64 b, u64 c) {
    u64 d;
    asm("fma.rn.f32x2 %0, %1, %2, %3;" : "=l"(d) : "l"(a), "l"(b), "l"(c));
    return d;
}
__device__ __forceinline__ u64 fadd2(u64 a, u64 b) {
    u64 d;
    asm("add.rn.f32x2 %0, %1, %2;" : "=l"(d) : "l"(a), "l"(b));
    return d;
}
__device__ __forceinline__ u32 smem_u32(const void* p) {
    u32 a;
    asm("{ .reg .u64 t; cvta.to.shared.u64 t, %1; cvt.u32.u64 %0, t; }" : "=r"(a) : "l"(p));
    return a;
}
__device__ __forceinline__ void ldsm4(u32 addr, u32 &r0, u32 &r1, u32 &r2, u32 &r3) {
    asm volatile("ldmatrix.sync.aligned.m8n8.x4.shared.b16 {%0,%1,%2,%3}, [%4];"
                 : "=r"(r0), "=r"(r1), "=r"(r2), "=r"(r3) : "r"(addr));
}
__device__ __forceinline__ void mma16816(float* d, const u32* a, const u32* b) {
    asm volatile("mma.sync.aligned.m16n8k16.row.col.f32.bf16.bf16.f32 "
                 "{%0,%1,%2,%3}, {%4,%5,%6,%7}, {%8,%9}, {%0,%1,%2,%3};"
                 : "+f"(d[0]), "+f"(d[1]), "+f"(d[2]), "+f"(d[3])
                 : "r"(a[0]), "r"(a[1]), "r"(a[2]), "r"(a[3]), "r"(b[0]), "r"(b[1]));
}
#define CP16(dst, src) \
    asm volatile("cp.async.cg.shared.global [%0], [%1], 16;" :: "r"(dst), "l"(src) : "memory")
#define CP_COMMIT() asm volatile("cp.async.commit_group;" ::: "memory")
#define CP_WAIT0()  asm volatile("cp.async.wait_group 0;" ::: "memory")

// ---------------------------------------------------------------------------
// Kernel A: embedding gather + sum; emits x fp32 [b][f] and bf16 hi/lo splits.
// ---------------------------------------------------------------------------
__global__ __launch_bounds__(256) void gather_kernel(const int* __restrict__ ids32,
                                                     const float4* __restrict__ emb) {
    __shared__ int s_is64;
    if (threadIdx.x == 0) {
        const unsigned* w = (const unsigned*)ids32;
        s_is64 = (w[1] == 0u && w[3] == 0u && w[5] == 0u && w[7] == 0u) ? 1 : 0;
    }
    __syncthreads();
    const int is64 = s_is64;

    int tid  = threadIdx.x;
    int p    = blockIdx.x * 64 + (tid >> 2);
    int lane = tid & 3;
    int f = p >> 14;
    int b = p & (BATCH - 1);
    long base = (long)p * LL;

    float4 acc = make_float4(0.f, 0.f, 0.f, 0.f);
    if (is64) {
        #pragma unroll
        for (int l = 0; l < LL; l++) {
            int id = ids32[2 * (base + l)];
            float4 v = __ldg(&emb[(long)id * 4 + lane]);
            acc.x += v.x; acc.y += v.y; acc.z += v.z; acc.w += v.w;
        }
    } else {
        #pragma unroll
        for (int l = 0; l < LL; l++) {
            int id = ids32[base + l];
            float4 v = __ldg(&emb[(long)id * 4 + lane]);
            acc.x += v.x; acc.y += v.y; acc.z += v.z; acc.w += v.w;
        }
    }
    int fb = f * DD + lane * 4;
    long xoff = (long)b * FEAT + fb;
    *(float4*)&g_x[xoff] = acc;

    float vals[4] = {acc.x, acc.y, acc.z, acc.w};
    unsigned short hi[4], lo[4];
    #pragma unroll
    for (int j = 0; j < 4; j++) {
        __nv_bfloat16 h = __float2bfloat16_rn(vals[j]);
        float r = vals[j] - __bfloat162float(h);
        __nv_bfloat16 l = __float2bfloat16_rn(r);
        hi[j] = *(unsigned short*)&h;
        lo[j] = *(unsigned short*)&l;
    }
    *(uint2*)&g_xhi[xoff] = make_uint2((u32)hi[0] | ((u32)hi[1] << 16),
                                       (u32)hi[2] | ((u32)hi[3] << 16));
    *(uint2*)&g_xlo[xoff] = make_uint2((u32)lo[0] | ((u32)lo[1] << 16),
                                       (u32)lo[2] | ((u32)lo[3] << 16));
}

// ---------------------------------------------------------------------------
// Kernel W: weight transpose + bf16 hi/lo split
// ---------------------------------------------------------------------------
__global__ __launch_bounds__(256) void wprep_kernel(const float* __restrict__ ew) {
    int idx = blockIdx.x * 256 + threadIdx.x;
    if (idx >= NCOLS * FEAT) return;
    int c = idx & (NCOLS - 1);
    int k = idx >> 9;
    int e = c >> 6, s = c & 63;
    float w = ew[((long)e * FEAT + k) * SS + s];
    __nv_bfloat16 h = __float2bfloat16_rn(w);
    float r = w - __bfloat162float(h);
    __nv_bfloat16 l = __float2bfloat16_rn(r);
    g_whi[(long)c * FEAT + k] = *(unsigned short*)&h;
    g_wlo[(long)c * FEAT + k] = *(unsigned short*)&l;
}

// ---------------------------------------------------------------------------
// Kernel B: experts GEMM, mma.sync bf16 3-term split, cp.async fills.
// ---------------------------------------------------------------------------
__global__ __launch_bounds__(256) void expert_mma_kernel(const float* __restrict__ eb) {
    extern __shared__ unsigned short sm16[];
    unsigned short* sAhi = sm16;
    unsigned short* sAlo = sm16 + TILE_U16;
    unsigned short* sBhi = sm16 + 2 * TILE_U16;
    unsigned short* sBlo = sm16 + 3 * TILE_U16;
    __shared__ float s_bias[TN];

    int tid  = threadIdx.x;
    int wid  = tid >> 5;
    int lane = tid & 31;
    int b0   = blockIdx.x * TM;
    int c0   = blockIdx.y * TN;

    if (tid < TN) {
        int c = c0 + tid;
        s_bias[tid] = eb[(c >> 6) * SS + (c & 63)];
    }

    u32 bAhi = smem_u32(sAhi), bAlo = smem_u32(sAlo);
    u32 bBhi = smem_u32(sBhi), bBlo = smem_u32(sBlo);

    #pragma unroll
    for (int it = 0; it < 10; it++) {
        int idx = tid + it * 256;
        int row = idx / 20;
        int ch  = idx % 20;
        long ga = (long)(b0 + row) * FEAT + ch * 8;
        u32 so  = (u32)(row * STRIDE + ch * 8) * 2;
        CP16(bAhi + so, &g_xhi[ga]);
        CP16(bAlo + so, &g_xlo[ga]);
    }
    #pragma unroll
    for (int it = 0; it < 10; it++) {
        int idx = tid + it * 256;
        int row = idx / 20;
        int ch  = idx % 20;
        long ga = (long)(c0 + row) * FEAT + ch * 8;
        u32 so  = (u32)(row * STRIDE + ch * 8) * 2;
        CP16(bBhi + so, &g_whi[ga]);
        CP16(bBlo + so, &g_wlo[ga]);
    }
    CP_COMMIT();
    CP_WAIT0();
    __syncthreads();

    int m0 = (wid >> 1) * 32;
    int n0 = (wid & 1) * 64;

    u32 aOff = (u32)((m0 + (lane & 7) + ((lane & 8) ? 8 : 0)) * STRIDE + ((lane & 16) ? 8 : 0));
    u32 bOff = (u32)((n0 + (lane & 7) + ((lane & 16) ? 8 : 0)) * STRIDE + ((lane & 8) ? 8 : 0));

    u32 aHiB = bAhi + aOff * 2;
    u32 aLoB = bAlo + aOff * 2;
    u32 bHiB = bBhi + bOff * 2;
    u32 bLoB = bBlo + bOff * 2;

    float acc[2][8][4];
    #pragma unroll
    for (int mt = 0; mt < 2; mt++)
        #pragma unroll
        for (int nt = 0; nt < 8; nt++)
            #pragma unroll
            for (int q = 0; q < 4; q++) acc[mt][nt][q] = 0.f;

    #pragma unroll
    for (int ks = 0; ks < 10; ks++) {
        u32 kb = (u32)(ks * 16 * 2);

        u32 ah[2][4], al[2][4];
        #pragma unroll
        for (int mt = 0; mt < 2; mt++) {
            u32 moff = (u32)(mt * 16 * STRIDE * 2);
            ldsm4(aHiB + moff + kb, ah[mt][0], ah[mt][1], ah[mt][2], ah[mt][3]);
            ldsm4(aLoB + moff + kb, al[mt][0], al[mt][1], al[mt][2], al[mt][3]);
        }
        u32 bh[4][4], blo[4][4];
        #pragma unroll
        for (int nt2 = 0; nt2 < 4; nt2++) {
            u32 noff = (u32)(nt2 * 16 * STRIDE * 2);
            ldsm4(bHiB + noff + kb, bh[nt2][0], bh[nt2][1], bh[nt2][2], bh[nt2][3]);
            ldsm4(bLoB + noff + kb, blo[nt2][0], blo[nt2][1], blo[nt2][2], blo[nt2][3]);
        }

        #pragma unroll
        for (int mt = 0; mt < 2; mt++) {
            #pragma unroll
            for (int nt2 = 0; nt2 < 4; nt2++) {
                mma16816(acc[mt][2 * nt2],     ah[mt], &bh[nt2][0]);
                mma16816(acc[mt][2 * nt2 + 1], ah[mt], &bh[nt2][2]);
                mma16816(acc[mt][2 * nt2],     ah[mt], &blo[nt2][0]);
                mma16816(acc[mt][2 * nt2 + 1], ah[mt], &blo[nt2][2]);
                mma16816(acc[mt][2 * nt2],     al[mt], &bh[nt2][0]);
                mma16816(acc[mt][2 * nt2 + 1], al[mt], &bh[nt2][2]);
            }
        }
    }

    #pragma unroll
    for (int mt = 0; mt < 2; mt++) {
        int row = b0 + m0 + mt * 16 + (lane >> 2);
        #pragma unroll
        for (int nt = 0; nt < 8; nt++) {
            int cl = n0 + nt * 8 + (lane & 3) * 2;
            float bi0 = s_bias[cl], bi1 = s_bias[cl + 1];
            float* d = acc[mt][nt];
            *(float2*)&g_exp[(long)row * NCOLS + c0 + cl] =
                make_float2(fmaxf(d[0] + bi0, 0.f), fmaxf(d[1] + bi1, 0.f));
            *(float2*)&g_exp[(long)(row + 8) * NCOLS + c0 + cl] =
                make_float2(fmaxf(d[2] + bi0, 0.f), fmaxf(d[3] + bi1, 0.f));
        }
    }
}

// ---------------------------------------------------------------------------
// Kernel C: head. 32 rows/block, 4 threads/row (q = tid&3), phase-split.
// ---------------------------------------------------------------------------
#define HROWS 32
#define MIXSTRIDE 204     // floats per row in mix buffer (bank-safe)
#define GSTRIDE 66        // g stride within mix row

struct HeadSmem {
    u64   gw[FEAT][12];          // 15360 B
    u64   tw[SS][48];            // 24576 B
    float buf[HROWS * MIXSTRIDE];// 26112 B  (mix; gates-red overlaid)
    float ored[HROWS][4][6];     // 3072 B
    float ow[NG * TT * 2];
    float tb[NG * TT];
    float gb[NG * NE];
    float ob[8];
};

__global__ __launch_bounds__(128) void head_kernel(const float* __restrict__ gw,
                                                   const float* __restrict__ gb,
                                                   const float* __restrict__ tw,
                                                   const float* __restrict__ tb,
                                                   const float* __restrict__ ow,
                                                   const float* __restrict__ ob,
                                                   float* __restrict__ out) {
    extern __shared__ char smem_raw[];
    HeadSmem* sm = (HeadSmem*)smem_raw;

    int tid = threadIdx.x;
    int r   = tid >> 2;      // local row 0..31
    int q   = tid & 3;       // quarter
    int b   = blockIdx.x * HROWS + r;

    // ---- fills ----
    for (int i = tid; i < FEAT * 12; i += 128) {
        int f = i / 12, j = i % 12;
        int g = j >> 2, e2 = j & 3;
        float2 p = *(const float2*)&gw[(long)(g * FEAT + f) * NE + 2 * e2];
        sm->gw[f][j] = pack2(p.x, p.y);
    }
    for (int i = tid; i < SS * 48; i += 128) {
        int s = i / 48, j = i % 48;
        int g = j >> 4, t2 = j & 15;
        float2 p = *(const float2*)&tw[(long)(g * SS + s) * TT + 2 * t2];
        sm->tw[s][j] = pack2(p.x, p.y);
    }
    for (int i = tid; i < NG * TT * 2; i += 128) sm->ow[i] = ow[i];
    if (tid < NG * TT) sm->tb[tid] = tb[tid];
    if (tid < NG * NE) sm->gb[tid] = gb[tid];
    if (tid < NG * 2)  sm->ob[tid] = ob[tid];
    __syncthreads();

    // ---- phase 1: gate logit partials, k = 4*kk + q ----
    u64 gl[12];
    #pragma unroll
    for (int j = 0; j < 12; j++) gl[j] = 0ull;
    {
        const float* xrow = &g_x[(long)b * FEAT];
        #pragma unroll 8
        for (int kk = 0; kk < 40; kk++) {
            int k = kk * 4 + q;
            float x = xrow[k];
            u64 xv = pack2(x, x);
            const ulonglong2* gwrow = (const ulonglong2*)&sm->gw[k][0];
            #pragma unroll
            for (int p = 0; p < 6; p++) {
                ulonglong2 wp = gwrow[p];
                gl[2 * p]     = ffma2(xv, wp.x, gl[2 * p]);
                gl[2 * p + 1] = ffma2(xv, wp.y, gl[2 * p + 1]);
            }
        }
    }
    u64* gred = (u64*)sm->buf;   // overlay: [r*53 + q*13 + j]
    #pragma unroll
    for (int j = 0; j < 12; j++) gred[r * 53 + q * 13 + j] = gl[j];
    __syncthreads();

    // ---- phase 2: reduce + softmax (redundant in all 4 q) ----
    float gate[NG][NE];
    {
        #pragma unroll
        for (int j = 0; j < 12; j++) {
            u64 v = gred[r * 53 + j];
            #pragma unroll
            for (int qq = 1; qq < 4; qq++) v = fadd2(v, gred[r * 53 + qq * 13 + j]);
            int g = j >> 2, e2 = j & 3;
            u64 bias = pack2(sm->gb[g * NE + 2 * e2], sm->gb[g * NE + 2 * e2 + 1]);
            v = fadd2(v, bias);
            unpack2(v, gate[g][2 * e2], gate[g][2 * e2 + 1]);
        }
        #pragma unroll
        for (int g = 0; g < NG; g++) {
            float m = gate[g][0];
            #pragma unroll
            for (int e = 1; e < NE; e++) m = fmaxf(m, gate[g][e]);
            float sum = 0.f;
            #pragma unroll
            for (int e = 0; e < NE; e++) { gate[g][e] = __expf(gate[g][e] - m); sum += gate[g][e]; }
            float inv = __fdividef(1.f, sum);
            #pragma unroll
            for (int e = 0; e < NE; e++) gate[g][e] *= inv;
        }
    }
    __syncthreads();   // gred reads done; buf becomes mix

    // ---- phase 3: mix -> smem (thread q covers s in [q*16, q*16+16)) ----
    {
        const float* erow = &g_exp[(long)b * NCOLS];
        float* mrow = &sm->buf[r * MIXSTRIDE];
        #pragma unroll
        for (int grp = 0; grp < 4; grp++) {
            int s0 = q * 16 + grp * 4;
            float4 ve[NE];
            #pragma unroll
            for (int e = 0; e < NE; e++)
                ve[e] = *(const float4*)&erow[e * SS + s0];
            #pragma unroll
            for (int i = 0; i < 4; i++) {
                float comp[NE];
                #pragma unroll
                for (int e = 0; e < NE; e++)
                    comp[e] = (i == 0) ? ve[e].x : (i == 1) ? ve[e].y : (i == 2) ? ve[e].z : ve[e].w;
                #pragma unroll
                for (int g = 0; g < NG; g++) {
                    float m = 0.f;
                    #pragma unroll
                    for (int e = 0; e < NE; e++) m = fmaf(gate[g][e], comp[e], m);
                    mrow[g * GSTRIDE + s0 + i] = m;
                }
            }
        }
    }
    __syncthreads();

    // ---- phase 4: tower (thread q owns t2 in [q*4, q*4+4) for all g) ----
    u64 ta[12];
    #pragma unroll
    for (int g = 0; g < NG; g++)
        #pragma unroll
        for (int tt = 0; tt < 4; tt++) {
            int t2 = q * 4 + tt;
            ta[g * 4 + tt] = pack2(sm->tb[g * TT + 2 * t2], sm->tb[g * TT + 2 * t2 + 1]);
        }
    {
        const float* mrow = &sm->buf[r * MIXSTRIDE];
        #pragma unroll 2
        for (int s = 0; s < SS; s++) {
            float m0 = mrow[0 * GSTRIDE + s];
            float m1 = mrow[1 * GSTRIDE + s];
            float m2 = mrow[2 * GSTRIDE + s];
            u64 mv[NG] = {pack2(m0, m0), pack2(m1, m1), pack2(m2, m2)};
            #pragma unroll
            for (int g = 0; g < NG; g++) {
                const ulonglong2* wp = (const ulonglong2*)&sm->tw[s][g * 16 + q * 4];
                ulonglong2 w01 = wp[0], w23 = wp[1];
                ta[g * 4 + 0] = ffma2(mv[g], w01.x, ta[g * 4 + 0]);
                ta[g * 4 + 1] = ffma2(mv[g], w01.y, ta[g * 4 + 1]);
                ta[g * 4 + 2] = ffma2(mv[g], w23.x, ta[g * 4 + 2]);
                ta[g * 4 + 3] = ffma2(mv[g], w23.y, ta[g * 4 + 3]);
            }
        }
    }

    // ---- phase 5: out-head partials (relu local-complete per (g,t2)) ----
    #pragma unroll
    for (int g = 0; g < NG; g++) {
        float l0 = 0.f, l1 = 0.f;
        #pragma unroll
        for (int tt = 0; tt < 4; tt++) {
            int t = 2 * (q * 4 + tt);
            float a, c;
            unpack2(ta[g * 4 + tt], a, c);
            a = fmaxf(a, 0.f); c = fmaxf(c, 0.f);
            l0 = fmaf(a, sm->ow[(g * TT + t) * 2 + 0], l0);
            l1 = fmaf(a, sm->ow[(g * TT + t) * 2 + 1], l1);
            l0 = fmaf(c, sm->ow[(g * TT + t + 1) * 2 + 0], l0);
            l1 = fmaf(c, sm->ow[(g * TT + t + 1) * 2 + 1], l1);
        }
        sm->ored[r][q][g * 2 + 0] = l0;
        sm->ored[r][q][g * 2 + 1] = l1;
    }
    __syncthreads();

    if (q == 0) {
        float ctr0 = 0.f, ctr1 = 0.f, cvr0 = 0.f, cvr1 = 0.f, imp1 = 0.f;
        #pragma unroll
        for (int g = 0; g < NG; g++) {
            float l0 = sm->ob[g * 2 + 0], l1 = sm->ob[g * 2 + 1];
            #pragma unroll
            for (int qq = 0; qq < 4; qq++) {
                l0 += sm->ored[r][qq][g * 2 + 0];
                l1 += sm->ored[r][qq][g * 2 + 1];
            }
            float mm = fmaxf(l0, l1);
            float e0 = __expf(l0 - mm), e1 = __expf(l1 - mm);
            float inv = __fdividef(1.f, e0 + e1);
            float p0 = fminf(fmaxf(e0 * inv, 1e-15f), 1.f - 1e-15f);
            float p1 = fminf(fmaxf(e1 * inv, 1e-15f), 1.f - 1e-15f);
            if (g == 0)      { ctr0 = p0; ctr1 = p1; }
            else if (g == 1) { cvr0 = p0; cvr1 = p1; }
            else             { imp1 = p1; }
        }
        float cc = ctr1 * cvr1;
        float* o = out + (long)b * 10;
        o[0] = ctr0; o[1] = ctr1; o[2] = ctr1;
        o[3] = cvr0; o[4] = cvr1; o[5] = cvr1;
        o[6] = 1.f - cc; o[7] = cc; o[8] = cc;
        o[9] = imp1;
    }
}

extern "C" void kernel_launch(void* const* d_in, const int* in_sizes, int n_in,
                              void* d_out, int out_size) {
    const int*   ids = (const int*)d_in[0];
    const float* emb = (const float*)d_in[1];
    const float* ew  = (const float*)d_in[2];
    const float* eb  = (const float*)d_in[3];
    const float* gw  = (const float*)d_in[4];
    const float* gb  = (const float*)d_in[5];
    const float* tw  = (const float*)d_in[6];
    const float* tb  = (const float*)d_in[7];
    const float* ow  = (const float*)d_in[8];
    const float* ob  = (const float*)d_in[9];
    float* out = (float*)d_out;

    cudaFuncSetAttribute(expert_mma_kernel, cudaFuncAttributeMaxDynamicSharedMemorySize, DYN_SMEM);
    cudaFuncSetAttribute(head_kernel, cudaFuncAttributeMaxDynamicSharedMemorySize,
                         (int)sizeof(HeadSmem));

    wprep_kernel<<<(NCOLS * FEAT + 255) / 256, 256>>>(ew);
    gather_kernel<<<(NF * BATCH) / 64, 256>>>(ids, (const float4*)emb);
    expert_mma_kernel<<<dim3(BATCH / TM, NCOLS / TN), 256, DYN_SMEM>>>(eb);
    head_kernel<<<BATCH / HROWS, 128, sizeof(HeadSmem)>>>(gw, gb, tw, tb, ow, ob, out);
}

// round 6
// speedup vs baseline: 1.0246x; 1.0246x over previous
#include <cuda_runtime.h>
#include <cuda_bf16.h>
#include <math.h>

typedef unsigned long long u64;
typedef unsigned int u32;

#define BATCH 16384
#define NF 10
#define LL 20
#define DD 16
#define FEAT 160
#define NE 8
#define SS 64
#define NG 3
#define TT 32
#define NCOLS (NE*SS)

#define TM 128
#define TN 128
#define STRIDE 168                      // padded bf16 row stride (ldmatrix conflict-free)
#define TILE_U16 (128 * STRIDE)
#define DYN_SMEM (4 * TILE_U16 * 2)

// Scratch (device globals: no allocation allowed)
__device__ __align__(16) float          g_x  [BATCH * FEAT];
__device__ __align__(16) unsigned short g_xhi[BATCH * FEAT];
__device__ __align__(16) unsigned short g_xlo[BATCH * FEAT];
__device__ __align__(16) unsigned short g_whi[NCOLS * FEAT];
__device__ __align__(16) unsigned short g_wlo[NCOLS * FEAT];
__device__ __align__(16) float          g_exp[BATCH * NCOLS];

// ---------------- helpers ----------------
__device__ __forceinline__ u32 smem_u32(const void* p) {
    u32 a;
    asm("{ .reg .u64 t; cvta.to.shared.u64 t, %1; cvt.u32.u64 %0, t; }" : "=r"(a) : "l"(p));
    return a;
}
__device__ __forceinline__ void ldsm4(u32 addr, u32 &r0, u32 &r1, u32 &r2, u32 &r3) {
    asm volatile("ldmatrix.sync.aligned.m8n8.x4.shared.b16 {%0,%1,%2,%3}, [%4];"
                 : "=r"(r0), "=r"(r1), "=r"(r2), "=r"(r3) : "r"(addr));
}
__device__ __forceinline__ void mma16816(float* d, const u32* a, const u32* b) {
    asm volatile("mma.sync.aligned.m16n8k16.row.col.f32.bf16.bf16.f32 "
                 "{%0,%1,%2,%3}, {%4,%5,%6,%7}, {%8,%9}, {%0,%1,%2,%3};"
                 : "+f"(d[0]), "+f"(d[1]), "+f"(d[2]), "+f"(d[3])
                 : "r"(a[0]), "r"(a[1]), "r"(a[2]), "r"(a[3]), "r"(b[0]), "r"(b[1]));
}
#define CP16(dst, src) \
    asm volatile("cp.async.cg.shared.global [%0], [%1], 16;" :: "r"(dst), "l"(src) : "memory")
#define CP_COMMIT() asm volatile("cp.async.commit_group;" ::: "memory")
#define CP_WAIT0()  asm volatile("cp.async.wait_group 0;" ::: "memory")

// ---------------------------------------------------------------------------
// Kernel A: embedding gather + sum; emits x fp32 [b][f] and bf16 hi/lo splits.
// ---------------------------------------------------------------------------
__global__ __launch_bounds__(256) void gather_kernel(const int* __restrict__ ids32,
                                                     const float4* __restrict__ emb) {
    __shared__ int s_is64;
    if (threadIdx.x == 0) {
        const unsigned* w = (const unsigned*)ids32;
        s_is64 = (w[1] == 0u && w[3] == 0u && w[5] == 0u && w[7] == 0u) ? 1 : 0;
    }
    __syncthreads();
    const int is64 = s_is64;

    int tid  = threadIdx.x;
    int p    = blockIdx.x * 64 + (tid >> 2);
    int lane = tid & 3;
    int f = p >> 14;
    int b = p & (BATCH - 1);
    long base = (long)p * LL;

    float4 acc = make_float4(0.f, 0.f, 0.f, 0.f);
    if (is64) {
        #pragma unroll
        for (int l = 0; l < LL; l++) {
            int id = ids32[2 * (base + l)];
            float4 v = __ldg(&emb[(long)id * 4 + lane]);
            acc.x += v.x; acc.y += v.y; acc.z += v.z; acc.w += v.w;
        }
    } else {
        #pragma unroll
        for (int l = 0; l < LL; l++) {
            int id = ids32[base + l];
            float4 v = __ldg(&emb[(long)id * 4 + lane]);
            acc.x += v.x; acc.y += v.y; acc.z += v.z; acc.w += v.w;
        }
    }
    int fb = f * DD + lane * 4;
    long xoff = (long)b * FEAT + fb;
    *(float4*)&g_x[xoff] = acc;

    float vals[4] = {acc.x, acc.y, acc.z, acc.w};
    unsigned short hi[4], lo[4];
    #pragma unroll
    for (int j = 0; j < 4; j++) {
        __nv_bfloat16 h = __float2bfloat16_rn(vals[j]);
        float r = vals[j] - __bfloat162float(h);
        __nv_bfloat16 l = __float2bfloat16_rn(r);
        hi[j] = *(unsigned short*)&h;
        lo[j] = *(unsigned short*)&l;
    }
    *(uint2*)&g_xhi[xoff] = make_uint2((u32)hi[0] | ((u32)hi[1] << 16),
                                       (u32)hi[2] | ((u32)hi[3] << 16));
    *(uint2*)&g_xlo[xoff] = make_uint2((u32)lo[0] | ((u32)lo[1] << 16),
                                       (u32)lo[2] | ((u32)lo[3] << 16));
}

// ---------------------------------------------------------------------------
// Kernel W: weight transpose + bf16 hi/lo split
// ---------------------------------------------------------------------------
__global__ __launch_bounds__(256) void wprep_kernel(const float* __restrict__ ew) {
    int idx = blockIdx.x * 256 + threadIdx.x;
    if (idx >= NCOLS * FEAT) return;
    int c = idx & (NCOLS - 1);
    int k = idx >> 9;
    int e = c >> 6, s = c & 63;
    float w = ew[((long)e * FEAT + k) * SS + s];
    __nv_bfloat16 h = __float2bfloat16_rn(w);
    float r = w - __bfloat162float(h);
    __nv_bfloat16 l = __float2bfloat16_rn(r);
    g_whi[(long)c * FEAT + k] = *(unsigned short*)&h;
    g_wlo[(long)c * FEAT + k] = *(unsigned short*)&l;
}

// ---------------------------------------------------------------------------
// Kernel B: experts GEMM, mma.sync bf16 3-term split, cp.async fills.
// ---------------------------------------------------------------------------
__global__ __launch_bounds__(256) void expert_mma_kernel(const float* __restrict__ eb) {
    extern __shared__ unsigned short sm16[];
    unsigned short* sAhi = sm16;
    unsigned short* sAlo = sm16 + TILE_U16;
    unsigned short* sBhi = sm16 + 2 * TILE_U16;
    unsigned short* sBlo = sm16 + 3 * TILE_U16;
    __shared__ float s_bias[TN];

    int tid  = threadIdx.x;
    int wid  = tid >> 5;
    int lane = tid & 31;
    int b0   = blockIdx.x * TM;
    int c0   = blockIdx.y * TN;

    if (tid < TN) {
        int c = c0 + tid;
        s_bias[tid] = eb[(c >> 6) * SS + (c & 63)];
    }

    u32 bAhi = smem_u32(sAhi), bAlo = smem_u32(sAlo);
    u32 bBhi = smem_u32(sBhi), bBlo = smem_u32(sBlo);

    #pragma unroll
    for (int it = 0; it < 10; it++) {
        int idx = tid + it * 256;
        int row = idx / 20;
        int ch  = idx % 20;
        long ga = (long)(b0 + row) * FEAT + ch * 8;
        u32 so  = (u32)(row * STRIDE + ch * 8) * 2;
        CP16(bAhi + so, &g_xhi[ga]);
        CP16(bAlo + so, &g_xlo[ga]);
    }
    #pragma unroll
    for (int it = 0; it < 10; it++) {
        int idx = tid + it * 256;
        int row = idx / 20;
        int ch  = idx % 20;
        long ga = (long)(c0 + row) * FEAT + ch * 8;
        u32 so  = (u32)(row * STRIDE + ch * 8) * 2;
        CP16(bBhi + so, &g_whi[ga]);
        CP16(bBlo + so, &g_wlo[ga]);
    }
    CP_COMMIT();
    CP_WAIT0();
    __syncthreads();

    int m0 = (wid >> 1) * 32;
    int n0 = (wid & 1) * 64;

    u32 aOff = (u32)((m0 + (lane & 7) + ((lane & 8) ? 8 : 0)) * STRIDE + ((lane & 16) ? 8 : 0));
    u32 bOff = (u32)((n0 + (lane & 7) + ((lane & 16) ? 8 : 0)) * STRIDE + ((lane & 8) ? 8 : 0));

    u32 aHiB = bAhi + aOff * 2;
    u32 aLoB = bAlo + aOff * 2;
    u32 bHiB = bBhi + bOff * 2;
    u32 bLoB = bBlo + bOff * 2;

    float acc[2][8][4];
    #pragma unroll
    for (int mt = 0; mt < 2; mt++)
        #pragma unroll
        for (int nt = 0; nt < 8; nt++)
            #pragma unroll
            for (int q = 0; q < 4; q++) acc[mt][nt][q] = 0.f;

    #pragma unroll
    for (int ks = 0; ks < 10; ks++) {
        u32 kb = (u32)(ks * 16 * 2);

        u32 ah[2][4], al[2][4];
        #pragma unroll
        for (int mt = 0; mt < 2; mt++) {
            u32 moff = (u32)(mt * 16 * STRIDE * 2);
            ldsm4(aHiB + moff + kb, ah[mt][0], ah[mt][1], ah[mt][2], ah[mt][3]);
            ldsm4(aLoB + moff + kb, al[mt][0], al[mt][1], al[mt][2], al[mt][3]);
        }
        u32 bh[4][4], blo[4][4];
        #pragma unroll
        for (int nt2 = 0; nt2 < 4; nt2++) {
            u32 noff = (u32)(nt2 * 16 * STRIDE * 2);
            ldsm4(bHiB + noff + kb, bh[nt2][0], bh[nt2][1], bh[nt2][2], bh[nt2][3]);
            ldsm4(bLoB + noff + kb, blo[nt2][0], blo[nt2][1], blo[nt2][2], blo[nt2][3]);
        }

        #pragma unroll
        for (int mt = 0; mt < 2; mt++) {
            #pragma unroll
            for (int nt2 = 0; nt2 < 4; nt2++) {
                mma16816(acc[mt][2 * nt2],     ah[mt], &bh[nt2][0]);
                mma16816(acc[mt][2 * nt2 + 1], ah[mt], &bh[nt2][2]);
                mma16816(acc[mt][2 * nt2],     ah[mt], &blo[nt2][0]);
                mma16816(acc[mt][2 * nt2 + 1], ah[mt], &blo[nt2][2]);
                mma16816(acc[mt][2 * nt2],     al[mt], &bh[nt2][0]);
                mma16816(acc[mt][2 * nt2 + 1], al[mt], &bh[nt2][2]);
            }
        }
    }

    #pragma unroll
    for (int mt = 0; mt < 2; mt++) {
        int row = b0 + m0 + mt * 16 + (lane >> 2);
        #pragma unroll
        for (int nt = 0; nt < 8; nt++) {
            int cl = n0 + nt * 8 + (lane & 3) * 2;
            float bi0 = s_bias[cl], bi1 = s_bias[cl + 1];
            float* d = acc[mt][nt];
            *(float2*)&g_exp[(long)row * NCOLS + c0 + cl] =
                make_float2(fmaxf(d[0] + bi0, 0.f), fmaxf(d[1] + bi1, 0.f));
            *(float2*)&g_exp[(long)(row + 8) * NCOLS + c0 + cl] =
                make_float2(fmaxf(d[2] + bi0, 0.f), fmaxf(d[3] + bi1, 0.f));
        }
    }
}

// ---------------------------------------------------------------------------
// Kernel C: head, warp-per-row. 8 rows/block (256 thr), grid 1024 x 2 iters.
// No block-level syncs inside the row loop; shfl reductions only.
// ---------------------------------------------------------------------------
#define GWPAD 25

struct HeadSmem {
    float gw[FEAT][GWPAD];     // [f][g*8+e], padded     16000 B
    float tw[SS][NG * TT];     // [s][g*32+t]            24576 B
    float mix[8][NG * SS];     // per-warp mix            6144 B
    float ow0[NG * TT];        // out_w[..][0]             384 B
    float ow1[NG * TT];        // out_w[..][1]             384 B
    float tb[NG * TT];         //                          384 B
    float gb[NG * NE];
    float ob[8];
};

__global__ __launch_bounds__(256) void head_kernel(const float* __restrict__ gw,
                                                   const float* __restrict__ gb,
                                                   const float* __restrict__ tw,
                                                   const float* __restrict__ tb,
                                                   const float* __restrict__ ow,
                                                   const float* __restrict__ ob,
                                                   float* __restrict__ out) {
    extern __shared__ char smem_raw[];
    HeadSmem* sm = (HeadSmem*)smem_raw;

    int tid  = threadIdx.x;
    int warp = tid >> 5;
    int lane = tid & 31;

    // ---- weight fills (once per block) ----
    for (int i = tid; i < FEAT * 24; i += 256) {
        int f = i / 24, o = i % 24;
        int g = o >> 3, e = o & 7;
        sm->gw[f][o] = gw[((long)g * FEAT + f) * NE + e];
    }
    for (int i = tid; i < SS * NG * TT; i += 256) {
        int s = i / (NG * TT), j = i % (NG * TT);
        int g = j >> 5, t = j & 31;
        sm->tw[s][j] = tw[((long)g * SS + s) * TT + t];
    }
    for (int i = tid; i < NG * TT; i += 256) {
        sm->ow0[i] = ow[i * 2 + 0];
        sm->ow1[i] = ow[i * 2 + 1];
        sm->tb[i]  = tb[i];
    }
    if (tid < NG * NE) sm->gb[tid] = gb[tid];
    if (tid < NG * 2)  sm->ob[tid] = ob[tid];
    __syncthreads();

    for (int b = blockIdx.x * 8 + warp; b < BATCH; b += gridDim.x * 8) {
        // ---- phase A: gate logits (lane owns k = 32j+lane) ----
        const float* xrow = &g_x[(long)b * FEAT];
        float x5[5];
        #pragma unroll
        for (int j = 0; j < 5; j++) x5[j] = xrow[j * 32 + lane];

        float acc[24];
        #pragma unroll
        for (int o = 0; o < 24; o++) acc[o] = 0.f;
        #pragma unroll
        for (int j = 0; j < 5; j++) {
            const float* grow = &sm->gw[j * 32 + lane][0];
            float xv = x5[j];
            #pragma unroll
            for (int o = 0; o < 24; o++) acc[o] = fmaf(xv, grow[o], acc[o]);
        }
        #pragma unroll
        for (int off = 16; off > 0; off >>= 1) {
            #pragma unroll
            for (int o = 0; o < 24; o++)
                acc[o] += __shfl_xor_sync(0xFFFFFFFFu, acc[o], off);
        }

        // ---- softmax per gate group (redundant in every lane) ----
        float gate[NG][NE];
        #pragma unroll
        for (int g = 0; g < NG; g++) {
            float lg[NE];
            #pragma unroll
            for (int e = 0; e < NE; e++) lg[e] = acc[g * 8 + e] + sm->gb[g * 8 + e];
            float m = lg[0];
            #pragma unroll
            for (int e = 1; e < NE; e++) m = fmaxf(m, lg[e]);
            float sum = 0.f;
            #pragma unroll
            for (int e = 0; e < NE; e++) { lg[e] = __expf(lg[e] - m); sum += lg[e]; }
            float inv = __fdividef(1.f, sum);
            #pragma unroll
            for (int e = 0; e < NE; e++) gate[g][e] = lg[e] * inv;
        }

        // ---- phase B: mix (lane owns 6 (g,s): idx = i*32 + lane) ----
        __syncwarp();   // previous iteration's mix reads complete
        const float* erow = &g_exp[(long)b * NCOLS];
        #pragma unroll
        for (int i = 0; i < 6; i++) {
            int idx = i * 32 + lane;
            int g = idx >> 6, s = idx & 63;
            float v = 0.f;
            #pragma unroll
            for (int e = 0; e < NE; e++)
                v = fmaf(gate[g][e], erow[e * SS + s], v);
            sm->mix[warp][idx] = v;
        }
        __syncwarp();

        // ---- phase C: tower (lane owns t = lane for each g) ----
        float tow[NG];
        const float* mrow = &sm->mix[warp][0];
        #pragma unroll
        for (int g = 0; g < NG; g++) {
            float a = sm->tb[g * TT + lane];
            const float* mg = &mrow[g * SS];
            const float* twc = &sm->tw[0][g * TT + lane];
            #pragma unroll 8
            for (int s = 0; s < SS; s++)
                a = fmaf(mg[s], twc[s * (NG * TT)], a);
            tow[g] = fmaxf(a, 0.f);
        }

        // ---- phase D: out logits, shfl reduce, epilogue ----
        float l[6];
        #pragma unroll
        for (int g = 0; g < NG; g++) {
            l[g * 2 + 0] = tow[g] * sm->ow0[g * TT + lane];
            l[g * 2 + 1] = tow[g] * sm->ow1[g * TT + lane];
        }
        #pragma unroll
        for (int off = 16; off > 0; off >>= 1) {
            #pragma unroll
            for (int o = 0; o < 6; o++)
                l[o] += __shfl_xor_sync(0xFFFFFFFFu, l[o], off);
        }

        if (lane == 0) {
            float probs[6];
            #pragma unroll
            for (int g = 0; g < NG; g++) {
                float l0 = l[g * 2 + 0] + sm->ob[g * 2 + 0];
                float l1 = l[g * 2 + 1] + sm->ob[g * 2 + 1];
                float mm = fmaxf(l0, l1);
                float e0 = __expf(l0 - mm), e1 = __expf(l1 - mm);
                float inv = __fdividef(1.f, e0 + e1);
                probs[g * 2 + 0] = fminf(fmaxf(e0 * inv, 1e-15f), 1.f - 1e-15f);
                probs[g * 2 + 1] = fminf(fmaxf(e1 * inv, 1e-15f), 1.f - 1e-15f);
            }
            float cc = probs[1] * probs[3];
            float* o = out + (long)b * 10;
            o[0] = probs[0]; o[1] = probs[1]; o[2] = probs[1];
            o[3] = probs[2]; o[4] = probs[3]; o[5] = probs[3];
            o[6] = 1.f - cc; o[7] = cc; o[8] = cc;
            o[9] = probs[5];
        }
    }
}

extern "C" void kernel_launch(void* const* d_in, const int* in_sizes, int n_in,
                              void* d_out, int out_size) {
    const int*   ids = (const int*)d_in[0];
    const float* emb = (const float*)d_in[1];
    const float* ew  = (const float*)d_in[2];
    const float* eb  = (const float*)d_in[3];
    const float* gw  = (const float*)d_in[4];
    const float* gb  = (const float*)d_in[5];
    const float* tw  = (const float*)d_in[6];
    const float* tb  = (const float*)d_in[7];
    const float* ow  = (const float*)d_in[8];
    const float* ob  = (const float*)d_in[9];
    float* out = (float*)d_out;

    cudaFuncSetAttribute(expert_mma_kernel, cudaFuncAttributeMaxDynamicSharedMemorySize, DYN_SMEM);
    cudaFuncSetAttribute(head_kernel, cudaFuncAttributeMaxDynamicSharedMemorySize,
                         (int)sizeof(HeadSmem));

    wprep_kernel<<<(NCOLS * FEAT + 255) / 256, 256>>>(ew);
    gather_kernel<<<(NF * BATCH) / 64, 256>>>(ids, (const float4*)emb);
    expert_mma_kernel<<<dim3(BATCH / TM, NCOLS / TN), 256, DYN_SMEM>>>(eb);
    head_kernel<<<1024, 256, sizeof(HeadSmem)>>>(gw, gb, tw, tb, ow, ob, out);
}

// round 7
// speedup vs baseline: 1.1951x; 1.1665x over previous
#include <cuda_runtime.h>
#include <cuda_bf16.h>
#include <math.h>

typedef unsigned long long u64;
typedef unsigned int u32;

#define BATCH 16384
#define NF 10
#define LL 20
#define DD 16
#define FEAT 160
#define NE 8
#define SS 64
#define NG 3
#define TT 32
#define NCOLS (NE*SS)

#define TM 128
#define TN 128
#define STRIDE 168
#define TILE_U16 (128 * STRIDE)
#define DYN_SMEM (4 * TILE_U16 * 2)

// Scratch (device globals: no allocation allowed)
__device__ __align__(16) float          g_x  [BATCH * FEAT];
__device__ __align__(16) unsigned short g_xhi[BATCH * FEAT];
__device__ __align__(16) unsigned short g_xlo[BATCH * FEAT];
__device__ __align__(16) unsigned short g_whi[NCOLS * FEAT];
__device__ __align__(16) unsigned short g_wlo[NCOLS * FEAT];
__device__ __align__(16) float          g_exp[BATCH * NCOLS];

// ---------------- helpers ----------------
__device__ __forceinline__ u64 pack2(float lo, float hi) {
    u64 d;
    asm("mov.b64 %0, {%1, %2};" : "=l"(d)
        : "r"(__float_as_uint(lo)), "r"(__float_as_uint(hi)));
    return d;
}
__device__ __forceinline__ void unpack2(u64 v, float &lo, float &hi) {
    unsigned a, b;
    asm("mov.b64 {%0, %1}, %2;" : "=r"(a), "=r"(b) : "l"(v));
    lo = __uint_as_float(a); hi = __uint_as_float(b);
}
__device__ __forceinline__ u64 ffma2(u64 a, u64 b, u64 c) {
    u64 d;
    asm("fma.rn.f32x2 %0, %1, %2, %3;" : "=l"(d) : "l"(a), "l"(b), "l"(c));
    return d;
}
__device__ __forceinline__ u32 smem_u32(const void* p) {
    u32 a;
    asm("{ .reg .u64 t; cvta.to.shared.u64 t, %1; cvt.u32.u64 %0, t; }" : "=r"(a) : "l"(p));
    return a;
}
__device__ __forceinline__ void ldsm4(u32 addr, u32 &r0, u32 &r1, u32 &r2, u32 &r3) {
    asm volatile("ldmatrix.sync.aligned.m8n8.x4.shared.b16 {%0,%1,%2,%3}, [%4];"
                 : "=r"(r0), "=r"(r1), "=r"(r2), "=r"(r3) : "r"(addr));
}
__device__ __forceinline__ void mma16816(float* d, const u32* a, const u32* b) {
    asm volatile("mma.sync.aligned.m16n8k16.row.col.f32.bf16.bf16.f32 "
                 "{%0,%1,%2,%3}, {%4,%5,%6,%7}, {%8,%9}, {%0,%1,%2,%3};"
                 : "+f"(d[0]), "+f"(d[1]), "+f"(d[2]), "+f"(d[3])
                 : "r"(a[0]), "r"(a[1]), "r"(a[2]), "r"(a[3]), "r"(b[0]), "r"(b[1]));
}
#define CP16(dst, src) \
    asm volatile("cp.async.cg.shared.global [%0], [%1], 16;" :: "r"(dst), "l"(src) : "memory")
#define CP_COMMIT() asm volatile("cp.async.commit_group;" ::: "memory")
#define CP_WAIT0()  asm volatile("cp.async.wait_group 0;" ::: "memory")

// Exchange-halving transpose-reduce: input = 12 packed f32x2 partials
// (outputs 0..23, dup-padded to 32); returns the full sum of output o = lane.
__device__ __forceinline__ float reduce24(const u64* a2, int lane) {
    float A[32];
    #pragma unroll
    for (int q = 0; q < 12; q++) unpack2(a2[q], A[2 * q], A[2 * q + 1]);
    #pragma unroll
    for (int o = 24; o < 32; o++) A[o] = 0.f;

    float B[16];
    {   int kb = lane & 1;
        #pragma unroll
        for (int i = 0; i < 16; i++) {
            float oth = kb ? A[2 * i] : A[2 * i + 1];
            float rc  = __shfl_xor_sync(0xFFFFFFFFu, oth, 1);
            B[i] = (kb ? A[2 * i + 1] : A[2 * i]) + rc;
        }
    }
    float C[8];
    {   int kb = (lane >> 1) & 1;
        #pragma unroll
        for (int i = 0; i < 8; i++) {
            float oth = kb ? B[2 * i] : B[2 * i + 1];
            float rc  = __shfl_xor_sync(0xFFFFFFFFu, oth, 2);
            C[i] = (kb ? B[2 * i + 1] : B[2 * i]) + rc;
        }
    }
    float D[4];
    {   int kb = (lane >> 2) & 1;
        #pragma unroll
        for (int i = 0; i < 4; i++) {
            float oth = kb ? C[2 * i] : C[2 * i + 1];
            float rc  = __shfl_xor_sync(0xFFFFFFFFu, oth, 4);
            D[i] = (kb ? C[2 * i + 1] : C[2 * i]) + rc;
        }
    }
    float E[2];
    {   int kb = (lane >> 3) & 1;
        #pragma unroll
        for (int i = 0; i < 2; i++) {
            float oth = kb ? D[2 * i] : D[2 * i + 1];
            float rc  = __shfl_xor_sync(0xFFFFFFFFu, oth, 8);
            E[i] = (kb ? D[2 * i + 1] : D[2 * i]) + rc;
        }
    }
    {   int kb = (lane >> 4) & 1;
        float oth = kb ? E[0] : E[1];
        float rc  = __shfl_xor_sync(0xFFFFFFFFu, oth, 16);
        return (kb ? E[1] : E[0]) + rc;
    }
}

// ---------------------------------------------------------------------------
// Kernel A: embedding gather + sum; emits x fp32 [b][f] and bf16 hi/lo splits.
// ---------------------------------------------------------------------------
__global__ __launch_bounds__(256) void gather_kernel(const int* __restrict__ ids32,
                                                     const float4* __restrict__ emb) {
    __shared__ int s_is64;
    if (threadIdx.x == 0) {
        const unsigned* w = (const unsigned*)ids32;
        s_is64 = (w[1] == 0u && w[3] == 0u && w[5] == 0u && w[7] == 0u) ? 1 : 0;
    }
    __syncthreads();
    const int is64 = s_is64;

    int tid  = threadIdx.x;
    int p    = blockIdx.x * 64 + (tid >> 2);
    int lane = tid & 3;
    int f = p >> 14;
    int b = p & (BATCH - 1);
    long base = (long)p * LL;

    float4 acc = make_float4(0.f, 0.f, 0.f, 0.f);
    if (is64) {
        #pragma unroll
        for (int l = 0; l < LL; l++) {
            int id = ids32[2 * (base + l)];
            float4 v = __ldg(&emb[(long)id * 4 + lane]);
            acc.x += v.x; acc.y += v.y; acc.z += v.z; acc.w += v.w;
        }
    } else {
        #pragma unroll
        for (int l = 0; l < LL; l++) {
            int id = ids32[base + l];
            float4 v = __ldg(&emb[(long)id * 4 + lane]);
            acc.x += v.x; acc.y += v.y; acc.z += v.z; acc.w += v.w;
        }
    }
    int fb = f * DD + lane * 4;
    long xoff = (long)b * FEAT + fb;
    *(float4*)&g_x[xoff] = acc;

    float vals[4] = {acc.x, acc.y, acc.z, acc.w};
    unsigned short hi[4], lo[4];
    #pragma unroll
    for (int j = 0; j < 4; j++) {
        __nv_bfloat16 h = __float2bfloat16_rn(vals[j]);
        float r = vals[j] - __bfloat162float(h);
        __nv_bfloat16 l = __float2bfloat16_rn(r);
        hi[j] = *(unsigned short*)&h;
        lo[j] = *(unsigned short*)&l;
    }
    *(uint2*)&g_xhi[xoff] = make_uint2((u32)hi[0] | ((u32)hi[1] << 16),
                                       (u32)hi[2] | ((u32)hi[3] << 16));
    *(uint2*)&g_xlo[xoff] = make_uint2((u32)lo[0] | ((u32)lo[1] << 16),
                                       (u32)lo[2] | ((u32)lo[3] << 16));
}

// ---------------------------------------------------------------------------
// Kernel W: weight transpose + bf16 hi/lo split
// ---------------------------------------------------------------------------
__global__ __launch_bounds__(256) void wprep_kernel(const float* __restrict__ ew) {
    int idx = blockIdx.x * 256 + threadIdx.x;
    if (idx >= NCOLS * FEAT) return;
    int c = idx & (NCOLS - 1);
    int k = idx >> 9;
    int e = c >> 6, s = c & 63;
    float w = ew[((long)e * FEAT + k) * SS + s];
    __nv_bfloat16 h = __float2bfloat16_rn(w);
    float r = w - __bfloat162float(h);
    __nv_bfloat16 l = __float2bfloat16_rn(r);
    g_whi[(long)c * FEAT + k] = *(unsigned short*)&h;
    g_wlo[(long)c * FEAT + k] = *(unsigned short*)&l;
}

// ---------------------------------------------------------------------------
// Kernel B: experts GEMM, mma.sync bf16 3-term split, cp.async fills.
// ---------------------------------------------------------------------------
__global__ __launch_bounds__(256) void expert_mma_kernel(const float* __restrict__ eb) {
    extern __shared__ unsigned short sm16[];
    unsigned short* sAhi = sm16;
    unsigned short* sAlo = sm16 + TILE_U16;
    unsigned short* sBhi = sm16 + 2 * TILE_U16;
    unsigned short* sBlo = sm16 + 3 * TILE_U16;
    __shared__ float s_bias[TN];

    int tid  = threadIdx.x;
    int wid  = tid >> 5;
    int lane = tid & 31;
    int b0   = blockIdx.x * TM;
    int c0   = blockIdx.y * TN;

    if (tid < TN) {
        int c = c0 + tid;
        s_bias[tid] = eb[(c >> 6) * SS + (c & 63)];
    }

    u32 bAhi = smem_u32(sAhi), bAlo = smem_u32(sAlo);
    u32 bBhi = smem_u32(sBhi), bBlo = smem_u32(sBlo);

    #pragma unroll
    for (int it = 0; it < 10; it++) {
        int idx = tid + it * 256;
        int row = idx / 20;
        int ch  = idx % 20;
        long ga = (long)(b0 + row) * FEAT + ch * 8;
        u32 so  = (u32)(row * STRIDE + ch * 8) * 2;
        CP16(bAhi + so, &g_xhi[ga]);
        CP16(bAlo + so, &g_xlo[ga]);
    }
    #pragma unroll
    for (int it = 0; it < 10; it++) {
        int idx = tid + it * 256;
        int row = idx / 20;
        int ch  = idx % 20;
        long ga = (long)(c0 + row) * FEAT + ch * 8;
        u32 so  = (u32)(row * STRIDE + ch * 8) * 2;
        CP16(bBhi + so, &g_whi[ga]);
        CP16(bBlo + so, &g_wlo[ga]);
    }
    CP_COMMIT();
    CP_WAIT0();
    __syncthreads();

    int m0 = (wid >> 1) * 32;
    int n0 = (wid & 1) * 64;

    u32 aOff = (u32)((m0 + (lane & 7) + ((lane & 8) ? 8 : 0)) * STRIDE + ((lane & 16) ? 8 : 0));
    u32 bOff = (u32)((n0 + (lane & 7) + ((lane & 16) ? 8 : 0)) * STRIDE + ((lane & 8) ? 8 : 0));

    u32 aHiB = bAhi + aOff * 2;
    u32 aLoB = bAlo + aOff * 2;
    u32 bHiB = bBhi + bOff * 2;
    u32 bLoB = bBlo + bOff * 2;

    float acc[2][8][4];
    #pragma unroll
    for (int mt = 0; mt < 2; mt++)
        #pragma unroll
        for (int nt = 0; nt < 8; nt++)
            #pragma unroll
            for (int q = 0; q < 4; q++) acc[mt][nt][q] = 0.f;

    #pragma unroll
    for (int ks = 0; ks < 10; ks++) {
        u32 kb = (u32)(ks * 16 * 2);

        u32 ah[2][4], al[2][4];
        #pragma unroll
        for (int mt = 0; mt < 2; mt++) {
            u32 moff = (u32)(mt * 16 * STRIDE * 2);
            ldsm4(aHiB + moff + kb, ah[mt][0], ah[mt][1], ah[mt][2], ah[mt][3]);
            ldsm4(aLoB + moff + kb, al[mt][0], al[mt][1], al[mt][2], al[mt][3]);
        }
        u32 bh[4][4], blo[4][4];
        #pragma unroll
        for (int nt2 = 0; nt2 < 4; nt2++) {
            u32 noff = (u32)(nt2 * 16 * STRIDE * 2);
            ldsm4(bHiB + noff + kb, bh[nt2][0], bh[nt2][1], bh[nt2][2], bh[nt2][3]);
            ldsm4(bLoB + noff + kb, blo[nt2][0], blo[nt2][1], blo[nt2][2], blo[nt2][3]);
        }

        #pragma unroll
        for (int mt = 0; mt < 2; mt++) {
            #pragma unroll
            for (int nt2 = 0; nt2 < 4; nt2++) {
                mma16816(acc[mt][2 * nt2],     ah[mt], &bh[nt2][0]);
                mma16816(acc[mt][2 * nt2 + 1], ah[mt], &bh[nt2][2]);
                mma16816(acc[mt][2 * nt2],     ah[mt], &blo[nt2][0]);
                mma16816(acc[mt][2 * nt2 + 1], ah[mt], &blo[nt2][2]);
                mma16816(acc[mt][2 * nt2],     al[mt], &bh[nt2][0]);
                mma16816(acc[mt][2 * nt2 + 1], al[mt], &bh[nt2][2]);
            }
        }
    }

    #pragma unroll
    for (int mt = 0; mt < 2; mt++) {
        int row = b0 + m0 + mt * 16 + (lane >> 2);
        #pragma unroll
        for (int nt = 0; nt < 8; nt++) {
            int cl = n0 + nt * 8 + (lane & 3) * 2;
            float bi0 = s_bias[cl], bi1 = s_bias[cl + 1];
            float* d = acc[mt][nt];
            *(float2*)&g_exp[(long)row * NCOLS + c0 + cl] =
                make_float2(fmaxf(d[0] + bi0, 0.f), fmaxf(d[1] + bi1, 0.f));
            *(float2*)&g_exp[(long)(row + 8) * NCOLS + c0 + cl] =
                make_float2(fmaxf(d[2] + bi0, 0.f), fmaxf(d[3] + bi1, 0.f));
        }
    }
}

// ---------------------------------------------------------------------------
// Kernel C: head, warp-per-2-rows. Packed f32x2 weights in smem; exchange-
// halving transpose-reduce; lane-parallel softmax. No block syncs in body.
// ---------------------------------------------------------------------------
struct HeadSmem {
    u64   gw2[12][161];        // gate_w pairs:  [q=o/2][k]        15456 B
    u64   tw2[32][96];         // tower_w s-pairs: [sp][g*32+t]    24576 B
    float mix[8][2][192];      // per-warp, per-row mix            12288 B
    float ow0[NG * TT];
    float ow1[NG * TT];
    float tb[NG * TT];
    float gb[NG * NE];
    float ob[8];
};

__global__ __launch_bounds__(256) void head_kernel(const float* __restrict__ gw,
                                                   const float* __restrict__ gb,
                                                   const float* __restrict__ tw,
                                                   const float* __restrict__ tb,
                                                   const float* __restrict__ ow,
                                                   const float* __restrict__ ob,
                                                   float* __restrict__ out) {
    extern __shared__ char smem_raw[];
    HeadSmem* sm = (HeadSmem*)smem_raw;

    int tid  = threadIdx.x;
    int warp = tid >> 5;
    int lane = tid & 31;

    // ---- weight fills (once per block) ----
    for (int i = tid; i < 12 * FEAT; i += 256) {
        int q = i / FEAT, k = i % FEAT;
        int o0 = 2 * q, g = o0 >> 3, e0 = o0 & 7;
        float2 p = *(const float2*)&gw[((long)g * FEAT + k) * NE + e0];
        sm->gw2[q][k] = pack2(p.x, p.y);
    }
    for (int i = tid; i < 32 * 96; i += 256) {
        int sp = i / 96, j = i % 96;
        int g = j >> 5, t = j & 31;
        float v0 = tw[((long)g * SS + 2 * sp) * TT + t];
        float v1 = tw[((long)g * SS + 2 * sp + 1) * TT + t];
        sm->tw2[sp][j] = pack2(v0, v1);
    }
    for (int i = tid; i < NG * TT; i += 256) {
        sm->ow0[i] = ow[i * 2 + 0];
        sm->ow1[i] = ow[i * 2 + 1];
        sm->tb[i]  = tb[i];
    }
    if (tid < NG * NE) sm->gb[tid] = gb[tid];
    if (tid < NG * 2)  sm->ob[tid] = ob[tid];
    __syncthreads();

    int bA = blockIdx.x * 8 + warp;           // row 0
    int bB = bA + 8192;                        // row 1

    // ---- phase A: gate logit partials (both rows share gw2 loads) ----
    const float* xrA = &g_x[(long)bA * FEAT];
    const float* xrB = &g_x[(long)bB * FEAT];
    float xA[5], xB[5];
    #pragma unroll
    for (int j = 0; j < 5; j++) { xA[j] = xrA[j * 32 + lane]; xB[j] = xrB[j * 32 + lane]; }

    u64 aA[12], aB[12];
    #pragma unroll
    for (int q = 0; q < 12; q++) { aA[q] = 0ull; aB[q] = 0ull; }
    #pragma unroll
    for (int j = 0; j < 5; j++) {
        u64 xvA = pack2(xA[j], xA[j]);
        u64 xvB = pack2(xB[j], xB[j]);
        int k = j * 32 + lane;
        #pragma unroll
        for (int q = 0; q < 12; q++) {
            u64 w = sm->gw2[q][k];
            aA[q] = ffma2(xvA, w, aA[q]);
            aB[q] = ffma2(xvB, w, aB[q]);
        }
    }

    float totA = reduce24(aA, lane);   // lane o holds logit o (o<24)
    float totB = reduce24(aB, lane);

    // ---- lane-parallel softmax (segments of 8 lanes == gate groups) ----
    int oSafe = (lane < 24) ? lane : 0;
    float gvA, gvB;
    {
        float lgA = totA + sm->gb[oSafe];
        float lgB = totB + sm->gb[oSafe];
        float mA = lgA, mB = lgB;
        #pragma unroll
        for (int b = 1; b <= 4; b <<= 1) {
            mA = fmaxf(mA, __shfl_xor_sync(0xFFFFFFFFu, mA, b));
            mB = fmaxf(mB, __shfl_xor_sync(0xFFFFFFFFu, mB, b));
        }
        float eA = __expf(lgA - mA);
        float eB = __expf(lgB - mB);
        float sA = eA, sB = eB;
        #pragma unroll
        for (int b = 1; b <= 4; b <<= 1) {
            sA += __shfl_xor_sync(0xFFFFFFFFu, sA, b);
            sB += __shfl_xor_sync(0xFFFFFFFFu, sB, b);
        }
        gvA = eA * __fdividef(1.f, sA);
        gvB = eB * __fdividef(1.f, sB);
    }
    // broadcast all 24 gates of both rows to every lane
    float gtA[24], gtB[24];
    #pragma unroll
    for (int o = 0; o < 24; o++) {
        gtA[o] = __shfl_sync(0xFFFFFFFFu, gvA, o);
        gtB[o] = __shfl_sync(0xFFFFFFFFu, gvB, o);
    }

    // ---- phase B: mix -> smem (lane owns 6 (g,s) per row) ----
    const float* erA = &g_exp[(long)bA * NCOLS];
    const float* erB = &g_exp[(long)bB * NCOLS];
    __syncwarp();
    #pragma unroll
    for (int i = 0; i < 6; i++) {
        int g = i >> 1;                       // compile-time per i
        int s = (i & 1) * 32 + lane;
        float vA = 0.f, vB = 0.f;
        #pragma unroll
        for (int e = 0; e < NE; e++) {
            vA = fmaf(gtA[g * 8 + e], erA[e * SS + s], vA);
            vB = fmaf(gtB[g * 8 + e], erB[e * SS + s], vB);
        }
        sm->mix[warp][0][i * 32 + lane] = vA;
        sm->mix[warp][1][i * 32 + lane] = vB;
    }
    __syncwarp();

    // ---- phase C: tower (lane owns t=lane; s-pairs via ffma2) ----
    float towA[NG], towB[NG];
    #pragma unroll
    for (int g = 0; g < NG; g++) {
        u64 accA = 0ull, accB = 0ull;
        const u64* mA = (const u64*)&sm->mix[warp][0][g * SS];
        const u64* mB = (const u64*)&sm->mix[warp][1][g * SS];
        #pragma unroll 8
        for (int sp = 0; sp < 32; sp++) {
            u64 w = sm->tw2[sp][g * TT + lane];
            accA = ffma2(mA[sp], w, accA);
            accB = ffma2(mB[sp], w, accB);
        }
        float l0, h0, l1, h1;
        unpack2(accA, l0, h0);
        unpack2(accB, l1, h1);
        float bias = sm->tb[g * TT + lane];
        towA[g] = fmaxf(l0 + h0 + bias, 0.f);
        towB[g] = fmaxf(l1 + h1 + bias, 0.f);
    }

    // ---- phase D: out logits + butterfly + epilogue ----
    float lA[6], lB[6];
    #pragma unroll
    for (int g = 0; g < NG; g++) {
        lA[g * 2 + 0] = towA[g] * sm->ow0[g * TT + lane];
        lA[g * 2 + 1] = towA[g] * sm->ow1[g * TT + lane];
        lB[g * 2 + 0] = towB[g] * sm->ow0[g * TT + lane];
        lB[g * 2 + 1] = towB[g] * sm->ow1[g * TT + lane];
    }
    #pragma unroll
    for (int off = 16; off > 0; off >>= 1) {
        #pragma unroll
        for (int o = 0; o < 6; o++) {
            lA[o] += __shfl_xor_sync(0xFFFFFFFFu, lA[o], off);
            lB[o] += __shfl_xor_sync(0xFFFFFFFFu, lB[o], off);
        }
    }

    if (lane < 2) {
        const float* l = (lane == 0) ? lA : lB;
        int b = (lane == 0) ? bA : bB;
        float probs[6];
        #pragma unroll
        for (int g = 0; g < NG; g++) {
            float l0 = l[g * 2 + 0] + sm->ob[g * 2 + 0];
            float l1 = l[g * 2 + 1] + sm->ob[g * 2 + 1];
            float mm = fmaxf(l0, l1);
            float e0 = __expf(l0 - mm), e1 = __expf(l1 - mm);
            float inv = __fdividef(1.f, e0 + e1);
            probs[g * 2 + 0] = fminf(fmaxf(e0 * inv, 1e-15f), 1.f - 1e-15f);
            probs[g * 2 + 1] = fminf(fmaxf(e1 * inv, 1e-15f), 1.f - 1e-15f);
        }
        float cc = probs[1] * probs[3];
        float* o = out + (long)b * 10;
        o[0] = probs[0]; o[1] = probs[1]; o[2] = probs[1];
        o[3] = probs[2]; o[4] = probs[3]; o[5] = probs[3];
        o[6] = 1.f - cc; o[7] = cc; o[8] = cc;
        o[9] = probs[5];
    }
}

extern "C" void kernel_launch(void* const* d_in, const int* in_sizes, int n_in,
                              void* d_out, int out_size) {
    const int*   ids = (const int*)d_in[0];
    const float* emb = (const float*)d_in[1];
    const float* ew  = (const float*)d_in[2];
    const float* eb  = (const float*)d_in[3];
    const float* gw  = (const float*)d_in[4];
    const float* gb  = (const float*)d_in[5];
    const float* tw  = (const float*)d_in[6];
    const float* tb  = (const float*)d_in[7];
    const float* ow  = (const float*)d_in[8];
    const float* ob  = (const float*)d_in[9];
    float* out = (float*)d_out;

    cudaFuncSetAttribute(expert_mma_kernel, cudaFuncAttributeMaxDynamicSharedMemorySize, DYN_SMEM);
    cudaFuncSetAttribute(head_kernel, cudaFuncAttributeMaxDynamicSharedMemorySize,
                         (int)sizeof(HeadSmem));

    wprep_kernel<<<(NCOLS * FEAT + 255) / 256, 256>>>(ew);
    gather_kernel<<<(NF * BATCH) / 64, 256>>>(ids, (const float4*)emb);
    expert_mma_kernel<<<dim3(BATCH / TM, NCOLS / TN), 256, DYN_SMEM>>>(eb);
    head_kernel<<<BATCH / 16, 256, sizeof(HeadSmem)>>>(gw, gb, tw, tb, ow, ob, out);
}

// round 8
// speedup vs baseline: 1.2836x; 1.0740x over previous
#include <cuda_runtime.h>
#include <cuda_bf16.h>
#include <math.h>

typedef unsigned long long u64;
typedef unsigned int u32;

#define BATCH 16384
#define NF 10
#define LL 20
#define DD 16
#define FEAT 160
#define NE 8
#define SS 64
#define NG 3
#define TT 32
#define NCOLS (NE*SS)

// ---- expert tiling: 128x128, K staged in 5 chunks of 32 ----
#define TM 128
#define TN 128
#define SSTRIDE 40                      // u16 per row per stage (80B: ldsm conflict-free)
#define STILE_U16 (128 * SSTRIDE)       // 5120 u16 = 10240 B per tile
#define DYN_E (2 * 4 * STILE_U16 * 2)   // 2 stages x 4 tiles = 81920 B

// Scratch (device globals: no allocation allowed)
__device__ __align__(16) float          g_x  [BATCH * FEAT];
__device__ __align__(16) unsigned short g_xhi[BATCH * FEAT];
__device__ __align__(16) unsigned short g_xlo[BATCH * FEAT];
__device__ __align__(16) unsigned short g_whi[NCOLS * FEAT];
__device__ __align__(16) unsigned short g_wlo[NCOLS * FEAT];
__device__ __align__(16) float          g_exp[BATCH * NCOLS];

// ---------------- helpers ----------------
__device__ __forceinline__ u64 pack2(float lo, float hi) {
    u64 d;
    asm("mov.b64 %0, {%1, %2};" : "=l"(d)
        : "r"(__float_as_uint(lo)), "r"(__float_as_uint(hi)));
    return d;
}
__device__ __forceinline__ void unpack2(u64 v, float &lo, float &hi) {
    unsigned a, b;
    asm("mov.b64 {%0, %1}, %2;" : "=r"(a), "=r"(b) : "l"(v));
    lo = __uint_as_float(a); hi = __uint_as_float(b);
}
__device__ __forceinline__ u64 ffma2(u64 a, u64 b, u64 c) {
    u64 d;
    asm("fma.rn.f32x2 %0, %1, %2, %3;" : "=l"(d) : "l"(a), "l"(b), "l"(c));
    return d;
}
__device__ __forceinline__ u32 smem_u32(const void* p) {
    u32 a;
    asm("{ .reg .u64 t; cvta.to.shared.u64 t, %1; cvt.u32.u64 %0, t; }" : "=r"(a) : "l"(p));
    return a;
}
__device__ __forceinline__ void ldsm4(u32 addr, u32 &r0, u32 &r1, u32 &r2, u32 &r3) {
    asm volatile("ldmatrix.sync.aligned.m8n8.x4.shared.b16 {%0,%1,%2,%3}, [%4];"
                 : "=r"(r0), "=r"(r1), "=r"(r2), "=r"(r3) : "r"(addr));
}
__device__ __forceinline__ void mma16816(float* d, const u32* a, const u32* b) {
    asm volatile("mma.sync.aligned.m16n8k16.row.col.f32.bf16.bf16.f32 "
                 "{%0,%1,%2,%3}, {%4,%5,%6,%7}, {%8,%9}, {%0,%1,%2,%3};"
                 : "+f"(d[0]), "+f"(d[1]), "+f"(d[2]), "+f"(d[3])
                 : "r"(a[0]), "r"(a[1]), "r"(a[2]), "r"(a[3]), "r"(b[0]), "r"(b[1]));
}
#define CP16(dst, src) \
    asm volatile("cp.async.cg.shared.global [%0], [%1], 16;" :: "r"(dst), "l"(src) : "memory")
#define CP_COMMIT() asm volatile("cp.async.commit_group;" ::: "memory")
#define CP_WAIT1()  asm volatile("cp.async.wait_group 1;" ::: "memory")
#define CP_WAIT0()  asm volatile("cp.async.wait_group 0;" ::: "memory")

// Exchange-halving transpose-reduce: 12 packed f32x2 partials (outputs 0..23,
// dup-padded to 32); returns the full sum of output o = lane.
__device__ __forceinline__ float reduce24(const u64* a2, int lane) {
    float A[32];
    #pragma unroll
    for (int q = 0; q < 12; q++) unpack2(a2[q], A[2 * q], A[2 * q + 1]);
    #pragma unroll
    for (int o = 24; o < 32; o++) A[o] = 0.f;

    float B[16];
    {   int kb = lane & 1;
        #pragma unroll
        for (int i = 0; i < 16; i++) {
            float oth = kb ? A[2 * i] : A[2 * i + 1];
            float rc  = __shfl_xor_sync(0xFFFFFFFFu, oth, 1);
            B[i] = (kb ? A[2 * i + 1] : A[2 * i]) + rc;
        }
    }
    float C[8];
    {   int kb = (lane >> 1) & 1;
        #pragma unroll
        for (int i = 0; i < 8; i++) {
            float oth = kb ? B[2 * i] : B[2 * i + 1];
            float rc  = __shfl_xor_sync(0xFFFFFFFFu, oth, 2);
            C[i] = (kb ? B[2 * i + 1] : B[2 * i]) + rc;
        }
    }
    float D[4];
    {   int kb = (lane >> 2) & 1;
        #pragma unroll
        for (int i = 0; i < 4; i++) {
            float oth = kb ? C[2 * i] : C[2 * i + 1];
            float rc  = __shfl_xor_sync(0xFFFFFFFFu, oth, 4);
            D[i] = (kb ? C[2 * i + 1] : C[2 * i]) + rc;
        }
    }
    float E[2];
    {   int kb = (lane >> 3) & 1;
        #pragma unroll
        for (int i = 0; i < 2; i++) {
            float oth = kb ? D[2 * i] : D[2 * i + 1];
            float rc  = __shfl_xor_sync(0xFFFFFFFFu, oth, 8);
            E[i] = (kb ? D[2 * i + 1] : D[2 * i]) + rc;
        }
    }
    {   int kb = (lane >> 4) & 1;
        float oth = kb ? E[0] : E[1];
        float rc  = __shfl_xor_sync(0xFFFFFFFFu, oth, 16);
        return (kb ? E[1] : E[0]) + rc;
    }
}

// ---------------------------------------------------------------------------
// Kernel A: embedding gather + sum (+ fused weight prep on trailing blocks).
// ---------------------------------------------------------------------------
__global__ __launch_bounds__(256) void gather_kernel(const int* __restrict__ ids32,
                                                     const float4* __restrict__ emb,
                                                     const float* __restrict__ ew) {
    if (blockIdx.x >= 2560) {
        // weight transpose + bf16 hi/lo split
        int idx = (blockIdx.x - 2560) * 256 + threadIdx.x;
        if (idx < NCOLS * FEAT) {
            int c = idx & (NCOLS - 1);
            int k = idx >> 9;
            int e = c >> 6, s = c & 63;
            float w = ew[((long)e * FEAT + k) * SS + s];
            __nv_bfloat16 h = __float2bfloat16_rn(w);
            float r = w - __bfloat162float(h);
            __nv_bfloat16 l = __float2bfloat16_rn(r);
            g_whi[(long)c * FEAT + k] = *(unsigned short*)&h;
            g_wlo[(long)c * FEAT + k] = *(unsigned short*)&l;
        }
        return;
    }

    __shared__ int s_is64;
    if (threadIdx.x == 0) {
        const unsigned* w = (const unsigned*)ids32;
        s_is64 = (w[1] == 0u && w[3] == 0u && w[5] == 0u && w[7] == 0u) ? 1 : 0;
    }
    __syncthreads();
    const int is64 = s_is64;

    int tid  = threadIdx.x;
    int p    = blockIdx.x * 64 + (tid >> 2);
    int lane = tid & 3;
    int f = p >> 14;
    int b = p & (BATCH - 1);
    long base = (long)p * LL;

    float4 acc = make_float4(0.f, 0.f, 0.f, 0.f);
    if (is64) {
        #pragma unroll
        for (int l = 0; l < LL; l++) {
            int id = ids32[2 * (base + l)];
            float4 v = __ldg(&emb[(long)id * 4 + lane]);
            acc.x += v.x; acc.y += v.y; acc.z += v.z; acc.w += v.w;
        }
    } else {
        #pragma unroll
        for (int l = 0; l < LL; l++) {
            int id = ids32[base + l];
            float4 v = __ldg(&emb[(long)id * 4 + lane]);
            acc.x += v.x; acc.y += v.y; acc.z += v.z; acc.w += v.w;
        }
    }
    int fb = f * DD + lane * 4;
    long xoff = (long)b * FEAT + fb;
    *(float4*)&g_x[xoff] = acc;

    float vals[4] = {acc.x, acc.y, acc.z, acc.w};
    unsigned short hi[4], lo[4];
    #pragma unroll
    for (int j = 0; j < 4; j++) {
        __nv_bfloat16 h = __float2bfloat16_rn(vals[j]);
        float r = vals[j] - __bfloat162float(h);
        __nv_bfloat16 l = __float2bfloat16_rn(r);
        hi[j] = *(unsigned short*)&h;
        lo[j] = *(unsigned short*)&l;
    }
    *(uint2*)&g_xhi[xoff] = make_uint2((u32)hi[0] | ((u32)hi[1] << 16),
                                       (u32)hi[2] | ((u32)hi[3] << 16));
    *(uint2*)&g_xlo[xoff] = make_uint2((u32)lo[0] | ((u32)lo[1] << 16),
                                       (u32)lo[2] | ((u32)lo[3] << 16));
}

// ---------------------------------------------------------------------------
// Kernel B: experts GEMM, mma.sync bf16 3-term split, k-staged (5 x k32)
// double-buffered cp.async pipeline. 80KB smem -> 2 CTAs/SM.
// ---------------------------------------------------------------------------
__device__ __forceinline__ void fill_stage(u32 smb, int stage, int ks,
                                           int b0, int c0, int tid) {
    int k0 = ks * 32;
    #pragma unroll
    for (int it = 0; it < 8; it++) {
        int idx  = tid + it * 256;
        int tile = idx >> 9;
        int r    = (idx >> 2) & 127;
        int ch   = idx & 3;
        u32 dst = smb + (u32)(((stage * 4 + tile) * STILE_U16 + r * SSTRIDE + ch * 8) * 2);
        const unsigned short* src;
        if (tile == 0)      src = &g_xhi[(long)(b0 + r) * FEAT + k0 + ch * 8];
        else if (tile == 1) src = &g_xlo[(long)(b0 + r) * FEAT + k0 + ch * 8];
        else if (tile == 2) src = &g_whi[(long)(c0 + r) * FEAT + k0 + ch * 8];
        else                src = &g_wlo[(long)(c0 + r) * FEAT + k0 + ch * 8];
        CP16(dst, src);
    }
}

__global__ void __launch_bounds__(256, 2) expert_mma_kernel(const float* __restrict__ eb) {
    extern __shared__ unsigned short sm16[];
    __shared__ float s_bias[TN];

    int tid  = threadIdx.x;
    int wid  = tid >> 5;
    int lane = tid & 31;
    int b0   = blockIdx.x * TM;
    int c0   = blockIdx.y * TN;

    if (tid < TN) {
        int c = c0 + tid;
        s_bias[tid] = eb[(c >> 6) * SS + (c & 63)];
    }

    u32 smb = smem_u32(sm16);

    fill_stage(smb, 0, 0, b0, c0, tid); CP_COMMIT();
    fill_stage(smb, 1, 1, b0, c0, tid); CP_COMMIT();

    int m0 = (wid >> 1) * 32;
    int n0 = (wid & 1) * 64;

    u32 aOff = (u32)((m0 + (lane & 7) + ((lane & 8) ? 8 : 0)) * SSTRIDE + ((lane & 16) ? 8 : 0)) * 2;
    u32 bOff = (u32)((n0 + (lane & 7) + ((lane & 16) ? 8 : 0)) * SSTRIDE + ((lane & 8) ? 8 : 0)) * 2;

    float acc[2][8][4];
    #pragma unroll
    for (int mt = 0; mt < 2; mt++)
        #pragma unroll
        for (int nt = 0; nt < 8; nt++)
            #pragma unroll
            for (int q = 0; q < 4; q++) acc[mt][nt][q] = 0.f;

    #pragma unroll 1
    for (int ks = 0; ks < 5; ks++) {
        if (ks < 4) CP_WAIT1(); else CP_WAIT0();
        __syncthreads();

        int stage = ks & 1;
        u32 aHiB = smb + (u32)((stage * 4 + 0) * STILE_U16 * 2) + aOff;
        u32 aLoB = smb + (u32)((stage * 4 + 1) * STILE_U16 * 2) + aOff;
        u32 bHiB = smb + (u32)((stage * 4 + 2) * STILE_U16 * 2) + bOff;
        u32 bLoB = smb + (u32)((stage * 4 + 3) * STILE_U16 * 2) + bOff;

        #pragma unroll
        for (int kk = 0; kk < 2; kk++) {
            u32 kb = (u32)(kk * 32);

            u32 ah[2][4], al[2][4];
            #pragma unroll
            for (int mt = 0; mt < 2; mt++) {
                u32 moff = (u32)(mt * 16 * SSTRIDE * 2);
                ldsm4(aHiB + moff + kb, ah[mt][0], ah[mt][1], ah[mt][2], ah[mt][3]);
                ldsm4(aLoB + moff + kb, al[mt][0], al[mt][1], al[mt][2], al[mt][3]);
            }
            u32 bh[4][4], blo[4][4];
            #pragma unroll
            for (int nt2 = 0; nt2 < 4; nt2++) {
                u32 noff = (u32)(nt2 * 16 * SSTRIDE * 2);
                ldsm4(bHiB + noff + kb, bh[nt2][0], bh[nt2][1], bh[nt2][2], bh[nt2][3]);
                ldsm4(bLoB + noff + kb, blo[nt2][0], blo[nt2][1], blo[nt2][2], blo[nt2][3]);
            }

            #pragma unroll
            for (int mt = 0; mt < 2; mt++) {
                #pragma unroll
                for (int nt2 = 0; nt2 < 4; nt2++) {
                    mma16816(acc[mt][2 * nt2],     ah[mt], &bh[nt2][0]);
                    mma16816(acc[mt][2 * nt2 + 1], ah[mt], &bh[nt2][2]);
                    mma16816(acc[mt][2 * nt2],     ah[mt], &blo[nt2][0]);
                    mma16816(acc[mt][2 * nt2 + 1], ah[mt], &blo[nt2][2]);
                    mma16816(acc[mt][2 * nt2],     al[mt], &bh[nt2][0]);
                    mma16816(acc[mt][2 * nt2 + 1], al[mt], &bh[nt2][2]);
                }
            }
        }

        __syncthreads();
        if (ks + 2 < 5) { fill_stage(smb, ks & 1, ks + 2, b0, c0, tid); CP_COMMIT(); }
    }

    #pragma unroll
    for (int mt = 0; mt < 2; mt++) {
        int row = b0 + m0 + mt * 16 + (lane >> 2);
        #pragma unroll
        for (int nt = 0; nt < 8; nt++) {
            int cl = n0 + nt * 8 + (lane & 3) * 2;
            float bi0 = s_bias[cl], bi1 = s_bias[cl + 1];
            float* d = acc[mt][nt];
            *(float2*)&g_exp[(long)row * NCOLS + c0 + cl] =
                make_float2(fmaxf(d[0] + bi0, 0.f), fmaxf(d[1] + bi1, 0.f));
            *(float2*)&g_exp[(long)(row + 8) * NCOLS + c0 + cl] =
                make_float2(fmaxf(d[2] + bi0, 0.f), fmaxf(d[3] + bi1, 0.f));
        }
    }
}

// ---------------------------------------------------------------------------
// Kernel C: head, warp-per-2-rows; all weight/mix smem traffic via LDS.128.
// ---------------------------------------------------------------------------
struct HeadSmem {
    ulonglong2 gw4[6][FEAT];   // gate_w: [q2][k] -> outputs 4q2..4q2+3   15360 B
    ulonglong2 tw4[16][96];    // tower_w: [sp2][g*32+t], s 4sp2..+3      24576 B
    float mix[8][2][192];      // per-warp, per-row mix                   12288 B
    float ow0[NG * TT];
    float ow1[NG * TT];
    float tb[NG * TT];
    float gb[NG * NE];
    float ob[8];
};

__global__ __launch_bounds__(256) void head_kernel(const float* __restrict__ gw,
                                                   const float* __restrict__ gb,
                                                   const float* __restrict__ tw,
                                                   const float* __restrict__ tb,
                                                   const float* __restrict__ ow,
                                                   const float* __restrict__ ob,
                                                   float* __restrict__ out) {
    extern __shared__ char smem_raw[];
    HeadSmem* sm = (HeadSmem*)smem_raw;

    int tid  = threadIdx.x;
    int warp = tid >> 5;
    int lane = tid & 31;

    // ---- weight fills (once per block) ----
    for (int i = tid; i < 6 * FEAT; i += 256) {
        int q2 = i / FEAT, k = i % FEAT;
        int o0 = 4 * q2, g = o0 >> 3, e0 = o0 & 7;
        float4 p = *(const float4*)&gw[((long)g * FEAT + k) * NE + e0];
        ulonglong2 v;
        v.x = pack2(p.x, p.y);
        v.y = pack2(p.z, p.w);
        sm->gw4[q2][k] = v;
    }
    for (int i = tid; i < 16 * 96; i += 256) {
        int sp2 = i / 96, j = i % 96;
        int g = j >> 5, t = j & 31;
        int s0 = 4 * sp2;
        float v0 = tw[((long)g * SS + s0 + 0) * TT + t];
        float v1 = tw[((long)g * SS + s0 + 1) * TT + t];
        float v2 = tw[((long)g * SS + s0 + 2) * TT + t];
        float v3 = tw[((long)g * SS + s0 + 3) * TT + t];
        ulonglong2 v;
        v.x = pack2(v0, v1);
        v.y = pack2(v2, v3);
        sm->tw4[sp2][j] = v;
    }
    for (int i = tid; i < NG * TT; i += 256) {
        sm->ow0[i] = ow[i * 2 + 0];
        sm->ow1[i] = ow[i * 2 + 1];
        sm->tb[i]  = tb[i];
    }
    if (tid < NG * NE) sm->gb[tid] = gb[tid];
    if (tid < NG * 2)  sm->ob[tid] = ob[tid];
    __syncthreads();

    int bA = blockIdx.x * 8 + warp;
    int bB = bA + 8192;

    // ---- phase A: gate logit partials ----
    const float* xrA = &g_x[(long)bA * FEAT];
    const float* xrB = &g_x[(long)bB * FEAT];
    float xA[5], xB[5];
    #pragma unroll
    for (int j = 0; j < 5; j++) { xA[j] = xrA[j * 32 + lane]; xB[j] = xrB[j * 32 + lane]; }

    u64 aA[12], aB[12];
    #pragma unroll
    for (int q = 0; q < 12; q++) { aA[q] = 0ull; aB[q] = 0ull; }
    #pragma unroll
    for (int j = 0; j < 5; j++) {
        u64 xvA = pack2(xA[j], xA[j]);
        u64 xvB = pack2(xB[j], xB[j]);
        int k = j * 32 + lane;
        #pragma unroll
        for (int q2 = 0; q2 < 6; q2++) {
            ulonglong2 w = sm->gw4[q2][k];
            aA[2 * q2]     = ffma2(xvA, w.x, aA[2 * q2]);
            aA[2 * q2 + 1] = ffma2(xvA, w.y, aA[2 * q2 + 1]);
            aB[2 * q2]     = ffma2(xvB, w.x, aB[2 * q2]);
            aB[2 * q2 + 1] = ffma2(xvB, w.y, aB[2 * q2 + 1]);
        }
    }

    float totA = reduce24(aA, lane);
    float totB = reduce24(aB, lane);

    // ---- lane-parallel softmax ----
    int oSafe = (lane < 24) ? lane : 0;
    float gvA, gvB;
    {
        float lgA = totA + sm->gb[oSafe];
        float lgB = totB + sm->gb[oSafe];
        float mA = lgA, mB = lgB;
        #pragma unroll
        for (int b = 1; b <= 4; b <<= 1) {
            mA = fmaxf(mA, __shfl_xor_sync(0xFFFFFFFFu, mA, b));
            mB = fmaxf(mB, __shfl_xor_sync(0xFFFFFFFFu, mB, b));
        }
        float eA = __expf(lgA - mA);
        float eB = __expf(lgB - mB);
        float sA = eA, sB = eB;
        #pragma unroll
        for (int b = 1; b <= 4; b <<= 1) {
            sA += __shfl_xor_sync(0xFFFFFFFFu, sA, b);
            sB += __shfl_xor_sync(0xFFFFFFFFu, sB, b);
        }
        gvA = eA * __fdividef(1.f, sA);
        gvB = eB * __fdividef(1.f, sB);
    }
    float gtA[24], gtB[24];
    #pragma unroll
    for (int o = 0; o < 24; o++) {
        gtA[o] = __shfl_sync(0xFFFFFFFFu, gvA, o);
        gtB[o] = __shfl_sync(0xFFFFFFFFu, gvB, o);
    }

    // ---- phase B: mix -> smem ----
    const float* erA = &g_exp[(long)bA * NCOLS];
    const float* erB = &g_exp[(long)bB * NCOLS];
    #pragma unroll
    for (int i = 0; i < 6; i++) {
        int g = i >> 1;
        int s = (i & 1) * 32 + lane;
        float vA = 0.f, vB = 0.f;
        #pragma unroll
        for (int e = 0; e < NE; e++) {
            vA = fmaf(gtA[g * 8 + e], erA[e * SS + s], vA);
            vB = fmaf(gtB[g * 8 + e], erB[e * SS + s], vB);
        }
        sm->mix[warp][0][i * 32 + lane] = vA;
        sm->mix[warp][1][i * 32 + lane] = vB;
    }
    __syncwarp();

    // ---- phase C: tower (LDS.128 pairs over s) ----
    float towA[NG], towB[NG];
    #pragma unroll
    for (int g = 0; g < NG; g++) {
        u64 accA = 0ull, accB = 0ull;
        const ulonglong2* mA = (const ulonglong2*)&sm->mix[warp][0][g * SS];
        const ulonglong2* mB = (const ulonglong2*)&sm->mix[warp][1][g * SS];
        #pragma unroll
        for (int sp2 = 0; sp2 < 16; sp2++) {
            ulonglong2 w  = sm->tw4[sp2][g * 32 + lane];
            ulonglong2 ma = mA[sp2];
            ulonglong2 mb = mB[sp2];
            accA = ffma2(ma.x, w.x, accA);
            accA = ffma2(ma.y, w.y, accA);
            accB = ffma2(mb.x, w.x, accB);
            accB = ffma2(mb.y, w.y, accB);
        }
        float l0, h0, l1, h1;
        unpack2(accA, l0, h0);
        unpack2(accB, l1, h1);
        float bias = sm->tb[g * TT + lane];
        towA[g] = fmaxf(l0 + h0 + bias, 0.f);
        towB[g] = fmaxf(l1 + h1 + bias, 0.f);
    }

    // ---- phase D: out logits + butterfly + epilogue ----
    float lA[6], lB[6];
    #pragma unroll
    for (int g = 0; g < NG; g++) {
        lA[g * 2 + 0] = towA[g] * sm->ow0[g * TT + lane];
        lA[g * 2 + 1] = towA[g] * sm->ow1[g * TT + lane];
        lB[g * 2 + 0] = towB[g] * sm->ow0[g * TT + lane];
        lB[g * 2 + 1] = towB[g] * sm->ow1[g * TT + lane];
    }
    #pragma unroll
    for (int off = 16; off > 0; off >>= 1) {
        #pragma unroll
        for (int o = 0; o < 6; o++) {
            lA[o] += __shfl_xor_sync(0xFFFFFFFFu, lA[o], off);
            lB[o] += __shfl_xor_sync(0xFFFFFFFFu, lB[o], off);
        }
    }

    if (lane < 2) {
        const float* l = (lane == 0) ? lA : lB;
        int b = (lane == 0) ? bA : bB;
        float probs[6];
        #pragma unroll
        for (int g = 0; g < NG; g++) {
            float l0 = l[g * 2 + 0] + sm->ob[g * 2 + 0];
            float l1 = l[g * 2 + 1] + sm->ob[g * 2 + 1];
            float mm = fmaxf(l0, l1);
            float e0 = __expf(l0 - mm), e1 = __expf(l1 - mm);
            float inv = __fdividef(1.f, e0 + e1);
            probs[g * 2 + 0] = fminf(fmaxf(e0 * inv, 1e-15f), 1.f - 1e-15f);
            probs[g * 2 + 1] = fminf(fmaxf(e1 * inv, 1e-15f), 1.f - 1e-15f);
        }
        float cc = probs[1] * probs[3];
        float* o = out + (long)b * 10;
        o[0] = probs[0]; o[1] = probs[1]; o[2] = probs[1];
        o[3] = probs[2]; o[4] = probs[3]; o[5] = probs[3];
        o[6] = 1.f - cc; o[7] = cc; o[8] = cc;
        o[9] = probs[5];
    }
}

extern "C" void kernel_launch(void* const* d_in, const int* in_sizes, int n_in,
                              void* d_out, int out_size) {
    const int*   ids = (const int*)d_in[0];
    const float* emb = (const float*)d_in[1];
    const float* ew  = (const float*)d_in[2];
    const float* eb  = (const float*)d_in[3];
    const float* gw  = (const float*)d_in[4];
    const float* gb  = (const float*)d_in[5];
    const float* tw  = (const float*)d_in[6];
    const float* tb  = (const float*)d_in[7];
    const float* ow  = (const float*)d_in[8];
    const float* ob  = (const float*)d_in[9];
    float* out = (float*)d_out;

    cudaFuncSetAttribute(expert_mma_kernel, cudaFuncAttributeMaxDynamicSharedMemorySize, DYN_E);
    cudaFuncSetAttribute(head_kernel, cudaFuncAttributeMaxDynamicSharedMemorySize,
                         (int)sizeof(HeadSmem));

    gather_kernel<<<2560 + 320, 256>>>(ids, (const float4*)emb, ew);
    expert_mma_kernel<<<dim3(BATCH / TM, NCOLS / TN), 256, DYN_E>>>(eb);
    head_kernel<<<BATCH / 16, 256, sizeof(HeadSmem)>>>(gw, gb, tw, tb, ow, ob, out);
}

// round 9
// speedup vs baseline: 1.3513x; 1.0527x over previous
#include <cuda_runtime.h>
#include <cuda_bf16.h>
#include <cuda_fp16.h>
#include <math.h>

typedef unsigned long long u64;
typedef unsigned int u32;

#define BATCH 16384
#define NF 10
#define LL 20
#define DD 16
#define FEAT 160
#define NE 8
#define SS 64
#define NG 3
#define TT 32
#define NCOLS (NE*SS)

// ---- expert tiling: 128x128, K staged in 5 chunks of 32 ----
#define TM 128
#define TN 128
#define SSTRIDE 40
#define STILE_U16 (128 * SSTRIDE)
#define DYN_E (2 * 4 * STILE_U16 * 2)   // 81920 B

// Scratch (device globals: no allocation allowed)
__device__ __align__(16) float          g_x  [BATCH * FEAT];
__device__ __align__(16) unsigned short g_xhi[BATCH * FEAT];
__device__ __align__(16) unsigned short g_xlo[BATCH * FEAT];
__device__ __align__(16) unsigned short g_whi[NCOLS * FEAT];
__device__ __align__(16) unsigned short g_wlo[NCOLS * FEAT];
__device__ __align__(16) __half         g_exp[BATCH * NCOLS];

// ---------------- helpers ----------------
__device__ __forceinline__ u64 pack2(float lo, float hi) {
    u64 d;
    asm("mov.b64 %0, {%1, %2};" : "=l"(d)
        : "r"(__float_as_uint(lo)), "r"(__float_as_uint(hi)));
    return d;
}
__device__ __forceinline__ void unpack2(u64 v, float &lo, float &hi) {
    unsigned a, b;
    asm("mov.b64 {%0, %1}, %2;" : "=r"(a), "=r"(b) : "l"(v));
    lo = __uint_as_float(a); hi = __uint_as_float(b);
}
__device__ __forceinline__ u64 ffma2(u64 a, u64 b, u64 c) {
    u64 d;
    asm("fma.rn.f32x2 %0, %1, %2, %3;" : "=l"(d) : "l"(a), "l"(b), "l"(c));
    return d;
}
__device__ __forceinline__ u32 smem_u32(const void* p) {
    u32 a;
    asm("{ .reg .u64 t; cvta.to.shared.u64 t, %1; cvt.u32.u64 %0, t; }" : "=r"(a) : "l"(p));
    return a;
}
__device__ __forceinline__ void ldsm4(u32 addr, u32 &r0, u32 &r1, u32 &r2, u32 &r3) {
    asm volatile("ldmatrix.sync.aligned.m8n8.x4.shared.b16 {%0,%1,%2,%3}, [%4];"
                 : "=r"(r0), "=r"(r1), "=r"(r2), "=r"(r3) : "r"(addr));
}
__device__ __forceinline__ void mma16816(float* d, const u32* a, const u32* b) {
    asm volatile("mma.sync.aligned.m16n8k16.row.col.f32.bf16.bf16.f32 "
                 "{%0,%1,%2,%3}, {%4,%5,%6,%7}, {%8,%9}, {%0,%1,%2,%3};"
                 : "+f"(d[0]), "+f"(d[1]), "+f"(d[2]), "+f"(d[3])
                 : "r"(a[0]), "r"(a[1]), "r"(a[2]), "r"(a[3]), "r"(b[0]), "r"(b[1]));
}
#define CP16(dst, src) \
    asm volatile("cp.async.cg.shared.global [%0], [%1], 16;" :: "r"(dst), "l"(src) : "memory")
#define CP_COMMIT() asm volatile("cp.async.commit_group;" ::: "memory")
#define CP_WAIT1()  asm volatile("cp.async.wait_group 1;" ::: "memory")
#define CP_WAIT0()  asm volatile("cp.async.wait_group 0;" ::: "memory")

// Exchange-halving transpose-reduce: 12 packed f32x2 partials (outputs 0..23,
// dup-padded to 32); returns the full sum of output o = lane.
__device__ __forceinline__ float reduce24(const u64* a2, int lane) {
    float A[32];
    #pragma unroll
    for (int q = 0; q < 12; q++) unpack2(a2[q], A[2 * q], A[2 * q + 1]);
    #pragma unroll
    for (int o = 24; o < 32; o++) A[o] = 0.f;

    float B[16];
    {   int kb = lane & 1;
        #pragma unroll
        for (int i = 0; i < 16; i++) {
            float oth = kb ? A[2 * i] : A[2 * i + 1];
            float rc  = __shfl_xor_sync(0xFFFFFFFFu, oth, 1);
            B[i] = (kb ? A[2 * i + 1] : A[2 * i]) + rc;
        }
    }
    float C[8];
    {   int kb = (lane >> 1) & 1;
        #pragma unroll
        for (int i = 0; i < 8; i++) {
            float oth = kb ? B[2 * i] : B[2 * i + 1];
            float rc  = __shfl_xor_sync(0xFFFFFFFFu, oth, 2);
            C[i] = (kb ? B[2 * i + 1] : B[2 * i]) + rc;
        }
    }
    float D[4];
    {   int kb = (lane >> 2) & 1;
        #pragma unroll
        for (int i = 0; i < 4; i++) {
            float oth = kb ? C[2 * i] : C[2 * i + 1];
            float rc  = __shfl_xor_sync(0xFFFFFFFFu, oth, 4);
            D[i] = (kb ? C[2 * i + 1] : C[2 * i]) + rc;
        }
    }
    float E[2];
    {   int kb = (lane >> 3) & 1;
        #pragma unroll
        for (int i = 0; i < 2; i++) {
            float oth = kb ? D[2 * i] : D[2 * i + 1];
            float rc  = __shfl_xor_sync(0xFFFFFFFFu, oth, 8);
            E[i] = (kb ? D[2 * i + 1] : D[2 * i]) + rc;
        }
    }
    {   int kb = (lane >> 4) & 1;
        float oth = kb ? E[0] : E[1];
        float rc  = __shfl_xor_sync(0xFFFFFFFFu, oth, 16);
        return (kb ? E[1] : E[0]) + rc;
    }
}

// ---------------------------------------------------------------------------
// Kernel A: embedding gather + sum (+ fused weight prep on trailing blocks).
// Vectorized id loads (ulonglong2 / int4).
// ---------------------------------------------------------------------------
__global__ __launch_bounds__(256) void gather_kernel(const int* __restrict__ ids32,
                                                     const float4* __restrict__ emb,
                                                     const float* __restrict__ ew) {
    if (blockIdx.x >= 2560) {
        int idx = (blockIdx.x - 2560) * 256 + threadIdx.x;
        if (idx < NCOLS * FEAT) {
            int c = idx & (NCOLS - 1);
            int k = idx >> 9;
            int e = c >> 6, s = c & 63;
            float w = ew[((long)e * FEAT + k) * SS + s];
            __nv_bfloat16 h = __float2bfloat16_rn(w);
            float r = w - __bfloat162float(h);
            __nv_bfloat16 l = __float2bfloat16_rn(r);
            g_whi[(long)c * FEAT + k] = *(unsigned short*)&h;
            g_wlo[(long)c * FEAT + k] = *(unsigned short*)&l;
        }
        return;
    }

    __shared__ int s_is64;
    if (threadIdx.x == 0) {
        const unsigned* w = (const unsigned*)ids32;
        s_is64 = (w[1] == 0u && w[3] == 0u && w[5] == 0u && w[7] == 0u) ? 1 : 0;
    }
    __syncthreads();
    const int is64 = s_is64;

    int tid  = threadIdx.x;
    int p    = blockIdx.x * 64 + (tid >> 2);
    int lane = tid & 3;
    int f = p >> 14;
    int b = p & (BATCH - 1);
    long base = (long)p * LL;

    float4 acc = make_float4(0.f, 0.f, 0.f, 0.f);
    if (is64) {
        const ulonglong2* idv = (const ulonglong2*)(ids32 + 2 * base);  // 16B aligned
        #pragma unroll
        for (int l2 = 0; l2 < 10; l2++) {
            ulonglong2 two = __ldg(&idv[l2]);
            int id0 = (int)two.x;
            int id1 = (int)two.y;
            float4 v0 = __ldg(&emb[(long)id0 * 4 + lane]);
            float4 v1 = __ldg(&emb[(long)id1 * 4 + lane]);
            acc.x += v0.x + v1.x; acc.y += v0.y + v1.y;
            acc.z += v0.z + v1.z; acc.w += v0.w + v1.w;
        }
    } else {
        const int4* idv = (const int4*)(ids32 + base);  // 16B aligned (p*80)
        #pragma unroll
        for (int l4 = 0; l4 < 5; l4++) {
            int4 four = __ldg(&idv[l4]);
            float4 v0 = __ldg(&emb[(long)four.x * 4 + lane]);
            float4 v1 = __ldg(&emb[(long)four.y * 4 + lane]);
            float4 v2 = __ldg(&emb[(long)four.z * 4 + lane]);
            float4 v3 = __ldg(&emb[(long)four.w * 4 + lane]);
            acc.x += (v0.x + v1.x) + (v2.x + v3.x);
            acc.y += (v0.y + v1.y) + (v2.y + v3.y);
            acc.z += (v0.z + v1.z) + (v2.z + v3.z);
            acc.w += (v0.w + v1.w) + (v2.w + v3.w);
        }
    }
    int fb = f * DD + lane * 4;
    long xoff = (long)b * FEAT + fb;
    *(float4*)&g_x[xoff] = acc;

    float vals[4] = {acc.x, acc.y, acc.z, acc.w};
    unsigned short hi[4], lo[4];
    #pragma unroll
    for (int j = 0; j < 4; j++) {
        __nv_bfloat16 h = __float2bfloat16_rn(vals[j]);
        float r = vals[j] - __bfloat162float(h);
        __nv_bfloat16 l = __float2bfloat16_rn(r);
        hi[j] = *(unsigned short*)&h;
        lo[j] = *(unsigned short*)&l;
    }
    *(uint2*)&g_xhi[xoff] = make_uint2((u32)hi[0] | ((u32)hi[1] << 16),
                                       (u32)hi[2] | ((u32)hi[3] << 16));
    *(uint2*)&g_xlo[xoff] = make_uint2((u32)lo[0] | ((u32)lo[1] << 16),
                                       (u32)lo[2] | ((u32)lo[3] << 16));
}

// ---------------------------------------------------------------------------
// Kernel B: experts GEMM, mma.sync bf16 3-term split, k-staged double-buffered
// cp.async pipeline, 2 CTAs/SM. Output stored fp16.
// ---------------------------------------------------------------------------
__device__ __forceinline__ void fill_stage(u32 smb, int stage, int ks,
                                           int b0, int c0, int tid) {
    int k0 = ks * 32;
    #pragma unroll
    for (int it = 0; it < 8; it++) {
        int idx  = tid + it * 256;
        int tile = idx >> 9;
        int r    = (idx >> 2) & 127;
        int ch   = idx & 3;
        u32 dst = smb + (u32)(((stage * 4 + tile) * STILE_U16 + r * SSTRIDE + ch * 8) * 2);
        const unsigned short* src;
        if (tile == 0)      src = &g_xhi[(long)(b0 + r) * FEAT + k0 + ch * 8];
        else if (tile == 1) src = &g_xlo[(long)(b0 + r) * FEAT + k0 + ch * 8];
        else if (tile == 2) src = &g_whi[(long)(c0 + r) * FEAT + k0 + ch * 8];
        else                src = &g_wlo[(long)(c0 + r) * FEAT + k0 + ch * 8];
        CP16(dst, src);
    }
}

__global__ void __launch_bounds__(256, 2) expert_mma_kernel(const float* __restrict__ eb) {
    extern __shared__ unsigned short sm16[];
    __shared__ float s_bias[TN];

    int tid  = threadIdx.x;
    int wid  = tid >> 5;
    int lane = tid & 31;
    int b0   = blockIdx.x * TM;
    int c0   = blockIdx.y * TN;

    if (tid < TN) {
        int c = c0 + tid;
        s_bias[tid] = eb[(c >> 6) * SS + (c & 63)];
    }

    u32 smb = smem_u32(sm16);

    fill_stage(smb, 0, 0, b0, c0, tid); CP_COMMIT();
    fill_stage(smb, 1, 1, b0, c0, tid); CP_COMMIT();

    int m0 = (wid >> 1) * 32;
    int n0 = (wid & 1) * 64;

    u32 aOff = (u32)((m0 + (lane & 7) + ((lane & 8) ? 8 : 0)) * SSTRIDE + ((lane & 16) ? 8 : 0)) * 2;
    u32 bOff = (u32)((n0 + (lane & 7) + ((lane & 16) ? 8 : 0)) * SSTRIDE + ((lane & 8) ? 8 : 0)) * 2;

    float acc[2][8][4];
    #pragma unroll
    for (int mt = 0; mt < 2; mt++)
        #pragma unroll
        for (int nt = 0; nt < 8; nt++)
            #pragma unroll
            for (int q = 0; q < 4; q++) acc[mt][nt][q] = 0.f;

    #pragma unroll 1
    for (int ks = 0; ks < 5; ks++) {
        if (ks < 4) CP_WAIT1(); else CP_WAIT0();
        __syncthreads();

        int stage = ks & 1;
        u32 aHiB = smb + (u32)((stage * 4 + 0) * STILE_U16 * 2) + aOff;
        u32 aLoB = smb + (u32)((stage * 4 + 1) * STILE_U16 * 2) + aOff;
        u32 bHiB = smb + (u32)((stage * 4 + 2) * STILE_U16 * 2) + bOff;
        u32 bLoB = smb + (u32)((stage * 4 + 3) * STILE_U16 * 2) + bOff;

        #pragma unroll
        for (int kk = 0; kk < 2; kk++) {
            u32 kb = (u32)(kk * 32);

            u32 ah[2][4], al[2][4];
            #pragma unroll
            for (int mt = 0; mt < 2; mt++) {
                u32 moff = (u32)(mt * 16 * SSTRIDE * 2);
                ldsm4(aHiB + moff + kb, ah[mt][0], ah[mt][1], ah[mt][2], ah[mt][3]);
                ldsm4(aLoB + moff + kb, al[mt][0], al[mt][1], al[mt][2], al[mt][3]);
            }
            u32 bh[4][4], blo[4][4];
            #pragma unroll
            for (int nt2 = 0; nt2 < 4; nt2++) {
                u32 noff = (u32)(nt2 * 16 * SSTRIDE * 2);
                ldsm4(bHiB + noff + kb, bh[nt2][0], bh[nt2][1], bh[nt2][2], bh[nt2][3]);
                ldsm4(bLoB + noff + kb, blo[nt2][0], blo[nt2][1], blo[nt2][2], blo[nt2][3]);
            }

            #pragma unroll
            for (int mt = 0; mt < 2; mt++) {
                #pragma unroll
                for (int nt2 = 0; nt2 < 4; nt2++) {
                    mma16816(acc[mt][2 * nt2],     ah[mt], &bh[nt2][0]);
                    mma16816(acc[mt][2 * nt2 + 1], ah[mt], &bh[nt2][2]);
                    mma16816(acc[mt][2 * nt2],     ah[mt], &blo[nt2][0]);
                    mma16816(acc[mt][2 * nt2 + 1], ah[mt], &blo[nt2][2]);
                    mma16816(acc[mt][2 * nt2],     al[mt], &bh[nt2][0]);
                    mma16816(acc[mt][2 * nt2 + 1], al[mt], &bh[nt2][2]);
                }
            }
        }

        __syncthreads();
        if (ks + 2 < 5) { fill_stage(smb, ks & 1, ks + 2, b0, c0, tid); CP_COMMIT(); }
    }

    #pragma unroll
    for (int mt = 0; mt < 2; mt++) {
        int row = b0 + m0 + mt * 16 + (lane >> 2);
        #pragma unroll
        for (int nt = 0; nt < 8; nt++) {
            int cl = n0 + nt * 8 + (lane & 3) * 2;
            float bi0 = s_bias[cl], bi1 = s_bias[cl + 1];
            float* d = acc[mt][nt];
            *(__half2*)&g_exp[(long)row * NCOLS + c0 + cl] =
                __floats2half2_rn(fmaxf(d[0] + bi0, 0.f), fmaxf(d[1] + bi1, 0.f));
            *(__half2*)&g_exp[(long)(row + 8) * NCOLS + c0 + cl] =
                __floats2half2_rn(fmaxf(d[2] + bi0, 0.f), fmaxf(d[3] + bi1, 0.f));
        }
    }
}

// ---------------------------------------------------------------------------
// Kernel C: head, warp-per-2-rows; LDS.128 weights; half2 exp reads.
// ---------------------------------------------------------------------------
struct HeadSmem {
    ulonglong2 gw4[6][FEAT];   // gate_w: [q2][k]                        15360 B
    ulonglong2 tw4[16][96];    // tower_w: [sp2][g*32+t]                 24576 B
    float mix[8][2][192];      // per-warp, per-row mix                  12288 B
    float ow0[NG * TT];
    float ow1[NG * TT];
    float tb[NG * TT];
    float gb[NG * NE];
    float ob[8];
};

__global__ __launch_bounds__(256) void head_kernel(const float* __restrict__ gw,
                                                   const float* __restrict__ gb,
                                                   const float* __restrict__ tw,
                                                   const float* __restrict__ tb,
                                                   const float* __restrict__ ow,
                                                   const float* __restrict__ ob,
                                                   float* __restrict__ out) {
    extern __shared__ char smem_raw[];
    HeadSmem* sm = (HeadSmem*)smem_raw;

    int tid  = threadIdx.x;
    int warp = tid >> 5;
    int lane = tid & 31;

    for (int i = tid; i < 6 * FEAT; i += 256) {
        int q2 = i / FEAT, k = i % FEAT;
        int o0 = 4 * q2, g = o0 >> 3, e0 = o0 & 7;
        float4 p = *(const float4*)&gw[((long)g * FEAT + k) * NE + e0];
        ulonglong2 v;
        v.x = pack2(p.x, p.y);
        v.y = pack2(p.z, p.w);
        sm->gw4[q2][k] = v;
    }
    for (int i = tid; i < 16 * 96; i += 256) {
        int sp2 = i / 96, j = i % 96;
        int g = j >> 5, t = j & 31;
        int s0 = 4 * sp2;
        float v0 = tw[((long)g * SS + s0 + 0) * TT + t];
        float v1 = tw[((long)g * SS + s0 + 1) * TT + t];
        float v2 = tw[((long)g * SS + s0 + 2) * TT + t];
        float v3 = tw[((long)g * SS + s0 + 3) * TT + t];
        ulonglong2 v;
        v.x = pack2(v0, v1);
        v.y = pack2(v2, v3);
        sm->tw4[sp2][j] = v;
    }
    for (int i = tid; i < NG * TT; i += 256) {
        sm->ow0[i] = ow[i * 2 + 0];
        sm->ow1[i] = ow[i * 2 + 1];
        sm->tb[i]  = tb[i];
    }
    if (tid < NG * NE) sm->gb[tid] = gb[tid];
    if (tid < NG * 2)  sm->ob[tid] = ob[tid];
    __syncthreads();

    int bA = blockIdx.x * 8 + warp;
    int bB = bA + 8192;

    // ---- phase A: gate logit partials ----
    const float* xrA = &g_x[(long)bA * FEAT];
    const float* xrB = &g_x[(long)bB * FEAT];
    float xA[5], xB[5];
    #pragma unroll
    for (int j = 0; j < 5; j++) { xA[j] = xrA[j * 32 + lane]; xB[j] = xrB[j * 32 + lane]; }

    u64 aA[12], aB[12];
    #pragma unroll
    for (int q = 0; q < 12; q++) { aA[q] = 0ull; aB[q] = 0ull; }
    #pragma unroll
    for (int j = 0; j < 5; j++) {
        u64 xvA = pack2(xA[j], xA[j]);
        u64 xvB = pack2(xB[j], xB[j]);
        int k = j * 32 + lane;
        #pragma unroll
        for (int q2 = 0; q2 < 6; q2++) {
            ulonglong2 w = sm->gw4[q2][k];
            aA[2 * q2]     = ffma2(xvA, w.x, aA[2 * q2]);
            aA[2 * q2 + 1] = ffma2(xvA, w.y, aA[2 * q2 + 1]);
            aB[2 * q2]     = ffma2(xvB, w.x, aB[2 * q2]);
            aB[2 * q2 + 1] = ffma2(xvB, w.y, aB[2 * q2 + 1]);
        }
    }

    float totA = reduce24(aA, lane);
    float totB = reduce24(aB, lane);

    // ---- lane-parallel softmax ----
    int oSafe = (lane < 24) ? lane : 0;
    float gvA, gvB;
    {
        float lgA = totA + sm->gb[oSafe];
        float lgB = totB + sm->gb[oSafe];
        float mA = lgA, mB = lgB;
        #pragma unroll
        for (int b = 1; b <= 4; b <<= 1) {
            mA = fmaxf(mA, __shfl_xor_sync(0xFFFFFFFFu, mA, b));
            mB = fmaxf(mB, __shfl_xor_sync(0xFFFFFFFFu, mB, b));
        }
        float eA = __expf(lgA - mA);
        float eB = __expf(lgB - mB);
        float sA = eA, sB = eB;
        #pragma unroll
        for (int b = 1; b <= 4; b <<= 1) {
            sA += __shfl_xor_sync(0xFFFFFFFFu, sA, b);
            sB += __shfl_xor_sync(0xFFFFFFFFu, sB, b);
        }
        gvA = eA * __fdividef(1.f, sA);
        gvB = eB * __fdividef(1.f, sB);
    }
    float gtA[24], gtB[24];
    #pragma unroll
    for (int o = 0; o < 24; o++) {
        gtA[o] = __shfl_sync(0xFFFFFFFFu, gvA, o);
        gtB[o] = __shfl_sync(0xFFFFFFFFu, gvB, o);
    }

    // ---- phase B: mix -> smem (half2 loads; lane owns s = 2*lane, 2*lane+1) ----
    const __half2* erA = (const __half2*)&g_exp[(long)bA * NCOLS];
    const __half2* erB = (const __half2*)&g_exp[(long)bB * NCOLS];
    #pragma unroll
    for (int g = 0; g < NG; g++) {
        float vA0 = 0.f, vA1 = 0.f, vB0 = 0.f, vB1 = 0.f;
        #pragma unroll
        for (int e = 0; e < NE; e++) {
            float2 fa = __half22float2(erA[e * (SS / 2) + lane]);
            float2 fb = __half22float2(erB[e * (SS / 2) + lane]);
            float ga = gtA[g * 8 + e], gbv = gtB[g * 8 + e];
            vA0 = fmaf(ga, fa.x, vA0);
            vA1 = fmaf(ga, fa.y, vA1);
            vB0 = fmaf(gbv, fb.x, vB0);
            vB1 = fmaf(gbv, fb.y, vB1);
        }
        *(float2*)&sm->mix[warp][0][g * SS + 2 * lane] = make_float2(vA0, vA1);
        *(float2*)&sm->mix[warp][1][g * SS + 2 * lane] = make_float2(vB0, vB1);
    }
    __syncwarp();

    // ---- phase C: tower (LDS.128 over s) ----
    float towA[NG], towB[NG];
    #pragma unroll
    for (int g = 0; g < NG; g++) {
        u64 accA = 0ull, accB = 0ull;
        const ulonglong2* mA = (const ulonglong2*)&sm->mix[warp][0][g * SS];
        const ulonglong2* mB = (const ulonglong2*)&sm->mix[warp][1][g * SS];
        #pragma unroll
        for (int sp2 = 0; sp2 < 16; sp2++) {
            ulonglong2 w  = sm->tw4[sp2][g * 32 + lane];
            ulonglong2 ma = mA[sp2];
            ulonglong2 mb = mB[sp2];
            accA = ffma2(ma.x, w.x, accA);
            accA = ffma2(ma.y, w.y, accA);
            accB = ffma2(mb.x, w.x, accB);
            accB = ffma2(mb.y, w.y, accB);
        }
        float l0, h0, l1, h1;
        unpack2(accA, l0, h0);
        unpack2(accB, l1, h1);
        float bias = sm->tb[g * TT + lane];
        towA[g] = fmaxf(l0 + h0 + bias, 0.f);
        towB[g] = fmaxf(l1 + h1 + bias, 0.f);
    }

    // ---- phase D: out logits + butterfly + epilogue ----
    float lA[6], lB[6];
    #pragma unroll
    for (int g = 0; g < NG; g++) {
        lA[g * 2 + 0] = towA[g] * sm->ow0[g * TT + lane];
        lA[g * 2 + 1] = towA[g] * sm->ow1[g * TT + lane];
        lB[g * 2 + 0] = towB[g] * sm->ow0[g * TT + lane];
        lB[g * 2 + 1] = towB[g] * sm->ow1[g * TT + lane];
    }
    #pragma unroll
    for (int off = 16; off > 0; off >>= 1) {
        #pragma unroll
        for (int o = 0; o < 6; o++) {
            lA[o] += __shfl_xor_sync(0xFFFFFFFFu, lA[o], off);
            lB[o] += __shfl_xor_sync(0xFFFFFFFFu, lB[o], off);
        }
    }

    if (lane < 2) {
        const float* l = (lane == 0) ? lA : lB;
        int b = (lane == 0) ? bA : bB;
        float probs[6];
        #pragma unroll
        for (int g = 0; g < NG; g++) {
            float l0 = l[g * 2 + 0] + sm->ob[g * 2 + 0];
            float l1 = l[g * 2 + 1] + sm->ob[g * 2 + 1];
            float mm = fmaxf(l0, l1);
            float e0 = __expf(l0 - mm), e1 = __expf(l1 - mm);
            float inv = __fdividef(1.f, e0 + e1);
            probs[g * 2 + 0] = fminf(fmaxf(e0 * inv, 1e-15f), 1.f - 1e-15f);
            probs[g * 2 + 1] = fminf(fmaxf(e1 * inv, 1e-15f), 1.f - 1e-15f);
        }
        float cc = probs[1] * probs[3];
        float* o = out + (long)b * 10;
        o[0] = probs[0]; o[1] = probs[1]; o[2] = probs[1];
        o[3] = probs[2]; o[4] = probs[3]; o[5] = probs[3];
        o[6] = 1.f - cc; o[7] = cc; o[8] = cc;
        o[9] = probs[5];
    }
}

extern "C" void kernel_launch(void* const* d_in, const int* in_sizes, int n_in,
                              void* d_out, int out_size) {
    const int*   ids = (const int*)d_in[0];
    const float* emb = (const float*)d_in[1];
    const float* ew  = (const float*)d_in[2];
    const float* eb  = (const float*)d_in[3];
    const float* gw  = (const float*)d_in[4];
    const float* gb  = (const float*)d_in[5];
    const float* tw  = (const float*)d_in[6];
    const float* tb  = (const float*)d_in[7];
    const float* ow  = (const float*)d_in[8];
    const float* ob  = (const float*)d_in[9];
    float* out = (float*)d_out;

    cudaFuncSetAttribute(expert_mma_kernel, cudaFuncAttributeMaxDynamicSharedMemorySize, DYN_E);
    cudaFuncSetAttribute(head_kernel, cudaFuncAttributeMaxDynamicSharedMemorySize,
                         (int)sizeof(HeadSmem));

    gather_kernel<<<2560 + 320, 256>>>(ids, (const float4*)emb, ew);
    expert_mma_kernel<<<dim3(BATCH / TM, NCOLS / TN), 256, DYN_E>>>(eb);
    head_kernel<<<BATCH / 16, 256, sizeof(HeadSmem)>>>(gw, gb, tw, tb, ow, ob, out);
}

// round 10
// speedup vs baseline: 1.5200x; 1.1249x over previous
#include <cuda_runtime.h>
#include <cuda_bf16.h>
#include <cuda_fp16.h>
#include <math.h>

typedef unsigned long long u64;
typedef unsigned int u32;

#define BATCH 16384
#define NF 10
#define LL 20
#define DD 16
#define FEAT 160
#define NE 8
#define SS 64
#define NG 3
#define TT 32
#define NCOLS (NE*SS)

// ---- expert tiling: 128x128, K staged in 5 chunks of 32 ----
#define TM 128
#define TN 128
#define SSTRIDE 40
#define STILE_U16 (128 * SSTRIDE)
#define DYN_E (2 * 4 * STILE_U16 * 2)   // 81920 B

// Scratch (device globals: no allocation allowed)
__device__ __align__(16) unsigned short g_xhi[BATCH * FEAT];
__device__ __align__(16) unsigned short g_xlo[BATCH * FEAT];
__device__ __align__(16) unsigned short g_whi[NCOLS * FEAT];
__device__ __align__(16) unsigned short g_wlo[NCOLS * FEAT];
__device__ __align__(16) unsigned short g_ghi[32 * FEAT];     // gate W^T hi (24 real cols)
__device__ __align__(16) unsigned short g_glo[32 * FEAT];     // gate W^T lo
__device__ __align__(16) float          g_gate[BATCH * 32];   // gate logits (+bias)
__device__ __align__(16) __half         g_exp[BATCH * NCOLS];

// ---------------- helpers ----------------
__device__ __forceinline__ u64 pack2(float lo, float hi) {
    u64 d;
    asm("mov.b64 %0, {%1, %2};" : "=l"(d)
        : "r"(__float_as_uint(lo)), "r"(__float_as_uint(hi)));
    return d;
}
__device__ __forceinline__ void unpack2(u64 v, float &lo, float &hi) {
    unsigned a, b;
    asm("mov.b64 {%0, %1}, %2;" : "=r"(a), "=r"(b) : "l"(v));
    lo = __uint_as_float(a); hi = __uint_as_float(b);
}
__device__ __forceinline__ u64 ffma2(u64 a, u64 b, u64 c) {
    u64 d;
    asm("fma.rn.f32x2 %0, %1, %2, %3;" : "=l"(d) : "l"(a), "l"(b), "l"(c));
    return d;
}
__device__ __forceinline__ u32 smem_u32(const void* p) {
    u32 a;
    asm("{ .reg .u64 t; cvta.to.shared.u64 t, %1; cvt.u32.u64 %0, t; }" : "=r"(a) : "l"(p));
    return a;
}
__device__ __forceinline__ void ldsm4(u32 addr, u32 &r0, u32 &r1, u32 &r2, u32 &r3) {
    asm volatile("ldmatrix.sync.aligned.m8n8.x4.shared.b16 {%0,%1,%2,%3}, [%4];"
                 : "=r"(r0), "=r"(r1), "=r"(r2), "=r"(r3) : "r"(addr));
}
__device__ __forceinline__ void mma16816(float* d, const u32* a, const u32* b) {
    asm volatile("mma.sync.aligned.m16n8k16.row.col.f32.bf16.bf16.f32 "
                 "{%0,%1,%2,%3}, {%4,%5,%6,%7}, {%8,%9}, {%0,%1,%2,%3};"
                 : "+f"(d[0]), "+f"(d[1]), "+f"(d[2]), "+f"(d[3])
                 : "r"(a[0]), "r"(a[1]), "r"(a[2]), "r"(a[3]), "r"(b[0]), "r"(b[1]));
}
#define CP16(dst, src) \
    asm volatile("cp.async.cg.shared.global [%0], [%1], 16;" :: "r"(dst), "l"(src) : "memory")
#define CP_COMMIT() asm volatile("cp.async.commit_group;" ::: "memory")
#define CP_WAIT1()  asm volatile("cp.async.wait_group 1;" ::: "memory")
#define CP_WAIT0()  asm volatile("cp.async.wait_group 0;" ::: "memory")

// ---------------------------------------------------------------------------
// Kernel A: embedding gather + sum (bf16 hi/lo only) + fused weight prep
// (expert W and gate W) on trailing blocks.
// ---------------------------------------------------------------------------
__global__ __launch_bounds__(256) void gather_kernel(const int* __restrict__ ids32,
                                                     const float4* __restrict__ emb,
                                                     const float* __restrict__ ew,
                                                     const float* __restrict__ gwp) {
    if (blockIdx.x >= 2560) {
        int wpidx = (blockIdx.x - 2560) * 256 + threadIdx.x;
        if (wpidx < NCOLS * FEAT) {
            int c = wpidx & (NCOLS - 1);
            int k = wpidx >> 9;
            int e = c >> 6, s = c & 63;
            float w = ew[((long)e * FEAT + k) * SS + s];
            __nv_bfloat16 h = __float2bfloat16_rn(w);
            float r = w - __bfloat162float(h);
            __nv_bfloat16 l = __float2bfloat16_rn(r);
            g_whi[(long)c * FEAT + k] = *(unsigned short*)&h;
            g_wlo[(long)c * FEAT + k] = *(unsigned short*)&l;
        } else if (wpidx < NCOLS * FEAT + 32 * FEAT) {
            int gidx = wpidx - NCOLS * FEAT;
            int c = gidx & 31;
            int k = gidx >> 5;
            float w = 0.f;
            if (c < 24) {
                int g = c >> 3, e = c & 7;
                w = gwp[((long)g * FEAT + k) * NE + e];
            }
            __nv_bfloat16 h = __float2bfloat16_rn(w);
            float r = w - __bfloat162float(h);
            __nv_bfloat16 l = __float2bfloat16_rn(r);
            g_ghi[(long)c * FEAT + k] = *(unsigned short*)&h;
            g_glo[(long)c * FEAT + k] = *(unsigned short*)&l;
        }
        return;
    }

    __shared__ int s_is64;
    if (threadIdx.x == 0) {
        const unsigned* w = (const unsigned*)ids32;
        s_is64 = (w[1] == 0u && w[3] == 0u && w[5] == 0u && w[7] == 0u) ? 1 : 0;
    }
    __syncthreads();
    const int is64 = s_is64;

    int tid  = threadIdx.x;
    int p    = blockIdx.x * 64 + (tid >> 2);
    int lane = tid & 3;
    int f = p >> 14;
    int b = p & (BATCH - 1);
    long base = (long)p * LL;

    float4 acc = make_float4(0.f, 0.f, 0.f, 0.f);
    if (is64) {
        const ulonglong2* idv = (const ulonglong2*)(ids32 + 2 * base);
        #pragma unroll
        for (int l2 = 0; l2 < 10; l2++) {
            ulonglong2 two = __ldg(&idv[l2]);
            int id0 = (int)two.x;
            int id1 = (int)two.y;
            float4 v0 = __ldg(&emb[(long)id0 * 4 + lane]);
            float4 v1 = __ldg(&emb[(long)id1 * 4 + lane]);
            acc.x += v0.x + v1.x; acc.y += v0.y + v1.y;
            acc.z += v0.z + v1.z; acc.w += v0.w + v1.w;
        }
    } else {
        const int4* idv = (const int4*)(ids32 + base);
        #pragma unroll
        for (int l4 = 0; l4 < 5; l4++) {
            int4 four = __ldg(&idv[l4]);
            float4 v0 = __ldg(&emb[(long)four.x * 4 + lane]);
            float4 v1 = __ldg(&emb[(long)four.y * 4 + lane]);
            float4 v2 = __ldg(&emb[(long)four.z * 4 + lane]);
            float4 v3 = __ldg(&emb[(long)four.w * 4 + lane]);
            acc.x += (v0.x + v1.x) + (v2.x + v3.x);
            acc.y += (v0.y + v1.y) + (v2.y + v3.y);
            acc.z += (v0.z + v1.z) + (v2.z + v3.z);
            acc.w += (v0.w + v1.w) + (v2.w + v3.w);
        }
    }
    int fb = f * DD + lane * 4;
    long xoff = (long)b * FEAT + fb;

    float vals[4] = {acc.x, acc.y, acc.z, acc.w};
    unsigned short hi[4], lo[4];
    #pragma unroll
    for (int j = 0; j < 4; j++) {
        __nv_bfloat16 h = __float2bfloat16_rn(vals[j]);
        float r = vals[j] - __bfloat162float(h);
        __nv_bfloat16 l = __float2bfloat16_rn(r);
        hi[j] = *(unsigned short*)&h;
        lo[j] = *(unsigned short*)&l;
    }
    *(uint2*)&g_xhi[xoff] = make_uint2((u32)hi[0] | ((u32)hi[1] << 16),
                                       (u32)hi[2] | ((u32)hi[3] << 16));
    *(uint2*)&g_xlo[xoff] = make_uint2((u32)lo[0] | ((u32)lo[1] << 16),
                                       (u32)lo[2] | ((u32)lo[3] << 16));
}

// ---------------------------------------------------------------------------
// Kernel B: experts GEMM + gates GEMM (blockIdx.y==4), mma.sync bf16 3-term,
// k-staged double-buffered cp.async pipeline, 2 CTAs/SM.
// ---------------------------------------------------------------------------
__device__ __forceinline__ void fill_stage(u32 smb, int stage, int ks,
                                           int b0, int c0, int tid) {
    int k0 = ks * 32;
    #pragma unroll
    for (int it = 0; it < 8; it++) {
        int idx  = tid + it * 256;
        int tile = idx >> 9;
        int r    = (idx >> 2) & 127;
        int ch   = idx & 3;
        u32 dst = smb + (u32)(((stage * 4 + tile) * STILE_U16 + r * SSTRIDE + ch * 8) * 2);
        const unsigned short* src;
        if (tile == 0)      src = &g_xhi[(long)(b0 + r) * FEAT + k0 + ch * 8];
        else if (tile == 1) src = &g_xlo[(long)(b0 + r) * FEAT + k0 + ch * 8];
        else if (tile == 2) src = &g_whi[(long)(c0 + r) * FEAT + k0 + ch * 8];
        else                src = &g_wlo[(long)(c0 + r) * FEAT + k0 + ch * 8];
        CP16(dst, src);
    }
}

__device__ __forceinline__ void fill_gate_stage(u32 smb, int stage, int ks,
                                                int b0, int tid) {
    int k0 = ks * 32;
    #pragma unroll
    for (int it = 0; it < 5; it++) {
        int idx = tid + it * 256;
        if (idx < 1024) {
            int tile = idx >> 9;
            int r    = (idx >> 2) & 127;
            int ch   = idx & 3;
            u32 dst = smb + (u32)(((stage * 4 + tile) * STILE_U16 + r * SSTRIDE + ch * 8) * 2);
            const unsigned short* src = (tile == 0)
                ? &g_xhi[(long)(b0 + r) * FEAT + k0 + ch * 8]
                : &g_xlo[(long)(b0 + r) * FEAT + k0 + ch * 8];
            CP16(dst, src);
        } else if (idx < 1280) {
            int idx2 = idx - 1024;
            int tile = 2 + (idx2 >> 7);
            int r    = (idx2 >> 2) & 31;
            int ch   = idx2 & 3;
            u32 dst = smb + (u32)(((stage * 4 + tile) * STILE_U16 + r * SSTRIDE + ch * 8) * 2);
            const unsigned short* src = (tile == 2)
                ? &g_ghi[(long)r * FEAT + k0 + ch * 8]
                : &g_glo[(long)r * FEAT + k0 + ch * 8];
            CP16(dst, src);
        }
    }
}

__global__ void __launch_bounds__(256, 2) expert_mma_kernel(const float* __restrict__ eb,
                                                            const float* __restrict__ gb) {
    extern __shared__ unsigned short sm16[];
    __shared__ float s_bias[TN];

    int tid  = threadIdx.x;
    int wid  = tid >> 5;
    int lane = tid & 31;
    int b0   = blockIdx.x * TM;

    u32 smb = smem_u32(sm16);

    if (blockIdx.y == 4) {
        // ---- gates: 128 rows x 32 cols (24 real) ----
        if (tid < 32) s_bias[tid] = (tid < 24) ? gb[tid] : 0.f;

        fill_gate_stage(smb, 0, 0, b0, tid); CP_COMMIT();
        fill_gate_stage(smb, 1, 1, b0, tid); CP_COMMIT();

        int m0 = wid * 16;
        u32 aOff = (u32)((m0 + (lane & 15)) * SSTRIDE + ((lane & 16) ? 8 : 0)) * 2;
        u32 bOff = (u32)(((lane & 7) + ((lane & 16) ? 8 : 0)) * SSTRIDE + ((lane & 8) ? 8 : 0)) * 2;

        float acc[4][4];
        #pragma unroll
        for (int nt = 0; nt < 4; nt++)
            #pragma unroll
            for (int q = 0; q < 4; q++) acc[nt][q] = 0.f;

        #pragma unroll 1
        for (int ks = 0; ks < 5; ks++) {
            if (ks < 4) CP_WAIT1(); else CP_WAIT0();
            __syncthreads();

            int stage = ks & 1;
            u32 aHiB = smb + (u32)((stage * 4 + 0) * STILE_U16 * 2) + aOff;
            u32 aLoB = smb + (u32)((stage * 4 + 1) * STILE_U16 * 2) + aOff;
            u32 bHiB = smb + (u32)((stage * 4 + 2) * STILE_U16 * 2) + bOff;
            u32 bLoB = smb + (u32)((stage * 4 + 3) * STILE_U16 * 2) + bOff;

            #pragma unroll
            for (int kk = 0; kk < 2; kk++) {
                u32 kb = (u32)(kk * 32);
                u32 ah[4], al[4];
                ldsm4(aHiB + kb, ah[0], ah[1], ah[2], ah[3]);
                ldsm4(aLoB + kb, al[0], al[1], al[2], al[3]);
                u32 bh[2][4], blo[2][4];
                #pragma unroll
                for (int nt2 = 0; nt2 < 2; nt2++) {
                    u32 noff = (u32)(nt2 * 16 * SSTRIDE * 2);
                    ldsm4(bHiB + noff + kb, bh[nt2][0], bh[nt2][1], bh[nt2][2], bh[nt2][3]);
                    ldsm4(bLoB + noff + kb, blo[nt2][0], blo[nt2][1], blo[nt2][2], blo[nt2][3]);
                }
                #pragma unroll
                for (int nt2 = 0; nt2 < 2; nt2++) {
                    mma16816(acc[2 * nt2],     ah, &bh[nt2][0]);
                    mma16816(acc[2 * nt2 + 1], ah, &bh[nt2][2]);
                    mma16816(acc[2 * nt2],     ah, &blo[nt2][0]);
                    mma16816(acc[2 * nt2 + 1], ah, &blo[nt2][2]);
                    mma16816(acc[2 * nt2],     al, &bh[nt2][0]);
                    mma16816(acc[2 * nt2 + 1], al, &bh[nt2][2]);
                }
            }

            __syncthreads();
            if (ks + 2 < 5) { fill_gate_stage(smb, ks & 1, ks + 2, b0, tid); CP_COMMIT(); }
        }

        int r0 = b0 + m0 + (lane >> 2);
        #pragma unroll
        for (int nt = 0; nt < 3; nt++) {          // cols 0..23 only
            int cl = nt * 8 + (lane & 3) * 2;
            float bi0 = s_bias[cl], bi1 = s_bias[cl + 1];
            g_gate[(long)r0 * 32 + cl]           = acc[nt][0] + bi0;
            g_gate[(long)r0 * 32 + cl + 1]       = acc[nt][1] + bi1;
            g_gate[(long)(r0 + 8) * 32 + cl]     = acc[nt][2] + bi0;
            g_gate[(long)(r0 + 8) * 32 + cl + 1] = acc[nt][3] + bi1;
        }
        return;
    }

    // ---- experts path ----
    int c0 = blockIdx.y * TN;
    if (tid < TN) {
        int c = c0 + tid;
        s_bias[tid] = eb[(c >> 6) * SS + (c & 63)];
    }

    fill_stage(smb, 0, 0, b0, c0, tid); CP_COMMIT();
    fill_stage(smb, 1, 1, b0, c0, tid); CP_COMMIT();

    int m0 = (wid >> 1) * 32;
    int n0 = (wid & 1) * 64;

    u32 aOff = (u32)((m0 + (lane & 15)) * SSTRIDE + ((lane & 16) ? 8 : 0)) * 2;
    u32 bOff = (u32)((n0 + (lane & 7) + ((lane & 16) ? 8 : 0)) * SSTRIDE + ((lane & 8) ? 8 : 0)) * 2;

    float acc[2][8][4];
    #pragma unroll
    for (int mt = 0; mt < 2; mt++)
        #pragma unroll
        for (int nt = 0; nt < 8; nt++)
            #pragma unroll
            for (int q = 0; q < 4; q++) acc[mt][nt][q] = 0.f;

    #pragma unroll 1
    for (int ks = 0; ks < 5; ks++) {
        if (ks < 4) CP_WAIT1(); else CP_WAIT0();
        __syncthreads();

        int stage = ks & 1;
        u32 aHiB = smb + (u32)((stage * 4 + 0) * STILE_U16 * 2) + aOff;
        u32 aLoB = smb + (u32)((stage * 4 + 1) * STILE_U16 * 2) + aOff;
        u32 bHiB = smb + (u32)((stage * 4 + 2) * STILE_U16 * 2) + bOff;
        u32 bLoB = smb + (u32)((stage * 4 + 3) * STILE_U16 * 2) + bOff;

        #pragma unroll
        for (int kk = 0; kk < 2; kk++) {
            u32 kb = (u32)(kk * 32);

            u32 ah[2][4], al[2][4];
            #pragma unroll
            for (int mt = 0; mt < 2; mt++) {
                u32 moff = (u32)(mt * 16 * SSTRIDE * 2);
                ldsm4(aHiB + moff + kb, ah[mt][0], ah[mt][1], ah[mt][2], ah[mt][3]);
                ldsm4(aLoB + moff + kb, al[mt][0], al[mt][1], al[mt][2], al[mt][3]);
            }
            u32 bh[4][4], blo[4][4];
            #pragma unroll
            for (int nt2 = 0; nt2 < 4; nt2++) {
                u32 noff = (u32)(nt2 * 16 * SSTRIDE * 2);
                ldsm4(bHiB + noff + kb, bh[nt2][0], bh[nt2][1], bh[nt2][2], bh[nt2][3]);
                ldsm4(bLoB + noff + kb, blo[nt2][0], blo[nt2][1], blo[nt2][2], blo[nt2][3]);
            }

            #pragma unroll
            for (int mt = 0; mt < 2; mt++) {
                #pragma unroll
                for (int nt2 = 0; nt2 < 4; nt2++) {
                    mma16816(acc[mt][2 * nt2],     ah[mt], &bh[nt2][0]);
                    mma16816(acc[mt][2 * nt2 + 1], ah[mt], &bh[nt2][2]);
                    mma16816(acc[mt][2 * nt2],     ah[mt], &blo[nt2][0]);
                    mma16816(acc[mt][2 * nt2 + 1], ah[mt], &blo[nt2][2]);
                    mma16816(acc[mt][2 * nt2],     al[mt], &bh[nt2][0]);
                    mma16816(acc[mt][2 * nt2 + 1], al[mt], &bh[nt2][2]);
                }
            }
        }

        __syncthreads();
        if (ks + 2 < 5) { fill_stage(smb, ks & 1, ks + 2, b0, c0, tid); CP_COMMIT(); }
    }

    #pragma unroll
    for (int mt = 0; mt < 2; mt++) {
        int row = b0 + m0 + mt * 16 + (lane >> 2);
        #pragma unroll
        for (int nt = 0; nt < 8; nt++) {
            int cl = n0 + nt * 8 + (lane & 3) * 2;
            float bi0 = s_bias[cl], bi1 = s_bias[cl + 1];
            float* d = acc[mt][nt];
            *(__half2*)&g_exp[(long)row * NCOLS + c0 + cl] =
                __floats2half2_rn(fmaxf(d[0] + bi0, 0.f), fmaxf(d[1] + bi1, 0.f));
            *(__half2*)&g_exp[(long)(row + 8) * NCOLS + c0 + cl] =
                __floats2half2_rn(fmaxf(d[2] + bi0, 0.f), fmaxf(d[3] + bi1, 0.f));
        }
    }
}

// ---------------------------------------------------------------------------
// Kernel C: head, warp-per-2-rows; gate logits precomputed in g_gate.
// ---------------------------------------------------------------------------
struct HeadSmem {
    ulonglong2 tw4[16][96];    // tower_w: [sp2][g*32+t]                 24576 B
    float mix[8][2][192];      // per-warp, per-row mix                  12288 B
    float ow0[NG * TT];
    float ow1[NG * TT];
    float tb[NG * TT];
    float ob[8];
};

__global__ __launch_bounds__(256) void head_kernel(const float* __restrict__ tw,
                                                   const float* __restrict__ tb,
                                                   const float* __restrict__ ow,
                                                   const float* __restrict__ ob,
                                                   float* __restrict__ out) {
    extern __shared__ char smem_raw[];
    HeadSmem* sm = (HeadSmem*)smem_raw;

    int tid  = threadIdx.x;
    int warp = tid >> 5;
    int lane = tid & 31;

    for (int i = tid; i < 16 * 96; i += 256) {
        int sp2 = i / 96, j = i % 96;
        int g = j >> 5, t = j & 31;
        int s0 = 4 * sp2;
        float v0 = tw[((long)g * SS + s0 + 0) * TT + t];
        float v1 = tw[((long)g * SS + s0 + 1) * TT + t];
        float v2 = tw[((long)g * SS + s0 + 2) * TT + t];
        float v3 = tw[((long)g * SS + s0 + 3) * TT + t];
        ulonglong2 v;
        v.x = pack2(v0, v1);
        v.y = pack2(v2, v3);
        sm->tw4[sp2][j] = v;
    }
    for (int i = tid; i < NG * TT; i += 256) {
        sm->ow0[i] = ow[i * 2 + 0];
        sm->ow1[i] = ow[i * 2 + 1];
        sm->tb[i]  = tb[i];
    }
    if (tid < NG * 2) sm->ob[tid] = ob[tid];
    __syncthreads();

    int bA = blockIdx.x * 8 + warp;
    int bB = bA + 8192;

    // ---- gate logits from g_gate + lane-parallel softmax ----
    int oSafe = (lane < 24) ? lane : 0;
    float lgA = g_gate[(long)bA * 32 + oSafe];
    float lgB = g_gate[(long)bB * 32 + oSafe];
    float gvA, gvB;
    {
        float mA = lgA, mB = lgB;
        #pragma unroll
        for (int b = 1; b <= 4; b <<= 1) {
            mA = fmaxf(mA, __shfl_xor_sync(0xFFFFFFFFu, mA, b));
            mB = fmaxf(mB, __shfl_xor_sync(0xFFFFFFFFu, mB, b));
        }
        float eA = __expf(lgA - mA);
        float eB = __expf(lgB - mB);
        float sA = eA, sB = eB;
        #pragma unroll
        for (int b = 1; b <= 4; b <<= 1) {
            sA += __shfl_xor_sync(0xFFFFFFFFu, sA, b);
            sB += __shfl_xor_sync(0xFFFFFFFFu, sB, b);
        }
        gvA = eA * __fdividef(1.f, sA);
        gvB = eB * __fdividef(1.f, sB);
    }
    float gtA[24], gtB[24];
    #pragma unroll
    for (int o = 0; o < 24; o++) {
        gtA[o] = __shfl_sync(0xFFFFFFFFu, gvA, o);
        gtB[o] = __shfl_sync(0xFFFFFFFFu, gvB, o);
    }

    // ---- mix -> smem (half2 loads; lane owns s = 2*lane, 2*lane+1) ----
    const __half2* erA = (const __half2*)&g_exp[(long)bA * NCOLS];
    const __half2* erB = (const __half2*)&g_exp[(long)bB * NCOLS];
    #pragma unroll
    for (int g = 0; g < NG; g++) {
        float vA0 = 0.f, vA1 = 0.f, vB0 = 0.f, vB1 = 0.f;
        #pragma unroll
        for (int e = 0; e < NE; e++) {
            float2 fa = __half22float2(erA[e * (SS / 2) + lane]);
            float2 fb = __half22float2(erB[e * (SS / 2) + lane]);
            float ga = gtA[g * 8 + e], gbv = gtB[g * 8 + e];
            vA0 = fmaf(ga, fa.x, vA0);
            vA1 = fmaf(ga, fa.y, vA1);
            vB0 = fmaf(gbv, fb.x, vB0);
            vB1 = fmaf(gbv, fb.y, vB1);
        }
        *(float2*)&sm->mix[warp][0][g * SS + 2 * lane] = make_float2(vA0, vA1);
        *(float2*)&sm->mix[warp][1][g * SS + 2 * lane] = make_float2(vB0, vB1);
    }
    __syncwarp();

    // ---- tower (LDS.128 over s) ----
    float towA[NG], towB[NG];
    #pragma unroll
    for (int g = 0; g < NG; g++) {
        u64 accA = 0ull, accB = 0ull;
        const ulonglong2* mA = (const ulonglong2*)&sm->mix[warp][0][g * SS];
        const ulonglong2* mB = (const ulonglong2*)&sm->mix[warp][1][g * SS];
        #pragma unroll
        for (int sp2 = 0; sp2 < 16; sp2++) {
            ulonglong2 w  = sm->tw4[sp2][g * 32 + lane];
            ulonglong2 ma = mA[sp2];
            ulonglong2 mb = mB[sp2];
            accA = ffma2(ma.x, w.x, accA);
            accA = ffma2(ma.y, w.y, accA);
            accB = ffma2(mb.x, w.x, accB);
            accB = ffma2(mb.y, w.y, accB);
        }
        float l0, h0, l1, h1;
        unpack2(accA, l0, h0);
        unpack2(accB, l1, h1);
        float bias = sm->tb[g * TT + lane];
        towA[g] = fmaxf(l0 + h0 + bias, 0.f);
        towB[g] = fmaxf(l1 + h1 + bias, 0.f);
    }

    // ---- out logits + butterfly + epilogue ----
    float lA[6], lB[6];
    #pragma unroll
    for (int g = 0; g < NG; g++) {
        lA[g * 2 + 0] = towA[g] * sm->ow0[g * TT + lane];
        lA[g * 2 + 1] = towA[g] * sm->ow1[g * TT + lane];
        lB[g * 2 + 0] = towB[g] * sm->ow0[g * TT + lane];
        lB[g * 2 + 1] = towB[g] * sm->ow1[g * TT + lane];
    }
    #pragma unroll
    for (int off = 16; off > 0; off >>= 1) {
        #pragma unroll
        for (int o = 0; o < 6; o++) {
            lA[o] += __shfl_xor_sync(0xFFFFFFFFu, lA[o], off);
            lB[o] += __shfl_xor_sync(0xFFFFFFFFu, lB[o], off);
        }
    }

    if (lane < 2) {
        const float* l = (lane == 0) ? lA : lB;
        int b = (lane == 0) ? bA : bB;
        float probs[6];
        #pragma unroll
        for (int g = 0; g < NG; g++) {
            float l0 = l[g * 2 + 0] + sm->ob[g * 2 + 0];
            float l1 = l[g * 2 + 1] + sm->ob[g * 2 + 1];
            float mm = fmaxf(l0, l1);
            float e0 = __expf(l0 - mm), e1 = __expf(l1 - mm);
            float inv = __fdividef(1.f, e0 + e1);
            probs[g * 2 + 0] = fminf(fmaxf(e0 * inv, 1e-15f), 1.f - 1e-15f);
            probs[g * 2 + 1] = fminf(fmaxf(e1 * inv, 1e-15f), 1.f - 1e-15f);
        }
        float cc = probs[1] * probs[3];
        float* o = out + (long)b * 10;
        o[0] = probs[0]; o[1] = probs[1]; o[2] = probs[1];
        o[3] = probs[2]; o[4] = probs[3]; o[5] = probs[3];
        o[6] = 1.f - cc; o[7] = cc; o[8] = cc;
        o[9] = probs[5];
    }
}

extern "C" void kernel_launch(void* const* d_in, const int* in_sizes, int n_in,
                              void* d_out, int out_size) {
    const int*   ids = (const int*)d_in[0];
    const float* emb = (const float*)d_in[1];
    const float* ew  = (const float*)d_in[2];
    const float* eb  = (const float*)d_in[3];
    const float* gw  = (const float*)d_in[4];
    const float* gb  = (const float*)d_in[5];
    const float* tw  = (const float*)d_in[6];
    const float* tb  = (const float*)d_in[7];
    const float* ow  = (const float*)d_in[8];
    const float* ob  = (const float*)d_in[9];
    float* out = (float*)d_out;

    cudaFuncSetAttribute(expert_mma_kernel, cudaFuncAttributeMaxDynamicSharedMemorySize, DYN_E);
    cudaFuncSetAttribute(head_kernel, cudaFuncAttributeMaxDynamicSharedMemorySize,
                         (int)sizeof(HeadSmem));

    gather_kernel<<<2560 + 340, 256>>>(ids, (const float4*)emb, ew, gw);
    expert_mma_kernel<<<dim3(BATCH / TM, 5), 256, DYN_E>>>(eb, gb);
    head_kernel<<<BATCH / 16, 256, sizeof(HeadSmem)>>>(tw, tb, ow, ob, out);
}

// round 11
// speedup vs baseline: 1.6457x; 1.0827x over previous
#include <cuda_runtime.h>
#include <cuda_bf16.h>
#include <cuda_fp16.h>
#include <math.h>

typedef unsigned long long u64;
typedef unsigned int u32;

#define BATCH 16384
#define NF 10
#define LL 20
#define DD 16
#define FEAT 160
#define NE 8
#define SS 64
#define NG 3
#define TT 32
#define NCOLS (NE*SS)

// ---- expert tiling: 128x128, K staged in 5 chunks of 32, 3 tiles/stage ----
#define TM 128
#define TN 128
#define SSTRIDE 40
#define STILE_U16 (128 * SSTRIDE)
#define DYN_E (2 * 3 * STILE_U16 * 2)   // 61440 B

// Scratch (device globals: no allocation allowed)
__device__ __align__(16) unsigned short g_xhi[BATCH * FEAT];
__device__ __align__(16) unsigned short g_xlo[BATCH * FEAT];
__device__ __align__(16) unsigned short g_whi[NCOLS * FEAT];  // W^T single-rounded bf16
__device__ __align__(16) unsigned short g_ghi[32 * FEAT];     // gate W^T hi (24 real cols)
__device__ __align__(16) unsigned short g_glo[32 * FEAT];     // gate W^T lo
__device__ __align__(16) float          g_gate[BATCH * 32];   // gate logits (+bias)
__device__ __align__(16) __half         g_exp[BATCH * NCOLS];

// ---------------- helpers ----------------
__device__ __forceinline__ u64 pack2(float lo, float hi) {
    u64 d;
    asm("mov.b64 %0, {%1, %2};" : "=l"(d)
        : "r"(__float_as_uint(lo)), "r"(__float_as_uint(hi)));
    return d;
}
__device__ __forceinline__ void unpack2(u64 v, float &lo, float &hi) {
    unsigned a, b;
    asm("mov.b64 {%0, %1}, %2;" : "=r"(a), "=r"(b) : "l"(v));
    lo = __uint_as_float(a); hi = __uint_as_float(b);
}
__device__ __forceinline__ u64 ffma2(u64 a, u64 b, u64 c) {
    u64 d;
    asm("fma.rn.f32x2 %0, %1, %2, %3;" : "=l"(d) : "l"(a), "l"(b), "l"(c));
    return d;
}
__device__ __forceinline__ u32 smem_u32(const void* p) {
    u32 a;
    asm("{ .reg .u64 t; cvta.to.shared.u64 t, %1; cvt.u32.u64 %0, t; }" : "=r"(a) : "l"(p));
    return a;
}
__device__ __forceinline__ void ldsm4(u32 addr, u32 &r0, u32 &r1, u32 &r2, u32 &r3) {
    asm volatile("ldmatrix.sync.aligned.m8n8.x4.shared.b16 {%0,%1,%2,%3}, [%4];"
                 : "=r"(r0), "=r"(r1), "=r"(r2), "=r"(r3) : "r"(addr));
}
__device__ __forceinline__ void mma16816(float* d, const u32* a, const u32* b) {
    asm volatile("mma.sync.aligned.m16n8k16.row.col.f32.bf16.bf16.f32 "
                 "{%0,%1,%2,%3}, {%4,%5,%6,%7}, {%8,%9}, {%0,%1,%2,%3};"
                 : "+f"(d[0]), "+f"(d[1]), "+f"(d[2]), "+f"(d[3])
                 : "r"(a[0]), "r"(a[1]), "r"(a[2]), "r"(a[3]), "r"(b[0]), "r"(b[1]));
}
#define CP16(dst, src) \
    asm volatile("cp.async.cg.shared.global [%0], [%1], 16;" :: "r"(dst), "l"(src) : "memory")
#define CP_COMMIT() asm volatile("cp.async.commit_group;" ::: "memory")
#define CP_WAIT1()  asm volatile("cp.async.wait_group 1;" ::: "memory")
#define CP_WAIT0()  asm volatile("cp.async.wait_group 0;" ::: "memory")

// ---------------------------------------------------------------------------
// Kernel A: embedding gather + sum (bf16 hi/lo) + fused weight prep on
// trailing blocks (expert W single-rounded; gate W hi/lo split).
// ---------------------------------------------------------------------------
__global__ __launch_bounds__(256) void gather_kernel(const int* __restrict__ ids32,
                                                     const float4* __restrict__ emb,
                                                     const float* __restrict__ ew,
                                                     const float* __restrict__ gwp) {
    if (blockIdx.x >= 2560) {
        int wpidx = (blockIdx.x - 2560) * 256 + threadIdx.x;
        if (wpidx < NCOLS * FEAT) {
            int c = wpidx & (NCOLS - 1);
            int k = wpidx >> 9;
            int e = c >> 6, s = c & 63;
            float w = ew[((long)e * FEAT + k) * SS + s];
            __nv_bfloat16 h = __float2bfloat16_rn(w);
            g_whi[(long)c * FEAT + k] = *(unsigned short*)&h;
        } else if (wpidx < NCOLS * FEAT + 32 * FEAT) {
            int gidx = wpidx - NCOLS * FEAT;
            int c = gidx & 31;
            int k = gidx >> 5;
            float w = 0.f;
            if (c < 24) {
                int g = c >> 3, e = c & 7;
                w = gwp[((long)g * FEAT + k) * NE + e];
            }
            __nv_bfloat16 h = __float2bfloat16_rn(w);
            float r = w - __bfloat162float(h);
            __nv_bfloat16 l = __float2bfloat16_rn(r);
            g_ghi[(long)c * FEAT + k] = *(unsigned short*)&h;
            g_glo[(long)c * FEAT + k] = *(unsigned short*)&l;
        }
        return;
    }

    __shared__ int s_is64;
    if (threadIdx.x == 0) {
        const unsigned* w = (const unsigned*)ids32;
        s_is64 = (w[1] == 0u && w[3] == 0u && w[5] == 0u && w[7] == 0u) ? 1 : 0;
    }
    __syncthreads();
    const int is64 = s_is64;

    int tid  = threadIdx.x;
    int p    = blockIdx.x * 64 + (tid >> 2);
    int lane = tid & 3;
    int f = p >> 14;
    int b = p & (BATCH - 1);
    long base = (long)p * LL;

    float4 acc = make_float4(0.f, 0.f, 0.f, 0.f);
    if (is64) {
        const ulonglong2* idv = (const ulonglong2*)(ids32 + 2 * base);
        #pragma unroll
        for (int l2 = 0; l2 < 10; l2++) {
            ulonglong2 two = __ldcs(&idv[l2]);   // streaming: don't pollute L2
            int id0 = (int)two.x;
            int id1 = (int)two.y;
            float4 v0 = __ldg(&emb[(long)id0 * 4 + lane]);
            float4 v1 = __ldg(&emb[(long)id1 * 4 + lane]);
            acc.x += v0.x + v1.x; acc.y += v0.y + v1.y;
            acc.z += v0.z + v1.z; acc.w += v0.w + v1.w;
        }
    } else {
        const int4* idv = (const int4*)(ids32 + base);
        #pragma unroll
        for (int l4 = 0; l4 < 5; l4++) {
            int4 four = __ldcs(&idv[l4]);
            float4 v0 = __ldg(&emb[(long)four.x * 4 + lane]);
            float4 v1 = __ldg(&emb[(long)four.y * 4 + lane]);
            float4 v2 = __ldg(&emb[(long)four.z * 4 + lane]);
            float4 v3 = __ldg(&emb[(long)four.w * 4 + lane]);
            acc.x += (v0.x + v1.x) + (v2.x + v3.x);
            acc.y += (v0.y + v1.y) + (v2.y + v3.y);
            acc.z += (v0.z + v1.z) + (v2.z + v3.z);
            acc.w += (v0.w + v1.w) + (v2.w + v3.w);
        }
    }
    int fb = f * DD + lane * 4;
    long xoff = (long)b * FEAT + fb;

    float vals[4] = {acc.x, acc.y, acc.z, acc.w};
    unsigned short hi[4], lo[4];
    #pragma unroll
    for (int j = 0; j < 4; j++) {
        __nv_bfloat16 h = __float2bfloat16_rn(vals[j]);
        float r = vals[j] - __bfloat162float(h);
        __nv_bfloat16 l = __float2bfloat16_rn(r);
        hi[j] = *(unsigned short*)&h;
        lo[j] = *(unsigned short*)&l;
    }
    *(uint2*)&g_xhi[xoff] = make_uint2((u32)hi[0] | ((u32)hi[1] << 16),
                                       (u32)hi[2] | ((u32)hi[3] << 16));
    *(uint2*)&g_xlo[xoff] = make_uint2((u32)lo[0] | ((u32)lo[1] << 16),
                                       (u32)lo[2] | ((u32)lo[3] << 16));
}

// ---------------------------------------------------------------------------
// Kernel B: experts GEMM (2-term split) + gates GEMM (3-term, blockIdx.y==4).
// k-staged double-buffered cp.async, 3 tiles/stage, 2 CTAs/SM.
// ---------------------------------------------------------------------------
__device__ __forceinline__ void fill_stage(u32 smb, int stage, int ks,
                                           int b0, int c0, int tid) {
    int k0 = ks * 32;
    #pragma unroll
    for (int it = 0; it < 6; it++) {
        int idx  = tid + it * 256;          // < 1536
        int tile = idx / 512;
        int r    = (idx >> 2) & 127;
        int ch   = idx & 3;
        u32 dst = smb + (u32)(((stage * 3 + tile) * STILE_U16 + r * SSTRIDE + ch * 8) * 2);
        const unsigned short* src;
        if (tile == 0)      src = &g_xhi[(long)(b0 + r) * FEAT + k0 + ch * 8];
        else if (tile == 1) src = &g_xlo[(long)(b0 + r) * FEAT + k0 + ch * 8];
        else                src = &g_whi[(long)(c0 + r) * FEAT + k0 + ch * 8];
        CP16(dst, src);
    }
}

__device__ __forceinline__ void fill_gate_stage(u32 smb, int stage, int ks,
                                                int b0, int tid) {
    int k0 = ks * 32;
    #pragma unroll
    for (int it = 0; it < 5; it++) {
        int idx = tid + it * 256;           // < 1280
        if (idx < 1024) {
            int tile = idx >> 9;            // 0: xhi, 1: xlo
            int r    = (idx >> 2) & 127;
            int ch   = idx & 3;
            u32 dst = smb + (u32)(((stage * 3 + tile) * STILE_U16 + r * SSTRIDE + ch * 8) * 2);
            const unsigned short* src = (tile == 0)
                ? &g_xhi[(long)(b0 + r) * FEAT + k0 + ch * 8]
                : &g_xlo[(long)(b0 + r) * FEAT + k0 + ch * 8];
            CP16(dst, src);
        } else {
            int idx2 = idx - 1024;          // < 256
            int half = idx2 >> 7;           // 0: ghi, 1: glo
            int r    = (idx2 >> 2) & 31;
            int ch   = idx2 & 3;
            u32 dst = smb + (u32)(((stage * 3 + 2) * STILE_U16
                                   + (half * 32 + r) * SSTRIDE + ch * 8) * 2);
            const unsigned short* src = half
                ? &g_glo[(long)r * FEAT + k0 + ch * 8]
                : &g_ghi[(long)r * FEAT + k0 + ch * 8];
            CP16(dst, src);
        }
    }
}

__global__ void __launch_bounds__(256, 2) expert_mma_kernel(const float* __restrict__ eb,
                                                            const float* __restrict__ gb) {
    extern __shared__ unsigned short sm16[];
    __shared__ float s_bias[TN];

    int tid  = threadIdx.x;
    int wid  = tid >> 5;
    int lane = tid & 31;
    int b0   = blockIdx.x * TM;

    u32 smb = smem_u32(sm16);

    if (blockIdx.y == 4) {
        // ---- gates: 128 rows x 32 cols (24 real), 3-term split ----
        if (tid < 32) s_bias[tid] = (tid < 24) ? gb[tid] : 0.f;

        fill_gate_stage(smb, 0, 0, b0, tid); CP_COMMIT();
        fill_gate_stage(smb, 1, 1, b0, tid); CP_COMMIT();

        int m0 = wid * 16;
        u32 aOff = (u32)((m0 + (lane & 15)) * SSTRIDE + ((lane & 16) ? 8 : 0)) * 2;
        u32 bOff = (u32)(((lane & 7) + ((lane & 16) ? 8 : 0)) * SSTRIDE + ((lane & 8) ? 8 : 0)) * 2;

        float acc[4][4];
        #pragma unroll
        for (int nt = 0; nt < 4; nt++)
            #pragma unroll
            for (int q = 0; q < 4; q++) acc[nt][q] = 0.f;

        #pragma unroll 1
        for (int ks = 0; ks < 5; ks++) {
            if (ks < 4) CP_WAIT1(); else CP_WAIT0();
            __syncthreads();

            int stage = ks & 1;
            u32 aHiB = smb + (u32)((stage * 3 + 0) * STILE_U16 * 2) + aOff;
            u32 aLoB = smb + (u32)((stage * 3 + 1) * STILE_U16 * 2) + aOff;
            u32 bHiB = smb + (u32)((stage * 3 + 2) * STILE_U16 * 2) + bOff;
            u32 bLoB = bHiB + (u32)(32 * SSTRIDE * 2);

            #pragma unroll
            for (int kk = 0; kk < 2; kk++) {
                u32 kb = (u32)(kk * 32);
                u32 ah[4], al[4];
                ldsm4(aHiB + kb, ah[0], ah[1], ah[2], ah[3]);
                ldsm4(aLoB + kb, al[0], al[1], al[2], al[3]);
                u32 bh[2][4], blo[2][4];
                #pragma unroll
                for (int nt2 = 0; nt2 < 2; nt2++) {
                    u32 noff = (u32)(nt2 * 16 * SSTRIDE * 2);
                    ldsm4(bHiB + noff + kb, bh[nt2][0], bh[nt2][1], bh[nt2][2], bh[nt2][3]);
                    ldsm4(bLoB + noff + kb, blo[nt2][0], blo[nt2][1], blo[nt2][2], blo[nt2][3]);
                }
                #pragma unroll
                for (int nt2 = 0; nt2 < 2; nt2++) {
                    mma16816(acc[2 * nt2],     ah, &bh[nt2][0]);
                    mma16816(acc[2 * nt2 + 1], ah, &bh[nt2][2]);
                    mma16816(acc[2 * nt2],     ah, &blo[nt2][0]);
                    mma16816(acc[2 * nt2 + 1], ah, &blo[nt2][2]);
                    mma16816(acc[2 * nt2],     al, &bh[nt2][0]);
                    mma16816(acc[2 * nt2 + 1], al, &bh[nt2][2]);
                }
            }

            __syncthreads();
            if (ks + 2 < 5) { fill_gate_stage(smb, ks & 1, ks + 2, b0, tid); CP_COMMIT(); }
        }

        int r0 = b0 + m0 + (lane >> 2);
        #pragma unroll
        for (int nt = 0; nt < 3; nt++) {
            int cl = nt * 8 + (lane & 3) * 2;
            float bi0 = s_bias[cl], bi1 = s_bias[cl + 1];
            g_gate[(long)r0 * 32 + cl]           = acc[nt][0] + bi0;
            g_gate[(long)r0 * 32 + cl + 1]       = acc[nt][1] + bi1;
            g_gate[(long)(r0 + 8) * 32 + cl]     = acc[nt][2] + bi0;
            g_gate[(long)(r0 + 8) * 32 + cl + 1] = acc[nt][3] + bi1;
        }
        return;
    }

    // ---- experts path: 2-term split ----
    int c0 = blockIdx.y * TN;
    if (tid < TN) {
        int c = c0 + tid;
        s_bias[tid] = eb[(c >> 6) * SS + (c & 63)];
    }

    fill_stage(smb, 0, 0, b0, c0, tid); CP_COMMIT();
    fill_stage(smb, 1, 1, b0, c0, tid); CP_COMMIT();

    int m0 = (wid >> 1) * 32;
    int n0 = (wid & 1) * 64;

    u32 aOff = (u32)((m0 + (lane & 15)) * SSTRIDE + ((lane & 16) ? 8 : 0)) * 2;
    u32 bOff = (u32)((n0 + (lane & 7) + ((lane & 16) ? 8 : 0)) * SSTRIDE + ((lane & 8) ? 8 : 0)) * 2;

    float acc[2][8][4];
    #pragma unroll
    for (int mt = 0; mt < 2; mt++)
        #pragma unroll
        for (int nt = 0; nt < 8; nt++)
            #pragma unroll
            for (int q = 0; q < 4; q++) acc[mt][nt][q] = 0.f;

    #pragma unroll 1
    for (int ks = 0; ks < 5; ks++) {
        if (ks < 4) CP_WAIT1(); else CP_WAIT0();
        __syncthreads();

        int stage = ks & 1;
        u32 aHiB = smb + (u32)((stage * 3 + 0) * STILE_U16 * 2) + aOff;
        u32 aLoB = smb + (u32)((stage * 3 + 1) * STILE_U16 * 2) + aOff;
        u32 bHiB = smb + (u32)((stage * 3 + 2) * STILE_U16 * 2) + bOff;

        #pragma unroll
        for (int kk = 0; kk < 2; kk++) {
            u32 kb = (u32)(kk * 32);

            u32 ah[2][4], al[2][4];
            #pragma unroll
            for (int mt = 0; mt < 2; mt++) {
                u32 moff = (u32)(mt * 16 * SSTRIDE * 2);
                ldsm4(aHiB + moff + kb, ah[mt][0], ah[mt][1], ah[mt][2], ah[mt][3]);
                ldsm4(aLoB + moff + kb, al[mt][0], al[mt][1], al[mt][2], al[mt][3]);
            }
            u32 bh[4][4];
            #pragma unroll
            for (int nt2 = 0; nt2 < 4; nt2++) {
                u32 noff = (u32)(nt2 * 16 * SSTRIDE * 2);
                ldsm4(bHiB + noff + kb, bh[nt2][0], bh[nt2][1], bh[nt2][2], bh[nt2][3]);
            }

            #pragma unroll
            for (int mt = 0; mt < 2; mt++) {
                #pragma unroll
                for (int nt2 = 0; nt2 < 4; nt2++) {
                    mma16816(acc[mt][2 * nt2],     ah[mt], &bh[nt2][0]);
                    mma16816(acc[mt][2 * nt2 + 1], ah[mt], &bh[nt2][2]);
                    mma16816(acc[mt][2 * nt2],     al[mt], &bh[nt2][0]);
                    mma16816(acc[mt][2 * nt2 + 1], al[mt], &bh[nt2][2]);
                }
            }
        }

        __syncthreads();
        if (ks + 2 < 5) { fill_stage(smb, ks & 1, ks + 2, b0, c0, tid); CP_COMMIT(); }
    }

    #pragma unroll
    for (int mt = 0; mt < 2; mt++) {
        int row = b0 + m0 + mt * 16 + (lane >> 2);
        #pragma unroll
        for (int nt = 0; nt < 8; nt++) {
            int cl = n0 + nt * 8 + (lane & 3) * 2;
            float bi0 = s_bias[cl], bi1 = s_bias[cl + 1];
            float* d = acc[mt][nt];
            *(__half2*)&g_exp[(long)row * NCOLS + c0 + cl] =
                __floats2half2_rn(fmaxf(d[0] + bi0, 0.f), fmaxf(d[1] + bi1, 0.f));
            *(__half2*)&g_exp[(long)(row + 8) * NCOLS + c0 + cl] =
                __floats2half2_rn(fmaxf(d[2] + bi0, 0.f), fmaxf(d[3] + bi1, 0.f));
        }
    }
}

// ---------------------------------------------------------------------------
// Kernel C: head, warp-per-2-rows; gate logits precomputed in g_gate.
// ---------------------------------------------------------------------------
struct HeadSmem {
    ulonglong2 tw4[16][96];
    float mix[8][2][192];
    float ow0[NG * TT];
    float ow1[NG * TT];
    float tb[NG * TT];
    float ob[8];
};

__global__ __launch_bounds__(256) void head_kernel(const float* __restrict__ tw,
                                                   const float* __restrict__ tb,
                                                   const float* __restrict__ ow,
                                                   const float* __restrict__ ob,
                                                   float* __restrict__ out) {
    extern __shared__ char smem_raw[];
    HeadSmem* sm = (HeadSmem*)smem_raw;

    int tid  = threadIdx.x;
    int warp = tid >> 5;
    int lane = tid & 31;

    for (int i = tid; i < 16 * 96; i += 256) {
        int sp2 = i / 96, j = i % 96;
        int g = j >> 5, t = j & 31;
        int s0 = 4 * sp2;
        float v0 = tw[((long)g * SS + s0 + 0) * TT + t];
        float v1 = tw[((long)g * SS + s0 + 1) * TT + t];
        float v2 = tw[((long)g * SS + s0 + 2) * TT + t];
        float v3 = tw[((long)g * SS + s0 + 3) * TT + t];
        ulonglong2 v;
        v.x = pack2(v0, v1);
        v.y = pack2(v2, v3);
        sm->tw4[sp2][j] = v;
    }
    for (int i = tid; i < NG * TT; i += 256) {
        sm->ow0[i] = ow[i * 2 + 0];
        sm->ow1[i] = ow[i * 2 + 1];
        sm->tb[i]  = tb[i];
    }
    if (tid < NG * 2) sm->ob[tid] = ob[tid];
    __syncthreads();

    int bA = blockIdx.x * 8 + warp;
    int bB = bA + 8192;

    int oSafe = (lane < 24) ? lane : 0;
    float lgA = g_gate[(long)bA * 32 + oSafe];
    float lgB = g_gate[(long)bB * 32 + oSafe];
    float gvA, gvB;
    {
        float mA = lgA, mB = lgB;
        #pragma unroll
        for (int b = 1; b <= 4; b <<= 1) {
            mA = fmaxf(mA, __shfl_xor_sync(0xFFFFFFFFu, mA, b));
            mB = fmaxf(mB, __shfl_xor_sync(0xFFFFFFFFu, mB, b));
        }
        float eA = __expf(lgA - mA);
        float eB = __expf(lgB - mB);
        float sA = eA, sB = eB;
        #pragma unroll
        for (int b = 1; b <= 4; b <<= 1) {
            sA += __shfl_xor_sync(0xFFFFFFFFu, sA, b);
            sB += __shfl_xor_sync(0xFFFFFFFFu, sB, b);
        }
        gvA = eA * __fdividef(1.f, sA);
        gvB = eB * __fdividef(1.f, sB);
    }
    float gtA[24], gtB[24];
    #pragma unroll
    for (int o = 0; o < 24; o++) {
        gtA[o] = __shfl_sync(0xFFFFFFFFu, gvA, o);
        gtB[o] = __shfl_sync(0xFFFFFFFFu, gvB, o);
    }

    const __half2* erA = (const __half2*)&g_exp[(long)bA * NCOLS];
    const __half2* erB = (const __half2*)&g_exp[(long)bB * NCOLS];
    #pragma unroll
    for (int g = 0; g < NG; g++) {
        float vA0 = 0.f, vA1 = 0.f, vB0 = 0.f, vB1 = 0.f;
        #pragma unroll
        for (int e = 0; e < NE; e++) {
            float2 fa = __half22float2(erA[e * (SS / 2) + lane]);
            float2 fb = __half22float2(erB[e * (SS / 2) + lane]);
            float ga = gtA[g * 8 + e], gbv = gtB[g * 8 + e];
            vA0 = fmaf(ga, fa.x, vA0);
            vA1 = fmaf(ga, fa.y, vA1);
            vB0 = fmaf(gbv, fb.x, vB0);
            vB1 = fmaf(gbv, fb.y, vB1);
        }
        *(float2*)&sm->mix[warp][0][g * SS + 2 * lane] = make_float2(vA0, vA1);
        *(float2*)&sm->mix[warp][1][g * SS + 2 * lane] = make_float2(vB0, vB1);
    }
    __syncwarp();

    float towA[NG], towB[NG];
    #pragma unroll
    for (int g = 0; g < NG; g++) {
        u64 accA = 0ull, accB = 0ull;
        const ulonglong2* mA = (const ulonglong2*)&sm->mix[warp][0][g * SS];
        const ulonglong2* mB = (const ulonglong2*)&sm->mix[warp][1][g * SS];
        #pragma unroll
        for (int sp2 = 0; sp2 < 16; sp2++) {
            ulonglong2 w  = sm->tw4[sp2][g * 32 + lane];
            ulonglong2 ma = mA[sp2];
            ulonglong2 mb = mB[sp2];
            accA = ffma2(ma.x, w.x, accA);
            accA = ffma2(ma.y, w.y, accA);
            accB = ffma2(mb.x, w.x, accB);
            accB = ffma2(mb.y, w.y, accB);
        }
        float l0, h0, l1, h1;
        unpack2(accA, l0, h0);
        unpack2(accB, l1, h1);
        float bias = sm->tb[g * TT + lane];
        towA[g] = fmaxf(l0 + h0 + bias, 0.f);
        towB[g] = fmaxf(l1 + h1 + bias, 0.f);
    }

    float lA[6], lB[6];
    #pragma unroll
    for (int g = 0; g < NG; g++) {
        lA[g * 2 + 0] = towA[g] * sm->ow0[g * TT + lane];
        lA[g * 2 + 1] = towA[g] * sm->ow1[g * TT + lane];
        lB[g * 2 + 0] = towB[g] * sm->ow0[g * TT + lane];
        lB[g * 2 + 1] = towB[g] * sm->ow1[g * TT + lane];
    }
    #pragma unroll
    for (int off = 16; off > 0; off >>= 1) {
        #pragma unroll
        for (int o = 0; o < 6; o++) {
            lA[o] += __shfl_xor_sync(0xFFFFFFFFu, lA[o], off);
            lB[o] += __shfl_xor_sync(0xFFFFFFFFu, lB[o], off);
        }
    }

    if (lane < 2) {
        const float* l = (lane == 0) ? lA : lB;
        int b = (lane == 0) ? bA : bB;
        float probs[6];
        #pragma unroll
        for (int g = 0; g < NG; g++) {
            float l0 = l[g * 2 + 0] + sm->ob[g * 2 + 0];
            float l1 = l[g * 2 + 1] + sm->ob[g * 2 + 1];
            float mm = fmaxf(l0, l1);
            float e0 = __expf(l0 - mm), e1 = __expf(l1 - mm);
            float inv = __fdividef(1.f, e0 + e1);
            probs[g * 2 + 0] = fminf(fmaxf(e0 * inv, 1e-15f), 1.f - 1e-15f);
            probs[g * 2 + 1] = fminf(fmaxf(e1 * inv, 1e-15f), 1.f - 1e-15f);
        }
        float cc = probs[1] * probs[3];
        float* o = out + (long)b * 10;
        o[0] = probs[0]; o[1] = probs[1]; o[2] = probs[1];
        o[3] = probs[2]; o[4] = probs[3]; o[5] = probs[3];
        o[6] = 1.f - cc; o[7] = cc; o[8] = cc;
        o[9] = probs[5];
    }
}

extern "C" void kernel_launch(void* const* d_in, const int* in_sizes, int n_in,
                              void* d_out, int out_size) {
    const int*   ids = (const int*)d_in[0];
    const float* emb = (const float*)d_in[1];
    const float* ew  = (const float*)d_in[2];
    const float* eb  = (const float*)d_in[3];
    const float* gw  = (const float*)d_in[4];
    const float* gb  = (const float*)d_in[5];
    const float* tw  = (const float*)d_in[6];
    const float* tb  = (const float*)d_in[7];
    const float* ow  = (const float*)d_in[8];
    const float* ob  = (const float*)d_in[9];
    float* out = (float*)d_out;

    cudaFuncSetAttribute(expert_mma_kernel, cudaFuncAttributeMaxDynamicSharedMemorySize, DYN_E);
    cudaFuncSetAttribute(head_kernel, cudaFuncAttributeMaxDynamicSharedMemorySize,
                         (int)sizeof(HeadSmem));

    gather_kernel<<<2560 + 340, 256>>>(ids, (const float4*)emb, ew, gw);
    expert_mma_kernel<<<dim3(BATCH / TM, 5), 256, DYN_E>>>(eb, gb);
    head_kernel<<<BATCH / 16, 256, sizeof(HeadSmem)>>>(tw, tb, ow, ob, out);
}

// round 12
// speedup vs baseline: 1.7314x; 1.0521x over previous
#include <cuda_runtime.h>
#include <cuda_bf16.h>
#include <cuda_fp16.h>
#include <math.h>

typedef unsigned long long u64;
typedef unsigned int u32;

#define BATCH 16384
#define NF 10
#define LL 20
#define DD 16
#define FEAT 160
#define NE 8
#define SS 64
#define NG 3
#define TT 32
#define NCOLS (NE*SS)

// ---- expert tiling: 128x128, K staged in 5 chunks of 32, 3 tile slots ----
#define TM 128
#define TN 128
#define SSTRIDE 40
#define STILE_U16 (128 * SSTRIDE)
#define DYN_E (2 * 3 * STILE_U16 * 2)   // 61440 B (slot 1 used by gates only)

// Scratch (device globals: no allocation allowed)
__device__ __align__(16) unsigned short g_xhi[BATCH * FEAT];
__device__ __align__(16) unsigned short g_xlo[BATCH * FEAT];
__device__ __align__(16) unsigned short g_whi[NCOLS * FEAT];  // W^T single-rounded bf16
__device__ __align__(16) unsigned short g_ghi[32 * FEAT];     // gate W^T hi (24 real cols)
__device__ __align__(16) unsigned short g_glo[32 * FEAT];     // gate W^T lo
__device__ __align__(16) float          g_gate[BATCH * 32];   // gate logits (+bias)
__device__ __align__(16) __half         g_exp[BATCH * NCOLS];

// ---------------- helpers ----------------
__device__ __forceinline__ u64 pack2(float lo, float hi) {
    u64 d;
    asm("mov.b64 %0, {%1, %2};" : "=l"(d)
        : "r"(__float_as_uint(lo)), "r"(__float_as_uint(hi)));
    return d;
}
__device__ __forceinline__ void unpack2(u64 v, float &lo, float &hi) {
    unsigned a, b;
    asm("mov.b64 {%0, %1}, %2;" : "=r"(a), "=r"(b) : "l"(v));
    lo = __uint_as_float(a); hi = __uint_as_float(b);
}
__device__ __forceinline__ u64 ffma2(u64 a, u64 b, u64 c) {
    u64 d;
    asm("fma.rn.f32x2 %0, %1, %2, %3;" : "=l"(d) : "l"(a), "l"(b), "l"(c));
    return d;
}
__device__ __forceinline__ u32 smem_u32(const void* p) {
    u32 a;
    asm("{ .reg .u64 t; cvta.to.shared.u64 t, %1; cvt.u32.u64 %0, t; }" : "=r"(a) : "l"(p));
    return a;
}
__device__ __forceinline__ void ldsm4(u32 addr, u32 &r0, u32 &r1, u32 &r2, u32 &r3) {
    asm volatile("ldmatrix.sync.aligned.m8n8.x4.shared.b16 {%0,%1,%2,%3}, [%4];"
                 : "=r"(r0), "=r"(r1), "=r"(r2), "=r"(r3) : "r"(addr));
}
__device__ __forceinline__ void mma16816(float* d, const u32* a, const u32* b) {
    asm volatile("mma.sync.aligned.m16n8k16.row.col.f32.bf16.bf16.f32 "
                 "{%0,%1,%2,%3}, {%4,%5,%6,%7}, {%8,%9}, {%0,%1,%2,%3};"
                 : "+f"(d[0]), "+f"(d[1]), "+f"(d[2]), "+f"(d[3])
                 : "r"(a[0]), "r"(a[1]), "r"(a[2]), "r"(a[3]), "r"(b[0]), "r"(b[1]));
}
#define CP16(dst, src) \
    asm volatile("cp.async.cg.shared.global [%0], [%1], 16;" :: "r"(dst), "l"(src) : "memory")
#define CP_COMMIT() asm volatile("cp.async.commit_group;" ::: "memory")
#define CP_WAIT1()  asm volatile("cp.async.wait_group 1;" ::: "memory")
#define CP_WAIT0()  asm volatile("cp.async.wait_group 0;" ::: "memory")

// ---------------------------------------------------------------------------
// Kernel A: embedding gather + sum (bf16 hi/lo) + fused weight prep.
// ---------------------------------------------------------------------------
__global__ __launch_bounds__(256) void gather_kernel(const int* __restrict__ ids32,
                                                     const float4* __restrict__ emb,
                                                     const float* __restrict__ ew,
                                                     const float* __restrict__ gwp) {
    if (blockIdx.x >= 2560) {
        int wpidx = (blockIdx.x - 2560) * 256 + threadIdx.x;
        if (wpidx < NCOLS * FEAT) {
            int c = wpidx & (NCOLS - 1);
            int k = wpidx >> 9;
            int e = c >> 6, s = c & 63;
            float w = ew[((long)e * FEAT + k) * SS + s];
            __nv_bfloat16 h = __float2bfloat16_rn(w);
            g_whi[(long)c * FEAT + k] = *(unsigned short*)&h;
        } else if (wpidx < NCOLS * FEAT + 32 * FEAT) {
            int gidx = wpidx - NCOLS * FEAT;
            int c = gidx & 31;
            int k = gidx >> 5;
            float w = 0.f;
            if (c < 24) {
                int g = c >> 3, e = c & 7;
                w = gwp[((long)g * FEAT + k) * NE + e];
            }
            __nv_bfloat16 h = __float2bfloat16_rn(w);
            float r = w - __bfloat162float(h);
            __nv_bfloat16 l = __float2bfloat16_rn(r);
            g_ghi[(long)c * FEAT + k] = *(unsigned short*)&h;
            g_glo[(long)c * FEAT + k] = *(unsigned short*)&l;
        }
        return;
    }

    __shared__ int s_is64;
    if (threadIdx.x == 0) {
        const unsigned* w = (const unsigned*)ids32;
        s_is64 = (w[1] == 0u && w[3] == 0u && w[5] == 0u && w[7] == 0u) ? 1 : 0;
    }
    __syncthreads();
    const int is64 = s_is64;

    int tid  = threadIdx.x;
    int p    = blockIdx.x * 64 + (tid >> 2);
    int lane = tid & 3;
    int f = p >> 14;
    int b = p & (BATCH - 1);
    long base = (long)p * LL;

    float4 acc = make_float4(0.f, 0.f, 0.f, 0.f);
    if (is64) {
        const ulonglong2* idv = (const ulonglong2*)(ids32 + 2 * base);
        #pragma unroll
        for (int l2 = 0; l2 < 10; l2++) {
            ulonglong2 two = __ldcs(&idv[l2]);
            int id0 = (int)two.x;
            int id1 = (int)two.y;
            float4 v0 = __ldg(&emb[(long)id0 * 4 + lane]);
            float4 v1 = __ldg(&emb[(long)id1 * 4 + lane]);
            acc.x += v0.x + v1.x; acc.y += v0.y + v1.y;
            acc.z += v0.z + v1.z; acc.w += v0.w + v1.w;
        }
    } else {
        const int4* idv = (const int4*)(ids32 + base);
        #pragma unroll
        for (int l4 = 0; l4 < 5; l4++) {
            int4 four = __ldcs(&idv[l4]);
            float4 v0 = __ldg(&emb[(long)four.x * 4 + lane]);
            float4 v1 = __ldg(&emb[(long)four.y * 4 + lane]);
            float4 v2 = __ldg(&emb[(long)four.z * 4 + lane]);
            float4 v3 = __ldg(&emb[(long)four.w * 4 + lane]);
            acc.x += (v0.x + v1.x) + (v2.x + v3.x);
            acc.y += (v0.y + v1.y) + (v2.y + v3.y);
            acc.z += (v0.z + v1.z) + (v2.z + v3.z);
            acc.w += (v0.w + v1.w) + (v2.w + v3.w);
        }
    }
    int fb = f * DD + lane * 4;
    long xoff = (long)b * FEAT + fb;

    float vals[4] = {acc.x, acc.y, acc.z, acc.w};
    unsigned short hi[4], lo[4];
    #pragma unroll
    for (int j = 0; j < 4; j++) {
        __nv_bfloat16 h = __float2bfloat16_rn(vals[j]);
        float r = vals[j] - __bfloat162float(h);
        __nv_bfloat16 l = __float2bfloat16_rn(r);
        hi[j] = *(unsigned short*)&h;
        lo[j] = *(unsigned short*)&l;
    }
    *(uint2*)&g_xhi[xoff] = make_uint2((u32)hi[0] | ((u32)hi[1] << 16),
                                       (u32)hi[2] | ((u32)hi[3] << 16));
    *(uint2*)&g_xlo[xoff] = make_uint2((u32)lo[0] | ((u32)lo[1] << 16),
                                       (u32)lo[2] | ((u32)lo[3] << 16));
}

// ---------------------------------------------------------------------------
// Kernel B: experts GEMM (1-term bf16) + gates GEMM (3-term, blockIdx.y==4).
// ---------------------------------------------------------------------------
__device__ __forceinline__ void fill_stage(u32 smb, int stage, int ks,
                                           int b0, int c0, int tid) {
    int k0 = ks * 32;
    #pragma unroll
    for (int it = 0; it < 4; it++) {
        int idx  = tid + it * 256;          // < 1024
        int tile = idx >> 9;                // 0: xhi, 1: whi
        int r    = (idx >> 2) & 127;
        int ch   = idx & 3;
        int slot = tile ? 2 : 0;
        u32 dst = smb + (u32)(((stage * 3 + slot) * STILE_U16 + r * SSTRIDE + ch * 8) * 2);
        const unsigned short* src = tile
            ? &g_whi[(long)(c0 + r) * FEAT + k0 + ch * 8]
            : &g_xhi[(long)(b0 + r) * FEAT + k0 + ch * 8];
        CP16(dst, src);
    }
}

__device__ __forceinline__ void fill_gate_stage(u32 smb, int stage, int ks,
                                                int b0, int tid) {
    int k0 = ks * 32;
    #pragma unroll
    for (int it = 0; it < 5; it++) {
        int idx = tid + it * 256;           // < 1280
        if (idx < 1024) {
            int tile = idx >> 9;            // 0: xhi, 1: xlo
            int r    = (idx >> 2) & 127;
            int ch   = idx & 3;
            u32 dst = smb + (u32)(((stage * 3 + tile) * STILE_U16 + r * SSTRIDE + ch * 8) * 2);
            const unsigned short* src = (tile == 0)
                ? &g_xhi[(long)(b0 + r) * FEAT + k0 + ch * 8]
                : &g_xlo[(long)(b0 + r) * FEAT + k0 + ch * 8];
            CP16(dst, src);
        } else {
            int idx2 = idx - 1024;          // < 256
            int half = idx2 >> 7;           // 0: ghi, 1: glo
            int r    = (idx2 >> 2) & 31;
            int ch   = idx2 & 3;
            u32 dst = smb + (u32)(((stage * 3 + 2) * STILE_U16
                                   + (half * 32 + r) * SSTRIDE + ch * 8) * 2);
            const unsigned short* src = half
                ? &g_glo[(long)r * FEAT + k0 + ch * 8]
                : &g_ghi[(long)r * FEAT + k0 + ch * 8];
            CP16(dst, src);
        }
    }
}

__global__ void __launch_bounds__(256, 2) expert_mma_kernel(const float* __restrict__ eb,
                                                            const float* __restrict__ gb) {
    extern __shared__ unsigned short sm16[];
    __shared__ float s_bias[TN];

    int tid  = threadIdx.x;
    int wid  = tid >> 5;
    int lane = tid & 31;
    int b0   = blockIdx.x * TM;

    u32 smb = smem_u32(sm16);

    if (blockIdx.y == 4) {
        // ---- gates: 128 rows x 32 cols (24 real), 3-term split ----
        if (tid < 32) s_bias[tid] = (tid < 24) ? gb[tid] : 0.f;

        fill_gate_stage(smb, 0, 0, b0, tid); CP_COMMIT();
        fill_gate_stage(smb, 1, 1, b0, tid); CP_COMMIT();

        int m0 = wid * 16;
        u32 aOff = (u32)((m0 + (lane & 15)) * SSTRIDE + ((lane & 16) ? 8 : 0)) * 2;
        u32 bOff = (u32)(((lane & 7) + ((lane & 16) ? 8 : 0)) * SSTRIDE + ((lane & 8) ? 8 : 0)) * 2;

        float acc[4][4];
        #pragma unroll
        for (int nt = 0; nt < 4; nt++)
            #pragma unroll
            for (int q = 0; q < 4; q++) acc[nt][q] = 0.f;

        #pragma unroll 1
        for (int ks = 0; ks < 5; ks++) {
            if (ks < 4) CP_WAIT1(); else CP_WAIT0();
            __syncthreads();

            int stage = ks & 1;
            u32 aHiB = smb + (u32)((stage * 3 + 0) * STILE_U16 * 2) + aOff;
            u32 aLoB = smb + (u32)((stage * 3 + 1) * STILE_U16 * 2) + aOff;
            u32 bHiB = smb + (u32)((stage * 3 + 2) * STILE_U16 * 2) + bOff;
            u32 bLoB = bHiB + (u32)(32 * SSTRIDE * 2);

            #pragma unroll
            for (int kk = 0; kk < 2; kk++) {
                u32 kb = (u32)(kk * 32);
                u32 ah[4], al[4];
                ldsm4(aHiB + kb, ah[0], ah[1], ah[2], ah[3]);
                ldsm4(aLoB + kb, al[0], al[1], al[2], al[3]);
                u32 bh[2][4], blo[2][4];
                #pragma unroll
                for (int nt2 = 0; nt2 < 2; nt2++) {
                    u32 noff = (u32)(nt2 * 16 * SSTRIDE * 2);
                    ldsm4(bHiB + noff + kb, bh[nt2][0], bh[nt2][1], bh[nt2][2], bh[nt2][3]);
                    ldsm4(bLoB + noff + kb, blo[nt2][0], blo[nt2][1], blo[nt2][2], blo[nt2][3]);
                }
                #pragma unroll
                for (int nt2 = 0; nt2 < 2; nt2++) {
                    mma16816(acc[2 * nt2],     ah, &bh[nt2][0]);
                    mma16816(acc[2 * nt2 + 1], ah, &bh[nt2][2]);
                    mma16816(acc[2 * nt2],     ah, &blo[nt2][0]);
                    mma16816(acc[2 * nt2 + 1], ah, &blo[nt2][2]);
                    mma16816(acc[2 * nt2],     al, &bh[nt2][0]);
                    mma16816(acc[2 * nt2 + 1], al, &bh[nt2][2]);
                }
            }

            __syncthreads();
            if (ks + 2 < 5) { fill_gate_stage(smb, ks & 1, ks + 2, b0, tid); CP_COMMIT(); }
        }

        int r0 = b0 + m0 + (lane >> 2);
        #pragma unroll
        for (int nt = 0; nt < 3; nt++) {
            int cl = nt * 8 + (lane & 3) * 2;
            float bi0 = s_bias[cl], bi1 = s_bias[cl + 1];
            g_gate[(long)r0 * 32 + cl]           = acc[nt][0] + bi0;
            g_gate[(long)r0 * 32 + cl + 1]       = acc[nt][1] + bi1;
            g_gate[(long)(r0 + 8) * 32 + cl]     = acc[nt][2] + bi0;
            g_gate[(long)(r0 + 8) * 32 + cl + 1] = acc[nt][3] + bi1;
        }
        return;
    }

    // ---- experts path: 1-term bf16 ----
    int c0 = blockIdx.y * TN;
    if (tid < TN) {
        int c = c0 + tid;
        s_bias[tid] = eb[(c >> 6) * SS + (c & 63)];
    }

    fill_stage(smb, 0, 0, b0, c0, tid); CP_COMMIT();
    fill_stage(smb, 1, 1, b0, c0, tid); CP_COMMIT();

    int m0 = (wid >> 1) * 32;
    int n0 = (wid & 1) * 64;

    u32 aOff = (u32)((m0 + (lane & 15)) * SSTRIDE + ((lane & 16) ? 8 : 0)) * 2;
    u32 bOff = (u32)((n0 + (lane & 7) + ((lane & 16) ? 8 : 0)) * SSTRIDE + ((lane & 8) ? 8 : 0)) * 2;

    float acc[2][8][4];
    #pragma unroll
    for (int mt = 0; mt < 2; mt++)
        #pragma unroll
        for (int nt = 0; nt < 8; nt++)
            #pragma unroll
            for (int q = 0; q < 4; q++) acc[mt][nt][q] = 0.f;

    #pragma unroll 1
    for (int ks = 0; ks < 5; ks++) {
        if (ks < 4) CP_WAIT1(); else CP_WAIT0();
        __syncthreads();

        int stage = ks & 1;
        u32 aHiB = smb + (u32)((stage * 3 + 0) * STILE_U16 * 2) + aOff;
        u32 bHiB = smb + (u32)((stage * 3 + 2) * STILE_U16 * 2) + bOff;

        #pragma unroll
        for (int kk = 0; kk < 2; kk++) {
            u32 kb = (u32)(kk * 32);

            u32 ah[2][4];
            #pragma unroll
            for (int mt = 0; mt < 2; mt++) {
                u32 moff = (u32)(mt * 16 * SSTRIDE * 2);
                ldsm4(aHiB + moff + kb, ah[mt][0], ah[mt][1], ah[mt][2], ah[mt][3]);
            }
            u32 bh[4][4];
            #pragma unroll
            for (int nt2 = 0; nt2 < 4; nt2++) {
                u32 noff = (u32)(nt2 * 16 * SSTRIDE * 2);
                ldsm4(bHiB + noff + kb, bh[nt2][0], bh[nt2][1], bh[nt2][2], bh[nt2][3]);
            }

            #pragma unroll
            for (int mt = 0; mt < 2; mt++) {
                #pragma unroll
                for (int nt2 = 0; nt2 < 4; nt2++) {
                    mma16816(acc[mt][2 * nt2],     ah[mt], &bh[nt2][0]);
                    mma16816(acc[mt][2 * nt2 + 1], ah[mt], &bh[nt2][2]);
                }
            }
        }

        __syncthreads();
        if (ks + 2 < 5) { fill_stage(smb, ks & 1, ks + 2, b0, c0, tid); CP_COMMIT(); }
    }

    #pragma unroll
    for (int mt = 0; mt < 2; mt++) {
        int row = b0 + m0 + mt * 16 + (lane >> 2);
        #pragma unroll
        for (int nt = 0; nt < 8; nt++) {
            int cl = n0 + nt * 8 + (lane & 3) * 2;
            float bi0 = s_bias[cl], bi1 = s_bias[cl + 1];
            float* d = acc[mt][nt];
            *(__half2*)&g_exp[(long)row * NCOLS + c0 + cl] =
                __floats2half2_rn(fmaxf(d[0] + bi0, 0.f), fmaxf(d[1] + bi1, 0.f));
            *(__half2*)&g_exp[(long)(row + 8) * NCOLS + c0 + cl] =
                __floats2half2_rn(fmaxf(d[2] + bi0, 0.f), fmaxf(d[3] + bi1, 0.f));
        }
    }
}

// ---------------------------------------------------------------------------
// Kernel C: head, warp-per-2-rows, 4 row-pair iterations per warp (grid 256).
// ---------------------------------------------------------------------------
struct HeadSmem {
    ulonglong2 tw4[16][96];
    float mix[8][2][192];
    float ow0[NG * TT];
    float ow1[NG * TT];
    float tb[NG * TT];
    float ob[8];
};

__global__ __launch_bounds__(256) void head_kernel(const float* __restrict__ tw,
                                                   const float* __restrict__ tb,
                                                   const float* __restrict__ ow,
                                                   const float* __restrict__ ob,
                                                   float* __restrict__ out) {
    extern __shared__ char smem_raw[];
    HeadSmem* sm = (HeadSmem*)smem_raw;

    int tid  = threadIdx.x;
    int warp = tid >> 5;
    int lane = tid & 31;

    for (int i = tid; i < 16 * 96; i += 256) {
        int sp2 = i / 96, j = i % 96;
        int g = j >> 5, t = j & 31;
        int s0 = 4 * sp2;
        float v0 = tw[((long)g * SS + s0 + 0) * TT + t];
        float v1 = tw[((long)g * SS + s0 + 1) * TT + t];
        float v2 = tw[((long)g * SS + s0 + 2) * TT + t];
        float v3 = tw[((long)g * SS + s0 + 3) * TT + t];
        ulonglong2 v;
        v.x = pack2(v0, v1);
        v.y = pack2(v2, v3);
        sm->tw4[sp2][j] = v;
    }
    for (int i = tid; i < NG * TT; i += 256) {
        sm->ow0[i] = ow[i * 2 + 0];
        sm->ow1[i] = ow[i * 2 + 1];
        sm->tb[i]  = tb[i];
    }
    if (tid < NG * 2) sm->ob[tid] = ob[tid];
    __syncthreads();

    #pragma unroll 1
    for (int it = 0; it < 4; it++) {
        int bA = blockIdx.x * 8 + warp + it * 2048;
        int bB = bA + 8192;

        __syncwarp();   // prior iteration's mix reads complete

        int oSafe = (lane < 24) ? lane : 0;
        float lgA = g_gate[(long)bA * 32 + oSafe];
        float lgB = g_gate[(long)bB * 32 + oSafe];
        float gvA, gvB;
        {
            float mA = lgA, mB = lgB;
            #pragma unroll
            for (int b = 1; b <= 4; b <<= 1) {
                mA = fmaxf(mA, __shfl_xor_sync(0xFFFFFFFFu, mA, b));
                mB = fmaxf(mB, __shfl_xor_sync(0xFFFFFFFFu, mB, b));
            }
            float eA = __expf(lgA - mA);
            float eB = __expf(lgB - mB);
            float sA = eA, sB = eB;
            #pragma unroll
            for (int b = 1; b <= 4; b <<= 1) {
                sA += __shfl_xor_sync(0xFFFFFFFFu, sA, b);
                sB += __shfl_xor_sync(0xFFFFFFFFu, sB, b);
            }
            gvA = eA * __fdividef(1.f, sA);
            gvB = eB * __fdividef(1.f, sB);
        }
        float gtA[24], gtB[24];
        #pragma unroll
        for (int o = 0; o < 24; o++) {
            gtA[o] = __shfl_sync(0xFFFFFFFFu, gvA, o);
            gtB[o] = __shfl_sync(0xFFFFFFFFu, gvB, o);
        }

        const __half2* erA = (const __half2*)&g_exp[(long)bA * NCOLS];
        const __half2* erB = (const __half2*)&g_exp[(long)bB * NCOLS];
        #pragma unroll
        for (int g = 0; g < NG; g++) {
            float vA0 = 0.f, vA1 = 0.f, vB0 = 0.f, vB1 = 0.f;
            #pragma unroll
            for (int e = 0; e < NE; e++) {
                float2 fa = __half22float2(erA[e * (SS / 2) + lane]);
                float2 fb = __half22float2(erB[e * (SS / 2) + lane]);
                float ga = gtA[g * 8 + e], gbv = gtB[g * 8 + e];
                vA0 = fmaf(ga, fa.x, vA0);
                vA1 = fmaf(ga, fa.y, vA1);
                vB0 = fmaf(gbv, fb.x, vB0);
                vB1 = fmaf(gbv, fb.y, vB1);
            }
            *(float2*)&sm->mix[warp][0][g * SS + 2 * lane] = make_float2(vA0, vA1);
            *(float2*)&sm->mix[warp][1][g * SS + 2 * lane] = make_float2(vB0, vB1);
        }
        __syncwarp();

        float towA[NG], towB[NG];
        #pragma unroll
        for (int g = 0; g < NG; g++) {
            u64 accA = 0ull, accB = 0ull;
            const ulonglong2* mA = (const ulonglong2*)&sm->mix[warp][0][g * SS];
            const ulonglong2* mB = (const ulonglong2*)&sm->mix[warp][1][g * SS];
            #pragma unroll
            for (int sp2 = 0; sp2 < 16; sp2++) {
                ulonglong2 w  = sm->tw4[sp2][g * 32 + lane];
                ulonglong2 ma = mA[sp2];
                ulonglong2 mb = mB[sp2];
                accA = ffma2(ma.x, w.x, accA);
                accA = ffma2(ma.y, w.y, accA);
                accB = ffma2(mb.x, w.x, accB);
                accB = ffma2(mb.y, w.y, accB);
            }
            float l0, h0, l1, h1;
            unpack2(accA, l0, h0);
            unpack2(accB, l1, h1);
            float bias = sm->tb[g * TT + lane];
            towA[g] = fmaxf(l0 + h0 + bias, 0.f);
            towB[g] = fmaxf(l1 + h1 + bias, 0.f);
        }

        float lA[6], lB[6];
        #pragma unroll
        for (int g = 0; g < NG; g++) {
            lA[g * 2 + 0] = towA[g] * sm->ow0[g * TT + lane];
            lA[g * 2 + 1] = towA[g] * sm->ow1[g * TT + lane];
            lB[g * 2 + 0] = towB[g] * sm->ow0[g * TT + lane];
            lB[g * 2 + 1] = towB[g] * sm->ow1[g * TT + lane];
        }
        #pragma unroll
        for (int off = 16; off > 0; off >>= 1) {
            #pragma unroll
            for (int o = 0; o < 6; o++) {
                lA[o] += __shfl_xor_sync(0xFFFFFFFFu, lA[o], off);
                lB[o] += __shfl_xor_sync(0xFFFFFFFFu, lB[o], off);
            }
        }

        if (lane < 2) {
            const float* l = (lane == 0) ? lA : lB;
            int b = (lane == 0) ? bA : bB;
            float probs[6];
            #pragma unroll
            for (int g = 0; g < NG; g++) {
                float l0 = l[g * 2 + 0] + sm->ob[g * 2 + 0];
                float l1 = l[g * 2 + 1] + sm->ob[g * 2 + 1];
                float mm = fmaxf(l0, l1);
                float e0 = __expf(l0 - mm), e1 = __expf(l1 - mm);
                float inv = __fdividef(1.f, e0 + e1);
                probs[g * 2 + 0] = fminf(fmaxf(e0 * inv, 1e-15f), 1.f - 1e-15f);
                probs[g * 2 + 1] = fminf(fmaxf(e1 * inv, 1e-15f), 1.f - 1e-15f);
            }
            float cc = probs[1] * probs[3];
            float* o = out + (long)b * 10;
            o[0] = probs[0]; o[1] = probs[1]; o[2] = probs[1];
            o[3] = probs[2]; o[4] = probs[3]; o[5] = probs[3];
            o[6] = 1.f - cc; o[7] = cc; o[8] = cc;
            o[9] = probs[5];
        }
    }
}

extern "C" void kernel_launch(void* const* d_in, const int* in_sizes, int n_in,
                              void* d_out, int out_size) {
    const int*   ids = (const int*)d_in[0];
    const float* emb = (const float*)d_in[1];
    const float* ew  = (const float*)d_in[2];
    const float* eb  = (const float*)d_in[3];
    const float* gw  = (const float*)d_in[4];
    const float* gb  = (const float*)d_in[5];
    const float* tw  = (const float*)d_in[6];
    const float* tb  = (const float*)d_in[7];
    const float* ow  = (const float*)d_in[8];
    const float* ob  = (const float*)d_in[9];
    float* out = (float*)d_out;

    cudaFuncSetAttribute(expert_mma_kernel, cudaFuncAttributeMaxDynamicSharedMemorySize, DYN_E);
    cudaFuncSetAttribute(head_kernel, cudaFuncAttributeMaxDynamicSharedMemorySize,
                         (int)sizeof(HeadSmem));

    gather_kernel<<<2560 + 340, 256>>>(ids, (const float4*)emb, ew, gw);
    expert_mma_kernel<<<dim3(BATCH / TM, 5), 256, DYN_E>>>(eb, gb);
    head_kernel<<<256, 256, sizeof(HeadSmem)>>>(tw, tb, ow, ob, out);
}

// round 13
// speedup vs baseline: 1.7384x; 1.0040x over previous
#include <cuda_runtime.h>
#include <cuda_bf16.h>
#include <cuda_fp16.h>
#include <math.h>

typedef unsigned long long u64;
typedef unsigned int u32;

#define BATCH 16384
#define NF 10
#define LL 20
#define DD 16
#define FEAT 160
#define NE 8
#define SS 64
#define NG 3
#define TT 32
#define NCOLS (NE*SS)

// ---- expert tiling: 128x128, full K=160 resident (5 chunks of 32) ----
#define TM 128
#define TN 128
#define SSTRIDE 40
#define STILE_U16 (128 * SSTRIDE)       // one 32-k chunk tile: 10240 B
#define DYN_E (10 * STILE_U16 * 2)      // 102400 B: xhi[5 chunks] + whi[5 chunks]

// Scratch (device globals: no allocation allowed)
__device__ __align__(16) unsigned short g_xhi[BATCH * FEAT];
__device__ __align__(16) unsigned short g_xlo[BATCH * FEAT];
__device__ __align__(16) unsigned short g_whi[NCOLS * FEAT];  // W^T single-rounded bf16
__device__ __align__(16) unsigned short g_ghi[32 * FEAT];     // gate W^T hi (24 real cols)
__device__ __align__(16) unsigned short g_glo[32 * FEAT];     // gate W^T lo
__device__ __align__(16) float          g_gate[BATCH * 32];   // gate logits (+bias)
__device__ __align__(16) __half         g_exp[BATCH * NCOLS];

// ---------------- helpers ----------------
__device__ __forceinline__ u64 pack2(float lo, float hi) {
    u64 d;
    asm("mov.b64 %0, {%1, %2};" : "=l"(d)
        : "r"(__float_as_uint(lo)), "r"(__float_as_uint(hi)));
    return d;
}
__device__ __forceinline__ void unpack2(u64 v, float &lo, float &hi) {
    unsigned a, b;
    asm("mov.b64 {%0, %1}, %2;" : "=r"(a), "=r"(b) : "l"(v));
    lo = __uint_as_float(a); hi = __uint_as_float(b);
}
__device__ __forceinline__ u64 ffma2(u64 a, u64 b, u64 c) {
    u64 d;
    asm("fma.rn.f32x2 %0, %1, %2, %3;" : "=l"(d) : "l"(a), "l"(b), "l"(c));
    return d;
}
__device__ __forceinline__ u32 smem_u32(const void* p) {
    u32 a;
    asm("{ .reg .u64 t; cvta.to.shared.u64 t, %1; cvt.u32.u64 %0, t; }" : "=r"(a) : "l"(p));
    return a;
}
__device__ __forceinline__ void ldsm4(u32 addr, u32 &r0, u32 &r1, u32 &r2, u32 &r3) {
    asm volatile("ldmatrix.sync.aligned.m8n8.x4.shared.b16 {%0,%1,%2,%3}, [%4];"
                 : "=r"(r0), "=r"(r1), "=r"(r2), "=r"(r3) : "r"(addr));
}
__device__ __forceinline__ void mma16816(float* d, const u32* a, const u32* b) {
    asm volatile("mma.sync.aligned.m16n8k16.row.col.f32.bf16.bf16.f32 "
                 "{%0,%1,%2,%3}, {%4,%5,%6,%7}, {%8,%9}, {%0,%1,%2,%3};"
                 : "+f"(d[0]), "+f"(d[1]), "+f"(d[2]), "+f"(d[3])
                 : "r"(a[0]), "r"(a[1]), "r"(a[2]), "r"(a[3]), "r"(b[0]), "r"(b[1]));
}
#define CP16(dst, src) \
    asm volatile("cp.async.cg.shared.global [%0], [%1], 16;" :: "r"(dst), "l"(src) : "memory")
#define CP_COMMIT() asm volatile("cp.async.commit_group;" ::: "memory")
#define CP_WAIT1()  asm volatile("cp.async.wait_group 1;" ::: "memory")
#define CP_WAIT0()  asm volatile("cp.async.wait_group 0;" ::: "memory")

// ---------------------------------------------------------------------------
// Kernel A: embedding gather + sum (bf16 hi/lo) + fused weight prep.
// ---------------------------------------------------------------------------
__global__ __launch_bounds__(256) void gather_kernel(const int* __restrict__ ids32,
                                                     const float4* __restrict__ emb,
                                                     const float* __restrict__ ew,
                                                     const float* __restrict__ gwp) {
    if (blockIdx.x >= 2560) {
        int wpidx = (blockIdx.x - 2560) * 256 + threadIdx.x;
        if (wpidx < NCOLS * FEAT) {
            int c = wpidx & (NCOLS - 1);
            int k = wpidx >> 9;
            int e = c >> 6, s = c & 63;
            float w = ew[((long)e * FEAT + k) * SS + s];
            __nv_bfloat16 h = __float2bfloat16_rn(w);
            g_whi[(long)c * FEAT + k] = *(unsigned short*)&h;
        } else if (wpidx < NCOLS * FEAT + 32 * FEAT) {
            int gidx = wpidx - NCOLS * FEAT;
            int c = gidx & 31;
            int k = gidx >> 5;
            float w = 0.f;
            if (c < 24) {
                int g = c >> 3, e = c & 7;
                w = gwp[((long)g * FEAT + k) * NE + e];
            }
            __nv_bfloat16 h = __float2bfloat16_rn(w);
            float r = w - __bfloat162float(h);
            __nv_bfloat16 l = __float2bfloat16_rn(r);
            g_ghi[(long)c * FEAT + k] = *(unsigned short*)&h;
            g_glo[(long)c * FEAT + k] = *(unsigned short*)&l;
        }
        return;
    }

    __shared__ int s_is64;
    if (threadIdx.x == 0) {
        const unsigned* w = (const unsigned*)ids32;
        s_is64 = (w[1] == 0u && w[3] == 0u && w[5] == 0u && w[7] == 0u) ? 1 : 0;
    }
    __syncthreads();
    const int is64 = s_is64;

    int tid  = threadIdx.x;
    int p    = blockIdx.x * 64 + (tid >> 2);
    int lane = tid & 3;
    int f = p >> 14;
    int b = p & (BATCH - 1);
    long base = (long)p * LL;

    float4 acc = make_float4(0.f, 0.f, 0.f, 0.f);
    if (is64) {
        const ulonglong2* idv = (const ulonglong2*)(ids32 + 2 * base);
        #pragma unroll
        for (int l2 = 0; l2 < 10; l2++) {
            ulonglong2 two = __ldcs(&idv[l2]);
            int id0 = (int)two.x;
            int id1 = (int)two.y;
            float4 v0 = __ldg(&emb[(long)id0 * 4 + lane]);
            float4 v1 = __ldg(&emb[(long)id1 * 4 + lane]);
            acc.x += v0.x + v1.x; acc.y += v0.y + v1.y;
            acc.z += v0.z + v1.z; acc.w += v0.w + v1.w;
        }
    } else {
        const int4* idv = (const int4*)(ids32 + base);
        #pragma unroll
        for (int l4 = 0; l4 < 5; l4++) {
            int4 four = __ldcs(&idv[l4]);
            float4 v0 = __ldg(&emb[(long)four.x * 4 + lane]);
            float4 v1 = __ldg(&emb[(long)four.y * 4 + lane]);
            float4 v2 = __ldg(&emb[(long)four.z * 4 + lane]);
            float4 v3 = __ldg(&emb[(long)four.w * 4 + lane]);
            acc.x += (v0.x + v1.x) + (v2.x + v3.x);
            acc.y += (v0.y + v1.y) + (v2.y + v3.y);
            acc.z += (v0.z + v1.z) + (v2.z + v3.z);
            acc.w += (v0.w + v1.w) + (v2.w + v3.w);
        }
    }
    int fb = f * DD + lane * 4;
    long xoff = (long)b * FEAT + fb;

    float vals[4] = {acc.x, acc.y, acc.z, acc.w};
    unsigned short hi[4], lo[4];
    #pragma unroll
    for (int j = 0; j < 4; j++) {
        __nv_bfloat16 h = __float2bfloat16_rn(vals[j]);
        float r = vals[j] - __bfloat162float(h);
        __nv_bfloat16 l = __float2bfloat16_rn(r);
        hi[j] = *(unsigned short*)&h;
        lo[j] = *(unsigned short*)&l;
    }
    *(uint2*)&g_xhi[xoff] = make_uint2((u32)hi[0] | ((u32)hi[1] << 16),
                                       (u32)hi[2] | ((u32)hi[3] << 16));
    *(uint2*)&g_xlo[xoff] = make_uint2((u32)lo[0] | ((u32)lo[1] << 16),
                                       (u32)lo[2] | ((u32)lo[3] << 16));
}

// ---------------------------------------------------------------------------
// Kernel B: experts GEMM (1-term bf16, full-K-resident SMEM, single sync)
//           + gates GEMM (3-term, staged pipeline, blockIdx.y==4).
// ---------------------------------------------------------------------------
__device__ __forceinline__ void fill_gate_stage(u32 smb, int stage, int ks,
                                                int b0, int tid) {
    int k0 = ks * 32;
    #pragma unroll
    for (int it = 0; it < 5; it++) {
        int idx = tid + it * 256;           // < 1280
        if (idx < 1024) {
            int tile = idx >> 9;            // 0: xhi, 1: xlo
            int r    = (idx >> 2) & 127;
            int ch   = idx & 3;
            u32 dst = smb + (u32)(((stage * 3 + tile) * STILE_U16 + r * SSTRIDE + ch * 8) * 2);
            const unsigned short* src = (tile == 0)
                ? &g_xhi[(long)(b0 + r) * FEAT + k0 + ch * 8]
                : &g_xlo[(long)(b0 + r) * FEAT + k0 + ch * 8];
            CP16(dst, src);
        } else {
            int idx2 = idx - 1024;          // < 256
            int half = idx2 >> 7;           // 0: ghi, 1: glo
            int r    = (idx2 >> 2) & 31;
            int ch   = idx2 & 3;
            u32 dst = smb + (u32)(((stage * 3 + 2) * STILE_U16
                                   + (half * 32 + r) * SSTRIDE + ch * 8) * 2);
            const unsigned short* src = half
                ? &g_glo[(long)r * FEAT + k0 + ch * 8]
                : &g_ghi[(long)r * FEAT + k0 + ch * 8];
            CP16(dst, src);
        }
    }
}

__global__ void __launch_bounds__(256, 2) expert_mma_kernel(const float* __restrict__ eb,
                                                            const float* __restrict__ gb) {
    extern __shared__ unsigned short sm16[];
    __shared__ float s_bias[TN];

    int tid  = threadIdx.x;
    int wid  = tid >> 5;
    int lane = tid & 31;
    int b0   = blockIdx.x * TM;

    u32 smb = smem_u32(sm16);

    if (blockIdx.y == 4) {
        // ---- gates: 128 rows x 32 cols (24 real), 3-term split, staged ----
        if (tid < 32) s_bias[tid] = (tid < 24) ? gb[tid] : 0.f;

        fill_gate_stage(smb, 0, 0, b0, tid); CP_COMMIT();
        fill_gate_stage(smb, 1, 1, b0, tid); CP_COMMIT();

        int m0 = wid * 16;
        u32 aOff = (u32)((m0 + (lane & 15)) * SSTRIDE + ((lane & 16) ? 8 : 0)) * 2;
        u32 bOff = (u32)(((lane & 7) + ((lane & 16) ? 8 : 0)) * SSTRIDE + ((lane & 8) ? 8 : 0)) * 2;

        float acc[4][4];
        #pragma unroll
        for (int nt = 0; nt < 4; nt++)
            #pragma unroll
            for (int q = 0; q < 4; q++) acc[nt][q] = 0.f;

        #pragma unroll 1
        for (int ks = 0; ks < 5; ks++) {
            if (ks < 4) CP_WAIT1(); else CP_WAIT0();
            __syncthreads();

            int stage = ks & 1;
            u32 aHiB = smb + (u32)((stage * 3 + 0) * STILE_U16 * 2) + aOff;
            u32 aLoB = smb + (u32)((stage * 3 + 1) * STILE_U16 * 2) + aOff;
            u32 bHiB = smb + (u32)((stage * 3 + 2) * STILE_U16 * 2) + bOff;
            u32 bLoB = bHiB + (u32)(32 * SSTRIDE * 2);

            #pragma unroll
            for (int kk = 0; kk < 2; kk++) {
                u32 kb = (u32)(kk * 32);
                u32 ah[4], al[4];
                ldsm4(aHiB + kb, ah[0], ah[1], ah[2], ah[3]);
                ldsm4(aLoB + kb, al[0], al[1], al[2], al[3]);
                u32 bh[2][4], blo[2][4];
                #pragma unroll
                for (int nt2 = 0; nt2 < 2; nt2++) {
                    u32 noff = (u32)(nt2 * 16 * SSTRIDE * 2);
                    ldsm4(bHiB + noff + kb, bh[nt2][0], bh[nt2][1], bh[nt2][2], bh[nt2][3]);
                    ldsm4(bLoB + noff + kb, blo[nt2][0], blo[nt2][1], blo[nt2][2], blo[nt2][3]);
                }
                #pragma unroll
                for (int nt2 = 0; nt2 < 2; nt2++) {
                    mma16816(acc[2 * nt2],     ah, &bh[nt2][0]);
                    mma16816(acc[2 * nt2 + 1], ah, &bh[nt2][2]);
                    mma16816(acc[2 * nt2],     ah, &blo[nt2][0]);
                    mma16816(acc[2 * nt2 + 1], ah, &blo[nt2][2]);
                    mma16816(acc[2 * nt2],     al, &bh[nt2][0]);
                    mma16816(acc[2 * nt2 + 1], al, &bh[nt2][2]);
                }
            }

            __syncthreads();
            if (ks + 2 < 5) { fill_gate_stage(smb, ks & 1, ks + 2, b0, tid); CP_COMMIT(); }
        }

        int r0 = b0 + m0 + (lane >> 2);
        #pragma unroll
        for (int nt = 0; nt < 3; nt++) {
            int cl = nt * 8 + (lane & 3) * 2;
            float bi0 = s_bias[cl], bi1 = s_bias[cl + 1];
            g_gate[(long)r0 * 32 + cl]           = acc[nt][0] + bi0;
            g_gate[(long)r0 * 32 + cl + 1]       = acc[nt][1] + bi1;
            g_gate[(long)(r0 + 8) * 32 + cl]     = acc[nt][2] + bi0;
            g_gate[(long)(r0 + 8) * 32 + cl + 1] = acc[nt][3] + bi1;
        }
        return;
    }

    // ---- experts path: 1-term bf16, full K resident, one fill + one sync ----
    int c0 = blockIdx.y * TN;
    if (tid < TN) {
        int c = c0 + tid;
        s_bias[tid] = eb[(c >> 6) * SS + (c & 63)];
    }

    // Bulk fill: xhi chunks 0..4 in slots 0..4, whi chunks in slots 5..9.
    #pragma unroll
    for (int it = 0; it < 20; it++) {
        int idx  = tid + it * 256;          // < 5120
        int half = idx >= 2560;             // 0: xhi, 1: whi
        int rem  = half ? idx - 2560 : idx; // < 2560
        int c    = rem >> 9;                // chunk 0..4
        int sub  = rem & 511;
        int r    = sub >> 2;
        int ch   = sub & 3;
        int k0   = c * 32;
        u32 dst = smb + (u32)(((half * 5 + c) * STILE_U16 + r * SSTRIDE + ch * 8) * 2);
        const unsigned short* src = half
            ? &g_whi[(long)(c0 + r) * FEAT + k0 + ch * 8]
            : &g_xhi[(long)(b0 + r) * FEAT + k0 + ch * 8];
        CP16(dst, src);
    }
    CP_COMMIT();
    CP_WAIT0();
    __syncthreads();

    int m0 = (wid >> 1) * 32;
    int n0 = (wid & 1) * 64;

    u32 aOff = (u32)((m0 + (lane & 15)) * SSTRIDE + ((lane & 16) ? 8 : 0)) * 2;
    u32 bOff = (u32)((n0 + (lane & 7) + ((lane & 16) ? 8 : 0)) * SSTRIDE + ((lane & 8) ? 8 : 0)) * 2;

    float acc[2][8][4];
    #pragma unroll
    for (int mt = 0; mt < 2; mt++)
        #pragma unroll
        for (int nt = 0; nt < 8; nt++)
            #pragma unroll
            for (int q = 0; q < 4; q++) acc[mt][nt][q] = 0.f;

    #pragma unroll
    for (int c = 0; c < 5; c++) {
        u32 aHiB = smb + (u32)(c * STILE_U16 * 2) + aOff;
        u32 bHiB = smb + (u32)((5 + c) * STILE_U16 * 2) + bOff;

        #pragma unroll
        for (int kk = 0; kk < 2; kk++) {
            u32 kb = (u32)(kk * 32);

            u32 ah[2][4];
            #pragma unroll
            for (int mt = 0; mt < 2; mt++) {
                u32 moff = (u32)(mt * 16 * SSTRIDE * 2);
                ldsm4(aHiB + moff + kb, ah[mt][0], ah[mt][1], ah[mt][2], ah[mt][3]);
            }
            u32 bh[4][4];
            #pragma unroll
            for (int nt2 = 0; nt2 < 4; nt2++) {
                u32 noff = (u32)(nt2 * 16 * SSTRIDE * 2);
                ldsm4(bHiB + noff + kb, bh[nt2][0], bh[nt2][1], bh[nt2][2], bh[nt2][3]);
            }

            #pragma unroll
            for (int mt = 0; mt < 2; mt++) {
                #pragma unroll
                for (int nt2 = 0; nt2 < 4; nt2++) {
                    mma16816(acc[mt][2 * nt2],     ah[mt], &bh[nt2][0]);
                    mma16816(acc[mt][2 * nt2 + 1], ah[mt], &bh[nt2][2]);
                }
            }
        }
    }

    #pragma unroll
    for (int mt = 0; mt < 2; mt++) {
        int row = b0 + m0 + mt * 16 + (lane >> 2);
        #pragma unroll
        for (int nt = 0; nt < 8; nt++) {
            int cl = n0 + nt * 8 + (lane & 3) * 2;
            float bi0 = s_bias[cl], bi1 = s_bias[cl + 1];
            float* d = acc[mt][nt];
            *(__half2*)&g_exp[(long)row * NCOLS + c0 + cl] =
                __floats2half2_rn(fmaxf(d[0] + bi0, 0.f), fmaxf(d[1] + bi1, 0.f));
            *(__half2*)&g_exp[(long)(row + 8) * NCOLS + c0 + cl] =
                __floats2half2_rn(fmaxf(d[2] + bi0, 0.f), fmaxf(d[3] + bi1, 0.f));
        }
    }
}

// ---------------------------------------------------------------------------
// Kernel C: head, warp-per-2-rows, 4 row-pair iterations per warp (grid 256).
// ---------------------------------------------------------------------------
struct HeadSmem {
    ulonglong2 tw4[16][96];
    float mix[8][2][192];
    float ow0[NG * TT];
    float ow1[NG * TT];
    float tb[NG * TT];
    float ob[8];
};

__global__ __launch_bounds__(256) void head_kernel(const float* __restrict__ tw,
                                                   const float* __restrict__ tb,
                                                   const float* __restrict__ ow,
                                                   const float* __restrict__ ob,
                                                   float* __restrict__ out) {
    extern __shared__ char smem_raw[];
    HeadSmem* sm = (HeadSmem*)smem_raw;

    int tid  = threadIdx.x;
    int warp = tid >> 5;
    int lane = tid & 31;

    for (int i = tid; i < 16 * 96; i += 256) {
        int sp2 = i / 96, j = i % 96;
        int g = j >> 5, t = j & 31;
        int s0 = 4 * sp2;
        float v0 = tw[((long)g * SS + s0 + 0) * TT + t];
        float v1 = tw[((long)g * SS + s0 + 1) * TT + t];
        float v2 = tw[((long)g * SS + s0 + 2) * TT + t];
        float v3 = tw[((long)g * SS + s0 + 3) * TT + t];
        ulonglong2 v;
        v.x = pack2(v0, v1);
        v.y = pack2(v2, v3);
        sm->tw4[sp2][j] = v;
    }
    for (int i = tid; i < NG * TT; i += 256) {
        sm->ow0[i] = ow[i * 2 + 0];
        sm->ow1[i] = ow[i * 2 + 1];
        sm->tb[i]  = tb[i];
    }
    if (tid < NG * 2) sm->ob[tid] = ob[tid];
    __syncthreads();

    #pragma unroll 1
    for (int it = 0; it < 4; it++) {
        int bA = blockIdx.x * 8 + warp + it * 2048;
        int bB = bA + 8192;

        __syncwarp();   // prior iteration's mix reads complete

        int oSafe = (lane < 24) ? lane : 0;
        float lgA = g_gate[(long)bA * 32 + oSafe];
        float lgB = g_gate[(long)bB * 32 + oSafe];
        float gvA, gvB;
        {
            float mA = lgA, mB = lgB;
            #pragma unroll
            for (int b = 1; b <= 4; b <<= 1) {
                mA = fmaxf(mA, __shfl_xor_sync(0xFFFFFFFFu, mA, b));
                mB = fmaxf(mB, __shfl_xor_sync(0xFFFFFFFFu, mB, b));
            }
            float eA = __expf(lgA - mA);
            float eB = __expf(lgB - mB);
            float sA = eA, sB = eB;
            #pragma unroll
            for (int b = 1; b <= 4; b <<= 1) {
                sA += __shfl_xor_sync(0xFFFFFFFFu, sA, b);
                sB += __shfl_xor_sync(0xFFFFFFFFu, sB, b);
            }
            gvA = eA * __fdividef(1.f, sA);
            gvB = eB * __fdividef(1.f, sB);
        }
        float gtA[24], gtB[24];
        #pragma unroll
        for (int o = 0; o < 24; o++) {
            gtA[o] = __shfl_sync(0xFFFFFFFFu, gvA, o);
            gtB[o] = __shfl_sync(0xFFFFFFFFu, gvB, o);
        }

        const __half2* erA = (const __half2*)&g_exp[(long)bA * NCOLS];
        const __half2* erB = (const __half2*)&g_exp[(long)bB * NCOLS];
        #pragma unroll
        for (int g = 0; g < NG; g++) {
            float vA0 = 0.f, vA1 = 0.f, vB0 = 0.f, vB1 = 0.f;
            #pragma unroll
            for (int e = 0; e < NE; e++) {
                float2 fa = __half22float2(erA[e * (SS / 2) + lane]);
                float2 fb = __half22float2(erB[e * (SS / 2) + lane]);
                float ga = gtA[g * 8 + e], gbv = gtB[g * 8 + e];
                vA0 = fmaf(ga, fa.x, vA0);
                vA1 = fmaf(ga, fa.y, vA1);
                vB0 = fmaf(gbv, fb.x, vB0);
                vB1 = fmaf(gbv, fb.y, vB1);
            }
            *(float2*)&sm->mix[warp][0][g * SS + 2 * lane] = make_float2(vA0, vA1);
            *(float2*)&sm->mix[warp][1][g * SS + 2 * lane] = make_float2(vB0, vB1);
        }
        __syncwarp();

        float towA[NG], towB[NG];
        #pragma unroll
        for (int g = 0; g < NG; g++) {
            u64 accA = 0ull, accB = 0ull;
            const ulonglong2* mA = (const ulonglong2*)&sm->mix[warp][0][g * SS];
            const ulonglong2* mB = (const ulonglong2*)&sm->mix[warp][1][g * SS];
            #pragma unroll
            for (int sp2 = 0; sp2 < 16; sp2++) {
                ulonglong2 w  = sm->tw4[sp2][g * 32 + lane];
                ulonglong2 ma = mA[sp2];
                ulonglong2 mb = mB[sp2];
                accA = ffma2(ma.x, w.x, accA);
                accA = ffma2(ma.y, w.y, accA);
                accB = ffma2(mb.x, w.x, accB);
                accB = ffma2(mb.y, w.y, accB);
            }
            float l0, h0, l1, h1;
            unpack2(accA, l0, h0);
            unpack2(accB, l1, h1);
            float bias = sm->tb[g * TT + lane];
            towA[g] = fmaxf(l0 + h0 + bias, 0.f);
            towB[g] = fmaxf(l1 + h1 + bias, 0.f);
        }

        float lA[6], lB[6];
        #pragma unroll
        for (int g = 0; g < NG; g++) {
            lA[g * 2 + 0] = towA[g] * sm->ow0[g * TT + lane];
            lA[g * 2 + 1] = towA[g] * sm->ow1[g * TT + lane];
            lB[g * 2 + 0] = towB[g] * sm->ow0[g * TT + lane];
            lB[g * 2 + 1] = towB[g] * sm->ow1[g * TT + lane];
        }
        #pragma unroll
        for (int off = 16; off > 0; off >>= 1) {
            #pragma unroll
            for (int o = 0; o < 6; o++) {
                lA[o] += __shfl_xor_sync(0xFFFFFFFFu, lA[o], off);
                lB[o] += __shfl_xor_sync(0xFFFFFFFFu, lB[o], off);
            }
        }

        if (lane < 2) {
            const float* l = (lane == 0) ? lA : lB;
            int b = (lane == 0) ? bA : bB;
            float probs[6];
            #pragma unroll
            for (int g = 0; g < NG; g++) {
                float l0 = l[g * 2 + 0] + sm->ob[g * 2 + 0];
                float l1 = l[g * 2 + 1] + sm->ob[g * 2 + 1];
                float mm = fmaxf(l0, l1);
                float e0 = __expf(l0 - mm), e1 = __expf(l1 - mm);
                float inv = __fdividef(1.f, e0 + e1);
                probs[g * 2 + 0] = fminf(fmaxf(e0 * inv, 1e-15f), 1.f - 1e-15f);
                probs[g * 2 + 1] = fminf(fmaxf(e1 * inv, 1e-15f), 1.f - 1e-15f);
            }
            float cc = probs[1] * probs[3];
            float* o = out + (long)b * 10;
            o[0] = probs[0]; o[1] = probs[1]; o[2] = probs[1];
            o[3] = probs[2]; o[4] = probs[3]; o[5] = probs[3];
            o[6] = 1.f - cc; o[7] = cc; o[8] = cc;
            o[9] = probs[5];
        }
    }
}

extern "C" void kernel_launch(void* const* d_in, const int* in_sizes, int n_in,
                              void* d_out, int out_size) {
    const int*   ids = (const int*)d_in[0];
    const float* emb = (const float*)d_in[1];
    const float* ew  = (const float*)d_in[2];
    const float* eb  = (const float*)d_in[3];
    const float* gw  = (const float*)d_in[4];
    const float* gb  = (const float*)d_in[5];
    const float* tw  = (const float*)d_in[6];
    const float* tb  = (const float*)d_in[7];
    const float* ow  = (const float*)d_in[8];
    const float* ob  = (const float*)d_in[9];
    float* out = (float*)d_out;

    cudaFuncSetAttribute(expert_mma_kernel, cudaFuncAttributeMaxDynamicSharedMemorySize, DYN_E);
    cudaFuncSetAttribute(head_kernel, cudaFuncAttributeMaxDynamicSharedMemorySize,
                         (int)sizeof(HeadSmem));

    gather_kernel<<<2560 + 340, 256>>>(ids, (const float4*)emb, ew, gw);
    expert_mma_kernel<<<dim3(BATCH / TM, 5), 256, DYN_E>>>(eb, gb);
    head_kernel<<<256, 256, sizeof(HeadSmem)>>>(tw, tb, ow, ob, out);
}